// round 4
// baseline (speedup 1.0000x reference)
#include <cuda_runtime.h>
#include <cuda_bf16.h>
#include <math.h>

// ---------------- constants ----------------
#define BATCH 4
#define NPIX  4096          // 64*64
#define ROWS  16384         // BATCH*NPIX
#define DIM   192
#define DEPTH 6
#define HEADS 8
#define DH    64
#define INNER 512
#define FF    768
#define MFEAT 266
#define MP    272           // padded feature dim (mult of 16)
#define BHN   32            // BATCH*HEADS
#define CTX_SPLIT 8         // split-K slices for context GEMM

typedef unsigned long long u64t;

__device__ __forceinline__ float gelu_exact(float x) {
    return 0.5f * x * (1.0f + erff(x * 0.70710678118654752f));
}
__device__ __forceinline__ float warpSum(float v) {
    #pragma unroll
    for (int o = 16; o; o >>= 1) v += __shfl_xor_sync(0xffffffffu, v, o);
    return v;
}
__device__ __forceinline__ float warpMax(float v) {
    #pragma unroll
    for (int o = 16; o; o >>= 1) v = fmaxf(v, __shfl_xor_sync(0xffffffffu, v, o));
    return v;
}
// packed fp32x2 helpers (Blackwell FFMA2 — bitwise identical to 2x scalar fmaf)
__device__ __forceinline__ void fma2(u64t& d, u64t a, u64t b) {
    asm("fma.rn.f32x2 %0, %1, %2, %3;" : "=l"(d) : "l"(a), "l"(b), "l"(d));
}
__device__ __forceinline__ u64t dup2(float v) {
    u64t r; asm("mov.b64 %0, {%1, %1};" : "=l"(r) : "f"(v)); return r;
}
__device__ __forceinline__ float2 unp2(u64t v) {
    float2 r; asm("mov.b64 {%0, %1}, %2;" : "=f"(r.x), "=f"(r.y) : "l"(v)); return r;
}

// ---------------- scratch (device globals; no allocs allowed) ----------------
__device__ float g_h   [ROWS * DIM];
__device__ float g_hn  [ROWS * DIM];
__device__ float g_q   [ROWS * INNER];
__device__ float g_k   [ROWS * INNER];
__device__ float g_v   [ROWS * INNER];
__device__ float g_qp  [(long)BHN * NPIX * MP];
__device__ float g_kp  [(long)BHN * NPIX * MP];
__device__ float g_ctx [BHN * MP * DH];
__device__ float g_ctxp[(long)CTX_SPLIT * BHN * MP * DH];
__device__ float g_ksum[BHN * MP];
__device__ float g_kmax[BHN];
__device__ float g_kmpart[BHN * 160];
__device__ float g_kspart[BHN * 8 * MP];
__device__ float g_denom[BHN * NPIX];
__device__ float g_attn[ROWS * INNER];
__device__ float g_ff  [ROWS * FF];
__device__ float g_t1  [ROWS * DIM];
__device__ float g_t2  [ROWS * DIM];
__device__ float g_y   [ROWS * DIM];
__device__ float g_nchw[BATCH * 192 * 64 * 64];
__device__ float g_c9o [BATCH * 192 * 64 * 64];
__device__ float g_c7o [BATCH * 96 * 64 * 64];
__device__ float g_c5o [BATCH * 48 * 64 * 64];

// ---------------- embed: h = x @ Win^T + bin + pos ----------------
__global__ void embed_kernel(const float* __restrict__ x, const float* __restrict__ W,
                             const float* __restrict__ bias, const float* __restrict__ pos,
                             float* __restrict__ H) {
    int row = blockIdx.x;
    int c = threadIdx.x;
    int n = row & (NPIX - 1);
    const float* xr = x + (long)row * 3;
    float v = bias[c] + xr[0] * W[c * 3 + 0] + xr[1] * W[c * 3 + 1] + xr[2] * W[c * 3 + 2]
            + pos[(long)n * DIM + c];
    H[(long)row * DIM + c] = v;
}

// ---------------- scalenorm ----------------
__global__ void scalenorm_kernel(const float* __restrict__ in, float* __restrict__ out,
                                 const float* __restrict__ gArr, int gIdx) {
    int w = (blockIdx.x * blockDim.x + threadIdx.x) >> 5;
    int lane = threadIdx.x & 31;
    if (w >= ROWS) return;
    const float* r = in + (long)w * DIM;
    float ss = 0.f;
    #pragma unroll
    for (int c = lane; c < DIM; c += 32) { float v = r[c]; ss += v * v; }
    ss = warpSum(ss);
    float nrm = sqrtf(ss) * 0.07216878364870323f;
    float s = gArr[gIdx] / fmaxf(nrm, 1e-5f);
    #pragma unroll
    for (int c = lane; c < DIM; c += 32) out[(long)w * DIM + c] = r[c] * s;
}

// =============================================================================
// f32x2 SGEMM: C[M,N] = A[M,K] @ B[N,K]^T.  BM=128 BN=64 BK=16, 128 threads,
// 8x8 per-thread tile. Accumulators packed along row pairs; B pre-duplicated
// in smem so the inner loop is pure LDS + FFMA2.
// EPI: 0 none, 1 +bias, 2 gelu(+bias), 3 +bias+resid
// =============================================================================
template<int EPI>
__global__ void __launch_bounds__(128) gemm_f2(
    const float* __restrict__ A, const float* __restrict__ B,
    const float* __restrict__ bias, const float* __restrict__ resid,
    float* __restrict__ C, int M, int N, int K) {
    __shared__ float As[16][128];
    __shared__ u64t  Bs[16][64];
    const int tid = threadIdx.x;
    const int bm = blockIdx.x * 128, bn = blockIdx.y * 64;
    const int tx = tid & 7, ty = tid >> 3;
    u64t acc[4][8];
    #pragma unroll
    for (int i = 0; i < 4; i++)
        #pragma unroll
        for (int j = 0; j < 8; j++) acc[i][j] = 0ull;

    const float* Arow = A + (long)(bm + tid) * K;
    const float* Brow = B + (long)(bn + (tid >> 1)) * K + (tid & 1) * 8;
    const int rB = tid >> 1, kB = (tid & 1) * 8;

    for (int k0 = 0; k0 < K; k0 += 16) {
        float4 a0 = *(const float4*)(Arow + k0 + 0);
        float4 a1 = *(const float4*)(Arow + k0 + 4);
        float4 a2 = *(const float4*)(Arow + k0 + 8);
        float4 a3 = *(const float4*)(Arow + k0 + 12);
        float4 b0 = *(const float4*)(Brow + k0 + 0);
        float4 b1 = *(const float4*)(Brow + k0 + 4);
        __syncthreads();
        As[ 0][tid]=a0.x; As[ 1][tid]=a0.y; As[ 2][tid]=a0.z; As[ 3][tid]=a0.w;
        As[ 4][tid]=a1.x; As[ 5][tid]=a1.y; As[ 6][tid]=a1.z; As[ 7][tid]=a1.w;
        As[ 8][tid]=a2.x; As[ 9][tid]=a2.y; As[10][tid]=a2.z; As[11][tid]=a2.w;
        As[12][tid]=a3.x; As[13][tid]=a3.y; As[14][tid]=a3.z; As[15][tid]=a3.w;
        Bs[kB+0][rB]=dup2(b0.x); Bs[kB+1][rB]=dup2(b0.y);
        Bs[kB+2][rB]=dup2(b0.z); Bs[kB+3][rB]=dup2(b0.w);
        Bs[kB+4][rB]=dup2(b1.x); Bs[kB+5][rB]=dup2(b1.y);
        Bs[kB+6][rB]=dup2(b1.z); Bs[kB+7][rB]=dup2(b1.w);
        __syncthreads();
        #pragma unroll
        for (int kk = 0; kk < 16; kk++) {
            u64t av[4];
            const u64t* ap = (const u64t*)&As[kk][ty * 8];
            av[0]=ap[0]; av[1]=ap[1]; av[2]=ap[2]; av[3]=ap[3];
            u64t bv[8];
            #pragma unroll
            for (int j = 0; j < 8; j++) bv[j] = Bs[kk][tx * 8 + j];
            #pragma unroll
            for (int i = 0; i < 4; i++)
                #pragma unroll
                for (int j = 0; j < 8; j++) fma2(acc[i][j], av[i], bv[j]);
        }
    }
    // epilogue
    float bcol[8];
    if (EPI >= 1) {
        #pragma unroll
        for (int j = 0; j < 8; j++) bcol[j] = bias[bn + tx * 8 + j];
    }
    #pragma unroll
    for (int i = 0; i < 4; i++) {
        int r0 = bm + ty * 8 + 2 * i;
        float o0[8], o1[8];
        #pragma unroll
        for (int j = 0; j < 8; j++) {
            float2 p = unp2(acc[i][j]);
            o0[j] = p.x; o1[j] = p.y;
        }
        if (EPI >= 1) {
            #pragma unroll
            for (int j = 0; j < 8; j++) { o0[j] += bcol[j]; o1[j] += bcol[j]; }
        }
        if (EPI == 2) {
            #pragma unroll
            for (int j = 0; j < 8; j++) { o0[j] = gelu_exact(o0[j]); o1[j] = gelu_exact(o1[j]); }
        }
        if (EPI == 3) {
            const float* rr0 = resid + (long)r0 * N + bn + tx * 8;
            const float* rr1 = rr0 + N;
            #pragma unroll
            for (int j = 0; j < 8; j++) { o0[j] += rr0[j]; o1[j] += rr1[j]; }
        }
        float* c0 = C + (long)r0 * N + bn + tx * 8;
        *(float4*)(c0 + 0) = make_float4(o0[0], o0[1], o0[2], o0[3]);
        *(float4*)(c0 + 4) = make_float4(o0[4], o0[5], o0[6], o0[7]);
        float* c1 = c0 + N;
        *(float4*)(c1 + 0) = make_float4(o1[0], o1[1], o1[2], o1[3]);
        *(float4*)(c1 + 4) = make_float4(o1[4], o1[5], o1[6], o1[7]);
    }
}

// =============================================================================
// dd GEMM (batched over b,h): dd[n,m] = dn * q[n,:64] . proj[m,:64]
// Same micro-kernel; optional fused block-max (for key-side global softmax max).
// =============================================================================
template<bool DO_MAX>
__global__ void __launch_bounds__(128) gemm_dd_f2(
    const float* __restrict__ Q, const float* __restrict__ P,
    float* __restrict__ DD, float* __restrict__ maxpart) {
    __shared__ float As[16][128];
    __shared__ u64t  Bs[16][64];
    const int tid = threadIdx.x;
    const int bh = blockIdx.z;
    const int b = bh >> 3, hh = bh & 7;
    const int bm = blockIdx.x * 128, bn = blockIdx.y * 64;
    const int tx = tid & 7, ty = tid >> 3;
    u64t acc[4][8];
    #pragma unroll
    for (int i = 0; i < 4; i++)
        #pragma unroll
        for (int j = 0; j < 8; j++) acc[i][j] = 0ull;

    const float* Arow = Q + ((long)b * NPIX + bm + tid) * INNER + hh * DH;
    const int rB = tid >> 1, kB = (tid & 1) * 8;
    const int mB = bn + rB;
    const float* Brow = P + (long)mB * DH + kB;

    for (int k0 = 0; k0 < DH; k0 += 16) {
        float4 a0 = *(const float4*)(Arow + k0 + 0);
        float4 a1 = *(const float4*)(Arow + k0 + 4);
        float4 a2 = *(const float4*)(Arow + k0 + 8);
        float4 a3 = *(const float4*)(Arow + k0 + 12);
        float4 b0 = make_float4(0.f,0.f,0.f,0.f), b1 = b0;
        if (mB < MFEAT) {
            b0 = *(const float4*)(Brow + k0 + 0);
            b1 = *(const float4*)(Brow + k0 + 4);
        }
        __syncthreads();
        As[ 0][tid]=a0.x; As[ 1][tid]=a0.y; As[ 2][tid]=a0.z; As[ 3][tid]=a0.w;
        As[ 4][tid]=a1.x; As[ 5][tid]=a1.y; As[ 6][tid]=a1.z; As[ 7][tid]=a1.w;
        As[ 8][tid]=a2.x; As[ 9][tid]=a2.y; As[10][tid]=a2.z; As[11][tid]=a2.w;
        As[12][tid]=a3.x; As[13][tid]=a3.y; As[14][tid]=a3.z; As[15][tid]=a3.w;
        Bs[kB+0][rB]=dup2(b0.x); Bs[kB+1][rB]=dup2(b0.y);
        Bs[kB+2][rB]=dup2(b0.z); Bs[kB+3][rB]=dup2(b0.w);
        Bs[kB+4][rB]=dup2(b1.x); Bs[kB+5][rB]=dup2(b1.y);
        Bs[kB+6][rB]=dup2(b1.z); Bs[kB+7][rB]=dup2(b1.w);
        __syncthreads();
        #pragma unroll
        for (int kk = 0; kk < 16; kk++) {
            u64t av[4];
            const u64t* ap = (const u64t*)&As[kk][ty * 8];
            av[0]=ap[0]; av[1]=ap[1]; av[2]=ap[2]; av[3]=ap[3];
            u64t bv[8];
            #pragma unroll
            for (int j = 0; j < 8; j++) bv[j] = Bs[kk][tx * 8 + j];
            #pragma unroll
            for (int i = 0; i < 4; i++)
                #pragma unroll
                for (int j = 0; j < 8; j++) fma2(acc[i][j], av[i], bv[j]);
        }
    }
    const float dn = 0.35355339059327373f;  // 64^-0.25
    float* Cb = DD + (long)bh * NPIX * MP;
    float mx = -1e30f;
    #pragma unroll
    for (int i = 0; i < 4; i++) {
        int r0 = bm + ty * 8 + 2 * i;
        #pragma unroll
        for (int j = 0; j < 8; j++) {
            int col = bn + tx * 8 + j;
            float2 p = unp2(acc[i][j]);
            float v0 = dn * p.x, v1 = dn * p.y;
            if (col < MFEAT) {
                Cb[(long)r0 * MP + col] = v0;
                Cb[(long)(r0 + 1) * MP + col] = v1;
                if (DO_MAX) mx = fmaxf(mx, fmaxf(v0, v1));
            }
        }
    }
    if (DO_MAX) {
        __shared__ float sm[4];
        mx = warpMax(mx);
        int lane = tid & 31, wid = tid >> 5;
        if (lane == 0) sm[wid] = mx;
        __syncthreads();
        if (tid == 0) {
            float m = fmaxf(fmaxf(sm[0], sm[1]), fmaxf(sm[2], sm[3]));
            maxpart[bh * 160 + blockIdx.x * 5 + blockIdx.y] = m;
        }
    }
}

__global__ void kmax_fin2(const float* __restrict__ part, float* __restrict__ kmax) {
    int bh = blockIdx.x;
    float v = -1e30f;
    for (int i = threadIdx.x; i < 160; i += 32) v = fmaxf(v, part[bh * 160 + i]);
    v = warpMax(v);
    if (threadIdx.x == 0) kmax[bh] = v;
}

// ---------------- finalize features ----------------
template<bool IS_QUERY>
__global__ void finalize_kernel(const float* __restrict__ QKV, float* __restrict__ DD,
                                const float* __restrict__ KM) {
    int w = (blockIdx.x * blockDim.x + threadIdx.x) >> 5;
    int lane = threadIdx.x & 31;
    int bh = w >> 12, n = w & (NPIX - 1);
    int b = bh >> 3, hh = bh & 7;
    const float* q = QKV + ((long)(b * NPIX + n)) * INNER + hh * DH;
    float ss = 0.f;
    #pragma unroll
    for (int d = lane; d < DH; d += 32) { float v = q[d]; ss += v * v; }
    ss = warpSum(ss);
    float diag = 0.0625f * ss;
    float* row = DD + (long)bh * NPIX * MP + (long)n * MP;
    float vals[9];
    float mx = -1e30f;
    #pragma unroll
    for (int i = 0; i < 9; i++) {
        int m = lane + i * 32;
        if (m < MFEAT) { vals[i] = row[m]; mx = fmaxf(mx, vals[i]); }
    }
    if (IS_QUERY) mx = warpMax(mx);
    else          mx = KM[bh];
    const float ratio = 0.06131393394849658f;
    #pragma unroll
    for (int i = 0; i < 9; i++) {
        int m = lane + i * 32;
        if (m < MP)
            row[m] = (m < MFEAT) ? ratio * (expf(vals[i] - diag - mx) + 1e-4f) : 0.f;
    }
}

// =============================================================================
// context split-K: CTP[sl][bh][m][d] = sum_{n in slice} kp[n,m] * v[n,d]
// BM(m)=64, BN(d)=64, 128 threads, 4x8 per-thread tile. grid (5, CTX_SPLIT, 32)
// =============================================================================
__global__ void __launch_bounds__(128) gemm_ctx_f2(
    const float* __restrict__ KP, const float* __restrict__ V, float* __restrict__ CTP) {
    __shared__ float As[16][64];
    __shared__ u64t  Bs[16][64];
    const int tid = threadIdx.x;
    const int bh = blockIdx.z;
    const int b = bh >> 3, hh = bh & 7;
    const int m0 = blockIdx.x * 64;
    const int sl = blockIdx.y;
    const int n0base = sl * (NPIX / CTX_SPLIT);
    const int tx = tid & 7, ty = tid >> 3;
    u64t acc[2][8];
    #pragma unroll
    for (int i = 0; i < 2; i++)
        #pragma unroll
        for (int j = 0; j < 8; j++) acc[i][j] = 0ull;

    const int nn = tid >> 3;               // 0..15
    const int cq = (tid & 7) * 8;          // 0..56
    const float* kpB = KP + (long)bh * NPIX * MP;
    const float* vB = V + ((long)b * NPIX) * INNER + hh * DH;
    const bool mvalid = (m0 + cq) < MP;    // float4-aligned guard (MP mult of 4)

    for (int n0 = n0base; n0 < n0base + NPIX / CTX_SPLIT; n0 += 16) {
        float4 a0 = make_float4(0.f,0.f,0.f,0.f), a1 = a0;
        if (mvalid) {
            const float* ar = kpB + (long)(n0 + nn) * MP + m0 + cq;
            a0 = *(const float4*)(ar + 0);
            a1 = *(const float4*)(ar + 4);
        }
        const float* br = vB + (long)(n0 + nn) * INNER + cq;
        float4 b0 = *(const float4*)(br + 0);
        float4 b1 = *(const float4*)(br + 4);
        __syncthreads();
        As[nn][cq+0]=a0.x; As[nn][cq+1]=a0.y; As[nn][cq+2]=a0.z; As[nn][cq+3]=a0.w;
        As[nn][cq+4]=a1.x; As[nn][cq+5]=a1.y; As[nn][cq+6]=a1.z; As[nn][cq+7]=a1.w;
        Bs[nn][cq+0]=dup2(b0.x); Bs[nn][cq+1]=dup2(b0.y);
        Bs[nn][cq+2]=dup2(b0.z); Bs[nn][cq+3]=dup2(b0.w);
        Bs[nn][cq+4]=dup2(b1.x); Bs[nn][cq+5]=dup2(b1.y);
        Bs[nn][cq+6]=dup2(b1.z); Bs[nn][cq+7]=dup2(b1.w);
        __syncthreads();
        #pragma unroll
        for (int kk = 0; kk < 16; kk++) {
            u64t av[2];
            const u64t* ap = (const u64t*)&As[kk][ty * 4];
            av[0]=ap[0]; av[1]=ap[1];
            u64t bv[8];
            #pragma unroll
            for (int j = 0; j < 8; j++) bv[j] = Bs[kk][tx * 8 + j];
            #pragma unroll
            for (int i = 0; i < 2; i++)
                #pragma unroll
                for (int j = 0; j < 8; j++) fma2(acc[i][j], av[i], bv[j]);
        }
    }
    float* Cb = CTP + ((long)sl * BHN + bh) * MP * DH;
    #pragma unroll
    for (int i = 0; i < 2; i++) {
        int m = m0 + ty * 4 + 2 * i;
        if (m < MP) {
            float o0[8], o1[8];
            #pragma unroll
            for (int j = 0; j < 8; j++) { float2 p = unp2(acc[i][j]); o0[j]=p.x; o1[j]=p.y; }
            float* c0 = Cb + (long)m * DH + tx * 8;
            *(float4*)(c0 + 0) = make_float4(o0[0],o0[1],o0[2],o0[3]);
            *(float4*)(c0 + 4) = make_float4(o0[4],o0[5],o0[6],o0[7]);
            float* c1 = c0 + DH;
            *(float4*)(c1 + 0) = make_float4(o1[0],o1[1],o1[2],o1[3]);
            *(float4*)(c1 + 4) = make_float4(o1[4],o1[5],o1[6],o1[7]);
        }
    }
}

__global__ void ctx_reduce_kernel(const float* __restrict__ P, float* __restrict__ C) {
    long i = (long)blockIdx.x * 256 + threadIdx.x;
    const long TOT = (long)BHN * MP * DH;
    if (i < TOT) {
        float s = 0.f;
        #pragma unroll
        for (int sl = 0; sl < CTX_SPLIT; sl++) s += P[(long)sl * TOT + i];
        C[i] = s;
    }
}

// ---------------- ksum (2-stage deterministic) ----------------
__global__ void ksum_part_kernel(const float* __restrict__ KP, float* __restrict__ part) {
    int bh = blockIdx.y, sl = blockIdx.x;
    int m = threadIdx.x;
    const float* p = KP + (long)bh * NPIX * MP + (long)sl * 512 * MP + m;
    float s = 0.f;
    #pragma unroll 4
    for (int n = 0; n < 512; n++) s += p[(long)n * MP];
    part[((long)bh * 8 + sl) * MP + m] = s;
}
__global__ void ksum_fin_kernel(const float* __restrict__ part, float* __restrict__ ksum) {
    int bh = blockIdx.x, m = threadIdx.x;
    float s = 0.f;
    #pragma unroll
    for (int sl = 0; sl < 8; sl++) s += part[((long)bh * 8 + sl) * MP + m];
    ksum[bh * MP + m] = s;
}

// ---------------- denom ----------------
__global__ void denom_kernel(const float* __restrict__ QP, const float* __restrict__ KS,
                             float* __restrict__ D) {
    int w = (blockIdx.x * blockDim.x + threadIdx.x) >> 5;
    int lane = threadIdx.x & 31;
    int bh = w >> 12, n = w & (NPIX - 1);
    const float* row = QP + (long)bh * NPIX * MP + (long)n * MP;
    const float* ks = KS + bh * MP;
    float s = 0.f;
    #pragma unroll
    for (int i = 0; i < 9; i++) {
        int m = lane + i * 32;
        if (m < MP) s += row[m] * ks[m];
    }
    s = warpSum(s);
    if (lane == 0) D[bh * NPIX + n] = s;
}

// =============================================================================
// out GEMM: out[n,d] = (sum_m qp[n,m] ctx[m,d]) / denom[n]
// BM=128, BN=64, 128 threads, 8x8 tile, K=MP=272 (17 iters). grid (32, 1, 32)
// =============================================================================
__global__ void __launch_bounds__(128) gemm_out_f2(
    const float* __restrict__ QP, const float* __restrict__ CT,
    const float* __restrict__ D, float* __restrict__ AT) {
    __shared__ float As[16][128];
    __shared__ u64t  Bs[16][64];
    const int tid = threadIdx.x;
    const int bh = blockIdx.z;
    const int b = bh >> 3, hh = bh & 7;
    const int bm = blockIdx.x * 128;
    const int tx = tid & 7, ty = tid >> 3;
    u64t acc[4][8];
    #pragma unroll
    for (int i = 0; i < 4; i++)
        #pragma unroll
        for (int j = 0; j < 8; j++) acc[i][j] = 0ull;

    const float* Arow = QP + (long)bh * NPIX * MP + (long)(bm + tid) * MP;
    const float* Bb = CT + (long)bh * MP * DH;
    const int nn = tid >> 3;           // k-row within tile (0..15)
    const int cq = (tid & 7) * 8;      // d offset

    for (int k0 = 0; k0 < MP; k0 += 16) {
        float4 a0 = *(const float4*)(Arow + k0 + 0);
        float4 a1 = *(const float4*)(Arow + k0 + 4);
        float4 a2 = *(const float4*)(Arow + k0 + 8);
        float4 a3 = *(const float4*)(Arow + k0 + 12);
        const float* br = Bb + (long)(k0 + nn) * DH + cq;
        float4 b0 = *(const float4*)(br + 0);
        float4 b1 = *(const float4*)(br + 4);
        __syncthreads();
        As[ 0][tid]=a0.x; As[ 1][tid]=a0.y; As[ 2][tid]=a0.z; As[ 3][tid]=a0.w;
        As[ 4][tid]=a1.x; As[ 5][tid]=a1.y; As[ 6][tid]=a1.z; As[ 7][tid]=a1.w;
        As[ 8][tid]=a2.x; As[ 9][tid]=a2.y; As[10][tid]=a2.z; As[11][tid]=a2.w;
        As[12][tid]=a3.x; As[13][tid]=a3.y; As[14][tid]=a3.z; As[15][tid]=a3.w;
        Bs[nn][cq+0]=dup2(b0.x); Bs[nn][cq+1]=dup2(b0.y);
        Bs[nn][cq+2]=dup2(b0.z); Bs[nn][cq+3]=dup2(b0.w);
        Bs[nn][cq+4]=dup2(b1.x); Bs[nn][cq+5]=dup2(b1.y);
        Bs[nn][cq+6]=dup2(b1.z); Bs[nn][cq+7]=dup2(b1.w);
        __syncthreads();
        #pragma unroll
        for (int kk = 0; kk < 16; kk++) {
            u64t av[4];
            const u64t* ap = (const u64t*)&As[kk][ty * 8];
            av[0]=ap[0]; av[1]=ap[1]; av[2]=ap[2]; av[3]=ap[3];
            u64t bv[8];
            #pragma unroll
            for (int j = 0; j < 8; j++) bv[j] = Bs[kk][tx * 8 + j];
            #pragma unroll
            for (int i = 0; i < 4; i++)
                #pragma unroll
                for (int j = 0; j < 8; j++) fma2(acc[i][j], av[i], bv[j]);
        }
    }
    #pragma unroll
    for (int i = 0; i < 4; i++) {
        int n0 = bm + ty * 8 + 2 * i;
        float rd0 = 1.0f / D[bh * NPIX + n0];
        float rd1 = 1.0f / D[bh * NPIX + n0 + 1];
        float o0[8], o1[8];
        #pragma unroll
        for (int j = 0; j < 8; j++) {
            float2 p = unp2(acc[i][j]);
            o0[j] = p.x * rd0; o1[j] = p.y * rd1;
        }
        float* c0 = AT + ((long)(b * NPIX + n0)) * INNER + hh * DH + tx * 8;
        *(float4*)(c0 + 0) = make_float4(o0[0],o0[1],o0[2],o0[3]);
        *(float4*)(c0 + 4) = make_float4(o0[4],o0[5],o0[6],o0[7]);
        float* c1 = c0 + INNER;
        *(float4*)(c1 + 0) = make_float4(o1[0],o1[1],o1[2],o1[3]);
        *(float4*)(c1 + 4) = make_float4(o1[4],o1[5],o1[6],o1[7]);
    }
}

// ---------------- group norm + NHWC -> NCHW ----------------
__global__ void groupnorm_kernel(const float* __restrict__ Y, const float* __restrict__ G,
                                 const float* __restrict__ Bt, float* __restrict__ Z) {
    int b = blockIdx.x >> 3, grp = blockIdx.x & 7;
    const int CPG = 24, NELEM = CPG * NPIX;
    float s = 0.f, s2 = 0.f;
    for (int t = threadIdx.x; t < NELEM; t += 256) {
        int c = grp * CPG + (t % CPG);
        int pix = t / CPG;
        float v = Y[((long)b * NPIX + pix) * DIM + c];
        s += v; s2 += v * v;
    }
    __shared__ float ssum[8], ssq[8];
    int lane = threadIdx.x & 31, wid = threadIdx.x >> 5;
    s = warpSum(s); s2 = warpSum(s2);
    if (lane == 0) { ssum[wid] = s; ssq[wid] = s2; }
    __syncthreads();
    if (wid == 0) {
        float a = (lane < 8) ? ssum[lane] : 0.f;
        float b2 = (lane < 8) ? ssq[lane] : 0.f;
        a = warpSum(a); b2 = warpSum(b2);
        if (lane == 0) { ssum[0] = a; ssq[0] = b2; }
    }
    __syncthreads();
    float mu = ssum[0] / NELEM;
    float var = ssq[0] / NELEM - mu * mu;
    float rstd = rsqrtf(var + 1e-5f);
    for (int t = threadIdx.x; t < NELEM; t += 256) {
        int c = grp * CPG + (t % CPG);
        int pix = t / CPG;
        float v = Y[((long)b * NPIX + pix) * DIM + c];
        Z[((long)(b * DIM + c)) * NPIX + pix] = (v - mu) * rstd * G[c] + Bt[c];
    }
}

// ---------------- circular grouped conv + gelu ----------------
template<int CIN_G, int COUT_G, int KS, int CIN_TOTAL, int COUT_TOTAL, bool DO_GELU>
__global__ void __launch_bounds__(256) conv_circ(
    const float* __restrict__ IN, const float* __restrict__ W,
    const float* __restrict__ Bi, float* __restrict__ OUT) {
    const int PAD = KS / 2;
    const int HALO = 16 + 2 * PAD;
    __shared__ float s_in[HALO * HALO];
    __shared__ float s_w[COUT_G * KS * KS];
    int tile = blockIdx.x;
    int ty0 = (tile >> 2) * 16, tx0 = (tile & 3) * 16;
    int g = blockIdx.y, b = blockIdx.z;
    int tid = threadIdx.x;
    int tx = tid & 15, ty = tid >> 4;
    float acc[COUT_G];
    #pragma unroll
    for (int co = 0; co < COUT_G; co++) acc[co] = Bi[g * COUT_G + co];
    for (int ci = 0; ci < CIN_G; ci++) {
        for (int t = tid; t < HALO * HALO; t += 256) {
            int r = t / HALO, c = t % HALO;
            int gy = (ty0 + r - PAD) & 63;
            int gx = (tx0 + c - PAD) & 63;
            s_in[t] = IN[(((long)b * CIN_TOTAL + g * CIN_G + ci) * 64 + gy) * 64 + gx];
        }
        for (int t = tid; t < COUT_G * KS * KS; t += 256) {
            int co = t / (KS * KS), r = t % (KS * KS);
            s_w[t] = W[(((long)(g * COUT_G + co)) * CIN_G + ci) * (KS * KS) + r];
        }
        __syncthreads();
        #pragma unroll
        for (int ky = 0; ky < KS; ky++) {
            #pragma unroll
            for (int kx = 0; kx < KS; kx++) {
                float v = s_in[(ty + ky) * HALO + tx + kx];
                #pragma unroll
                for (int co = 0; co < COUT_G; co++)
                    acc[co] = fmaf(v, s_w[co * KS * KS + ky * KS + kx], acc[co]);
            }
        }
        __syncthreads();
    }
    #pragma unroll
    for (int co = 0; co < COUT_G; co++) {
        float v = DO_GELU ? gelu_exact(acc[co]) : acc[co];
        OUT[(((long)b * COUT_TOTAL + g * COUT_G + co) * 64 + ty0 + ty) * 64 + tx0 + tx] = v;
    }
}

// ---------------- 1x1 conv 48->3 ----------------
__global__ void conv1_kernel(const float* __restrict__ IN, const float* __restrict__ W,
                             const float* __restrict__ Bi, float* __restrict__ OUT) {
    int b = blockIdx.y;
    int pix = blockIdx.x * 256 + threadIdx.x;
    float a0 = Bi[0], a1 = Bi[1], a2 = Bi[2];
    #pragma unroll
    for (int c = 0; c < 48; c++) {
        float v = IN[((long)b * 48 + c) * NPIX + pix];
        a0 = fmaf(v, W[0 * 48 + c], a0);
        a1 = fmaf(v, W[1 * 48 + c], a1);
        a2 = fmaf(v, W[2 * 48 + c], a2);
    }
    long base = ((long)b * NPIX + pix) * 3;
    OUT[base + 0] = a0; OUT[base + 1] = a1; OUT[base + 2] = a2;
}

// ---------------- host ----------------
extern "C" void kernel_launch(void* const* d_in, const int* in_sizes, int n_in,
                              void* d_out, int out_size) {
    const float* x        = (const float*)d_in[0];
    const float* to_in_w  = (const float*)d_in[1];
    const float* to_in_b  = (const float*)d_in[2];
    const float* pos_emb  = (const float*)d_in[3];
    const float* proj     = (const float*)d_in[4];
    const float* sn_attn_g= (const float*)d_in[5];
    const float* wq       = (const float*)d_in[6];
    const float* wk       = (const float*)d_in[7];
    const float* wv       = (const float*)d_in[8];
    const float* wo       = (const float*)d_in[9];
    const float* bo       = (const float*)d_in[10];
    const float* sn_ff_g  = (const float*)d_in[11];
    const float* w1       = (const float*)d_in[12];
    const float* b1       = (const float*)d_in[13];
    const float* w2       = (const float*)d_in[14];
    const float* b2       = (const float*)d_in[15];
    const float* expand_w = (const float*)d_in[16];
    const float* fwd_w    = (const float*)d_in[17];
    const float* dec_lin_w= (const float*)d_in[18];
    const float* dec_lin_b= (const float*)d_in[19];
    const float* gn_g     = (const float*)d_in[20];
    const float* gn_b     = (const float*)d_in[21];
    const float* c9_w     = (const float*)d_in[22];
    const float* c9_b     = (const float*)d_in[23];
    const float* c7_w     = (const float*)d_in[24];
    const float* c7_b     = (const float*)d_in[25];
    const float* c5_w     = (const float*)d_in[26];
    const float* c5_b     = (const float*)d_in[27];
    const float* c1_w     = (const float*)d_in[28];
    const float* c1_b     = (const float*)d_in[29];
    float* out = (float*)d_out;

    float *ph, *phn, *pq, *pk, *pv, *pqp, *pkp, *pctx, *pctxp, *pksum, *pkmax, *pkmp,
          *pksp, *pden, *pattn, *pff, *pt1, *pt2, *py, *pnchw, *pc9, *pc7, *pc5;
    cudaGetSymbolAddress((void**)&ph, g_h);
    cudaGetSymbolAddress((void**)&phn, g_hn);
    cudaGetSymbolAddress((void**)&pq, g_q);
    cudaGetSymbolAddress((void**)&pk, g_k);
    cudaGetSymbolAddress((void**)&pv, g_v);
    cudaGetSymbolAddress((void**)&pqp, g_qp);
    cudaGetSymbolAddress((void**)&pkp, g_kp);
    cudaGetSymbolAddress((void**)&pctx, g_ctx);
    cudaGetSymbolAddress((void**)&pctxp, g_ctxp);
    cudaGetSymbolAddress((void**)&pksum, g_ksum);
    cudaGetSymbolAddress((void**)&pkmax, g_kmax);
    cudaGetSymbolAddress((void**)&pkmp, g_kmpart);
    cudaGetSymbolAddress((void**)&pksp, g_kspart);
    cudaGetSymbolAddress((void**)&pden, g_denom);
    cudaGetSymbolAddress((void**)&pattn, g_attn);
    cudaGetSymbolAddress((void**)&pff, g_ff);
    cudaGetSymbolAddress((void**)&pt1, g_t1);
    cudaGetSymbolAddress((void**)&pt2, g_t2);
    cudaGetSymbolAddress((void**)&py, g_y);
    cudaGetSymbolAddress((void**)&pnchw, g_nchw);
    cudaGetSymbolAddress((void**)&pc9, g_c9o);
    cudaGetSymbolAddress((void**)&pc7, g_c7o);
    cudaGetSymbolAddress((void**)&pc5, g_c5o);

    embed_kernel<<<ROWS, DIM>>>(x, to_in_w, to_in_b, pos_emb, ph);

    const long CTOT = (long)BHN * MP * DH;
    for (int i = 0; i < DEPTH; i++) {
        const float* proj_i = proj + (long)i * MFEAT * DH;
        scalenorm_kernel<<<2048, 256>>>(ph, phn, sn_attn_g, i);
        gemm_f2<0><<<dim3(128, 8), 128>>>(phn, wq + (long)i * INNER * DIM, nullptr, nullptr, pq, ROWS, INNER, DIM);
        gemm_f2<0><<<dim3(128, 8), 128>>>(phn, wk + (long)i * INNER * DIM, nullptr, nullptr, pk, ROWS, INNER, DIM);
        gemm_f2<0><<<dim3(128, 8), 128>>>(phn, wv + (long)i * INNER * DIM, nullptr, nullptr, pv, ROWS, INNER, DIM);
        gemm_dd_f2<false><<<dim3(32, 5, BHN), 128>>>(pq, proj_i, pqp, nullptr);
        gemm_dd_f2<true ><<<dim3(32, 5, BHN), 128>>>(pk, proj_i, pkp, pkmp);
        kmax_fin2<<<BHN, 32>>>(pkmp, pkmax);
        finalize_kernel<true ><<<16384, 256>>>(pq, pqp, nullptr);
        finalize_kernel<false><<<16384, 256>>>(pk, pkp, pkmax);
        gemm_ctx_f2<<<dim3(5, CTX_SPLIT, BHN), 128>>>(pkp, pv, pctxp);
        ctx_reduce_kernel<<<(int)((CTOT + 255) / 256), 256>>>(pctxp, pctx);
        ksum_part_kernel<<<dim3(8, BHN), MP>>>(pkp, pksp);
        ksum_fin_kernel<<<BHN, MP>>>(pksp, pksum);
        denom_kernel<<<16384, 256>>>(pqp, pksum, pden);
        gemm_out_f2<<<dim3(32, 1, BHN), 128>>>(pqp, pctx, pden, pattn);
        gemm_f2<3><<<dim3(128, 3), 128>>>(pattn, wo + (long)i * DIM * INNER, bo + (long)i * DIM, ph, ph, ROWS, DIM, INNER);
        scalenorm_kernel<<<2048, 256>>>(ph, phn, sn_ff_g, i);
        gemm_f2<2><<<dim3(128, 12), 128>>>(phn, w1 + (long)i * FF * DIM, b1 + (long)i * FF, nullptr, pff, ROWS, FF, DIM);
        gemm_f2<3><<<dim3(128, 3), 128>>>(pff, w2 + (long)i * DIM * FF, b2 + (long)i * DIM, ph, ph, ROWS, DIM, FF);
    }

    gemm_f2<0><<<dim3(128, 3), 128>>>(ph, expand_w, nullptr, nullptr, pt1, ROWS, DIM, DIM);
    gemm_f2<0><<<dim3(128, 3), 128>>>(pt1, fwd_w, nullptr, nullptr, pt2, ROWS, DIM, DIM);
    gemm_f2<1><<<dim3(128, 3), 128>>>(pt2, dec_lin_w, dec_lin_b, nullptr, py, ROWS, DIM, DIM);

    groupnorm_kernel<<<32, 256>>>(py, gn_g, gn_b, pnchw);
    conv_circ<24, 24, 9, 192, 192, true><<<dim3(16, 8, 4), 256>>>(pnchw, c9_w, c9_b, pc9);
    conv_circ<24, 12, 7, 192,  96, true><<<dim3(16, 8, 4), 256>>>(pc9, c7_w, c7_b, pc7);
    conv_circ<12,  6, 5,  96,  48, true><<<dim3(16, 8, 4), 256>>>(pc7, c5_w, c5_b, pc5);
    conv1_kernel<<<dim3(16, 4), 256>>>(pc5, c1_w, c1_b, out);
}

// round 6
// speedup vs baseline: 2.3790x; 2.3790x over previous
#include <cuda_runtime.h>
#include <cuda_bf16.h>
#include <math.h>

// ---------------- constants ----------------
#define BATCH 4
#define NPIX  4096          // 64*64
#define ROWS  16384         // BATCH*NPIX
#define DIM   192
#define DEPTH 6
#define HEADS 8
#define DH    64
#define INNER 512
#define FF    768
#define MFEAT 266
#define MP    272           // padded feature dim (mult of 16)
#define BHN   32            // BATCH*HEADS
#define CTX_SPLIT 8         // split-K slices for context GEMM

typedef unsigned long long u64t;

__device__ __forceinline__ float gelu_exact(float x) {
    return 0.5f * x * (1.0f + erff(x * 0.70710678118654752f));
}
__device__ __forceinline__ float warpSum(float v) {
    #pragma unroll
    for (int o = 16; o; o >>= 1) v += __shfl_xor_sync(0xffffffffu, v, o);
    return v;
}
__device__ __forceinline__ float warpMax(float v) {
    #pragma unroll
    for (int o = 16; o; o >>= 1) v = fmaxf(v, __shfl_xor_sync(0xffffffffu, v, o));
    return v;
}
// packed fp32x2 helpers (Blackwell FFMA2 — bitwise identical to 2x scalar fmaf)
__device__ __forceinline__ void fma2(u64t& d, u64t a, u64t b) {
    asm("fma.rn.f32x2 %0, %1, %2, %3;" : "=l"(d) : "l"(a), "l"(b), "l"(d));
}
__device__ __forceinline__ u64t dup2(float v) {
    u64t r; asm("mov.b64 %0, {%1, %1};" : "=l"(r) : "f"(v)); return r;
}
__device__ __forceinline__ float2 unp2(u64t v) {
    float2 r; asm("mov.b64 {%0, %1}, %2;" : "=f"(r.x), "=f"(r.y) : "l"(v)); return r;
}

// ---------------- scratch (device globals; no allocs allowed) ----------------
__device__ float g_h   [ROWS * DIM];
__device__ float g_hn  [ROWS * DIM];
__device__ float g_q   [ROWS * INNER];
__device__ float g_k   [ROWS * INNER];
__device__ float g_v   [ROWS * INNER];
__device__ float g_qp  [(long)BHN * NPIX * MP];
__device__ float g_kp  [(long)BHN * NPIX * MP];
__device__ float g_ctx [BHN * MP * DH];
__device__ float g_ctxp[(long)CTX_SPLIT * BHN * MP * DH];
__device__ float g_ksum[BHN * MP];
__device__ float g_kmax[BHN];
__device__ float g_kmpart[BHN * 80];
__device__ float g_kspart[BHN * 8 * MP];
__device__ float g_denom[BHN * NPIX];
__device__ float g_attn[ROWS * INNER];
__device__ float g_ff  [ROWS * FF];
__device__ float g_t1  [ROWS * DIM];
__device__ float g_t2  [ROWS * DIM];
__device__ float g_y   [ROWS * DIM];
__device__ float g_nchw[BATCH * 192 * 64 * 64];
__device__ float g_c9o [BATCH * 192 * 64 * 64];
__device__ float g_c7o [BATCH * 96 * 64 * 64];
__device__ float g_c5o [BATCH * 48 * 64 * 64];

// ---------------- embed ----------------
__global__ void embed_kernel(const float* __restrict__ x, const float* __restrict__ W,
                             const float* __restrict__ bias, const float* __restrict__ pos,
                             float* __restrict__ H) {
    int row = blockIdx.x;
    int c = threadIdx.x;
    int n = row & (NPIX - 1);
    const float* xr = x + (long)row * 3;
    float v = bias[c] + xr[0] * W[c * 3 + 0] + xr[1] * W[c * 3 + 1] + xr[2] * W[c * 3 + 2]
            + pos[(long)n * DIM + c];
    H[(long)row * DIM + c] = v;
}

// ---------------- scalenorm ----------------
__global__ void scalenorm_kernel(const float* __restrict__ in, float* __restrict__ out,
                                 const float* __restrict__ gArr, int gIdx) {
    int w = (blockIdx.x * blockDim.x + threadIdx.x) >> 5;
    int lane = threadIdx.x & 31;
    if (w >= ROWS) return;
    const float* r = in + (long)w * DIM;
    float ss = 0.f;
    #pragma unroll
    for (int c = lane; c < DIM; c += 32) { float v = r[c]; ss += v * v; }
    ss = warpSum(ss);
    float nrm = sqrtf(ss) * 0.07216878364870323f;
    float s = gArr[gIdx] / fmaxf(nrm, 1e-5f);
    #pragma unroll
    for (int c = lane; c < DIM; c += 32) out[(long)w * DIM + c] = r[c] * s;
}

// =============================================================================
// FFMA2 GEMM, BN=128 variant: C[M,N] = A[M,K] @ B[N,K]^T.
// 256 threads, BM=128 BN=128 BK=16, per-thread 8 rows (4 packed u64) x 8 cols
// (two float4 column groups at tx*4 and 64+tx*4 -> conflict-free LDS.128).
// Plain-float smem; B duplicated into u64 in REGISTERS (alu pipe).
// EPI: 0 none, 1 +bias, 2 gelu(+bias), 3 +bias+resid
// =============================================================================
template<int EPI>
__global__ void __launch_bounds__(256) gemm_f2n128(
    const float* __restrict__ A, const float* __restrict__ B,
    const float* __restrict__ bias, const float* __restrict__ resid,
    float* __restrict__ C, int M, int N, int K) {
    __shared__ float As[16][128];
    __shared__ float Bs[16][128];
    const int tid = threadIdx.x;
    const int bm = blockIdx.x * 128, bn = blockIdx.y * 128;
    const int tx = tid & 15, ty = tid >> 4;
    u64t acc[4][8];
    #pragma unroll
    for (int i = 0; i < 4; i++)
        #pragma unroll
        for (int j = 0; j < 8; j++) acc[i][j] = 0ull;

    const int lr = tid >> 1, lk = (tid & 1) * 8;
    const float* Arow = A + (long)(bm + lr) * K + lk;
    const float* Brow = B + (long)(bn + lr) * K + lk;

    for (int k0 = 0; k0 < K; k0 += 16) {
        float4 a0 = *(const float4*)(Arow + k0);
        float4 a1 = *(const float4*)(Arow + k0 + 4);
        float4 b0 = *(const float4*)(Brow + k0);
        float4 b1 = *(const float4*)(Brow + k0 + 4);
        __syncthreads();
        As[lk+0][lr]=a0.x; As[lk+1][lr]=a0.y; As[lk+2][lr]=a0.z; As[lk+3][lr]=a0.w;
        As[lk+4][lr]=a1.x; As[lk+5][lr]=a1.y; As[lk+6][lr]=a1.z; As[lk+7][lr]=a1.w;
        Bs[lk+0][lr]=b0.x; Bs[lk+1][lr]=b0.y; Bs[lk+2][lr]=b0.z; Bs[lk+3][lr]=b0.w;
        Bs[lk+4][lr]=b1.x; Bs[lk+5][lr]=b1.y; Bs[lk+6][lr]=b1.z; Bs[lk+7][lr]=b1.w;
        __syncthreads();
        #pragma unroll
        for (int kk = 0; kk < 16; kk++) {
            const u64t* ap = (const u64t*)&As[kk][ty * 8];
            u64t av0 = ap[0], av1 = ap[1], av2 = ap[2], av3 = ap[3];
            float4 p0 = *(const float4*)&Bs[kk][tx * 4];
            float4 p1 = *(const float4*)&Bs[kk][64 + tx * 4];
            u64t bv[8];
            bv[0]=dup2(p0.x); bv[1]=dup2(p0.y); bv[2]=dup2(p0.z); bv[3]=dup2(p0.w);
            bv[4]=dup2(p1.x); bv[5]=dup2(p1.y); bv[6]=dup2(p1.z); bv[7]=dup2(p1.w);
            #pragma unroll
            for (int j = 0; j < 8; j++) {
                fma2(acc[0][j], av0, bv[j]);
                fma2(acc[1][j], av1, bv[j]);
                fma2(acc[2][j], av2, bv[j]);
                fma2(acc[3][j], av3, bv[j]);
            }
        }
    }
    const int col0 = bn + tx * 4, col1 = bn + 64 + tx * 4;
    float bcol[8];
    if (EPI >= 1) {
        #pragma unroll
        for (int j = 0; j < 4; j++) { bcol[j] = bias[col0 + j]; bcol[4 + j] = bias[col1 + j]; }
    }
    #pragma unroll
    for (int i = 0; i < 4; i++) {
        int r0 = bm + ty * 8 + 2 * i;
        float o0[8], o1[8];
        #pragma unroll
        for (int j = 0; j < 8; j++) { float2 p = unp2(acc[i][j]); o0[j] = p.x; o1[j] = p.y; }
        if (EPI >= 1) {
            #pragma unroll
            for (int j = 0; j < 8; j++) { o0[j] += bcol[j]; o1[j] += bcol[j]; }
        }
        if (EPI == 2) {
            #pragma unroll
            for (int j = 0; j < 8; j++) { o0[j] = gelu_exact(o0[j]); o1[j] = gelu_exact(o1[j]); }
        }
        if (EPI == 3) {
            const float* rr0 = resid + (long)r0 * N;
            const float* rr1 = rr0 + N;
            #pragma unroll
            for (int j = 0; j < 4; j++) {
                o0[j] += rr0[col0 + j]; o0[4+j] += rr0[col1 + j];
                o1[j] += rr1[col0 + j]; o1[4+j] += rr1[col1 + j];
            }
        }
        float* c0 = C + (long)r0 * N;
        *(float4*)(c0 + col0) = make_float4(o0[0], o0[1], o0[2], o0[3]);
        *(float4*)(c0 + col1) = make_float4(o0[4], o0[5], o0[6], o0[7]);
        float* c1 = c0 + N;
        *(float4*)(c1 + col0) = make_float4(o1[0], o1[1], o1[2], o1[3]);
        *(float4*)(c1 + col1) = make_float4(o1[4], o1[5], o1[6], o1[7]);
    }
}

// =============================================================================
// FFMA2 GEMM, BN=64 variant: BM=256, 256 threads, per-thread 8 rows x 8 cols,
// column groups at tx*4 and 32+tx*4. For N multiples of 64 (wo/ff2/tail).
// =============================================================================
template<int EPI>
__global__ void __launch_bounds__(256) gemm_f2n64(
    const float* __restrict__ A, const float* __restrict__ B,
    const float* __restrict__ bias, const float* __restrict__ resid,
    float* __restrict__ C, int M, int N, int K) {
    __shared__ float As[16][256];
    __shared__ float Bs[16][64];
    const int tid = threadIdx.x;
    const int bm = blockIdx.x * 256, bn = blockIdx.y * 64;
    const int tx = tid & 7, ty = tid >> 3;
    u64t acc[4][8];
    #pragma unroll
    for (int i = 0; i < 4; i++)
        #pragma unroll
        for (int j = 0; j < 8; j++) acc[i][j] = 0ull;

    const float* Arow = A + (long)(bm + tid) * K;
    const int br = tid >> 2, bk = (tid & 3) * 4;
    const float* Brow = B + (long)(bn + br) * K + bk;

    for (int k0 = 0; k0 < K; k0 += 16) {
        float4 a[4];
        a[0] = *(const float4*)(Arow + k0);
        a[1] = *(const float4*)(Arow + k0 + 4);
        a[2] = *(const float4*)(Arow + k0 + 8);
        a[3] = *(const float4*)(Arow + k0 + 12);
        float4 bb = *(const float4*)(Brow + k0);
        __syncthreads();
        #pragma unroll
        for (int q = 0; q < 4; q++) {
            As[q*4+0][tid]=a[q].x; As[q*4+1][tid]=a[q].y;
            As[q*4+2][tid]=a[q].z; As[q*4+3][tid]=a[q].w;
        }
        Bs[bk+0][br]=bb.x; Bs[bk+1][br]=bb.y; Bs[bk+2][br]=bb.z; Bs[bk+3][br]=bb.w;
        __syncthreads();
        #pragma unroll
        for (int kk = 0; kk < 16; kk++) {
            const u64t* ap = (const u64t*)&As[kk][ty * 8];
            u64t av0 = ap[0], av1 = ap[1], av2 = ap[2], av3 = ap[3];
            float4 p0 = *(const float4*)&Bs[kk][tx * 4];
            float4 p1 = *(const float4*)&Bs[kk][32 + tx * 4];
            u64t bv[8];
            bv[0]=dup2(p0.x); bv[1]=dup2(p0.y); bv[2]=dup2(p0.z); bv[3]=dup2(p0.w);
            bv[4]=dup2(p1.x); bv[5]=dup2(p1.y); bv[6]=dup2(p1.z); bv[7]=dup2(p1.w);
            #pragma unroll
            for (int j = 0; j < 8; j++) {
                fma2(acc[0][j], av0, bv[j]);
                fma2(acc[1][j], av1, bv[j]);
                fma2(acc[2][j], av2, bv[j]);
                fma2(acc[3][j], av3, bv[j]);
            }
        }
    }
    const int col0 = bn + tx * 4, col1 = bn + 32 + tx * 4;
    float bcol[8];
    if (EPI >= 1) {
        #pragma unroll
        for (int j = 0; j < 4; j++) { bcol[j] = bias[col0 + j]; bcol[4 + j] = bias[col1 + j]; }
    }
    #pragma unroll
    for (int i = 0; i < 4; i++) {
        int r0 = bm + ty * 8 + 2 * i;
        float o0[8], o1[8];
        #pragma unroll
        for (int j = 0; j < 8; j++) { float2 p = unp2(acc[i][j]); o0[j] = p.x; o1[j] = p.y; }
        if (EPI >= 1) {
            #pragma unroll
            for (int j = 0; j < 8; j++) { o0[j] += bcol[j]; o1[j] += bcol[j]; }
        }
        if (EPI == 2) {
            #pragma unroll
            for (int j = 0; j < 8; j++) { o0[j] = gelu_exact(o0[j]); o1[j] = gelu_exact(o1[j]); }
        }
        if (EPI == 3) {
            const float* rr0 = resid + (long)r0 * N;
            const float* rr1 = rr0 + N;
            #pragma unroll
            for (int j = 0; j < 4; j++) {
                o0[j] += rr0[col0 + j]; o0[4+j] += rr0[col1 + j];
                o1[j] += rr1[col0 + j]; o1[4+j] += rr1[col1 + j];
            }
        }
        float* c0 = C + (long)r0 * N;
        *(float4*)(c0 + col0) = make_float4(o0[0], o0[1], o0[2], o0[3]);
        *(float4*)(c0 + col1) = make_float4(o0[4], o0[5], o0[6], o0[7]);
        float* c1 = c0 + N;
        *(float4*)(c1 + col0) = make_float4(o1[0], o1[1], o1[2], o1[3]);
        *(float4*)(c1 + col1) = make_float4(o1[4], o1[5], o1[6], o1[7]);
    }
}

// =============================================================================
// dd GEMM (batched b,h): dd[n,m] = dn * q[n,:64] . proj[m,:64], + fused k-max.
// BM=256 (n), BN=64 (m), grid (16, 5, 32). K=64.
// =============================================================================
template<bool DO_MAX>
__global__ void __launch_bounds__(256) gemm_dd2(
    const float* __restrict__ Q, const float* __restrict__ P,
    float* __restrict__ DD, float* __restrict__ maxpart) {
    __shared__ float As[16][256];
    __shared__ float Bs[16][64];
    const int tid = threadIdx.x;
    const int bh = blockIdx.z;
    const int b = bh >> 3, hh = bh & 7;
    const int bm = blockIdx.x * 256, bn = blockIdx.y * 64;
    const int tx = tid & 7, ty = tid >> 3;
    u64t acc[4][8];
    #pragma unroll
    for (int i = 0; i < 4; i++)
        #pragma unroll
        for (int j = 0; j < 8; j++) acc[i][j] = 0ull;

    const float* Arow = Q + ((long)b * NPIX + bm + tid) * INNER + hh * DH;
    const int br = tid >> 2, bk = (tid & 3) * 4;
    const int mB = bn + br;
    const float* Brow = P + (long)mB * DH + bk;

    for (int k0 = 0; k0 < DH; k0 += 16) {
        float4 a[4];
        a[0] = *(const float4*)(Arow + k0);
        a[1] = *(const float4*)(Arow + k0 + 4);
        a[2] = *(const float4*)(Arow + k0 + 8);
        a[3] = *(const float4*)(Arow + k0 + 12);
        float4 bb = make_float4(0.f, 0.f, 0.f, 0.f);
        if (mB < MFEAT) bb = *(const float4*)(Brow + k0);
        __syncthreads();
        #pragma unroll
        for (int q = 0; q < 4; q++) {
            As[q*4+0][tid]=a[q].x; As[q*4+1][tid]=a[q].y;
            As[q*4+2][tid]=a[q].z; As[q*4+3][tid]=a[q].w;
        }
        Bs[bk+0][br]=bb.x; Bs[bk+1][br]=bb.y; Bs[bk+2][br]=bb.z; Bs[bk+3][br]=bb.w;
        __syncthreads();
        #pragma unroll
        for (int kk = 0; kk < 16; kk++) {
            const u64t* ap = (const u64t*)&As[kk][ty * 8];
            u64t av0 = ap[0], av1 = ap[1], av2 = ap[2], av3 = ap[3];
            float4 p0 = *(const float4*)&Bs[kk][tx * 4];
            float4 p1 = *(const float4*)&Bs[kk][32 + tx * 4];
            u64t bv[8];
            bv[0]=dup2(p0.x); bv[1]=dup2(p0.y); bv[2]=dup2(p0.z); bv[3]=dup2(p0.w);
            bv[4]=dup2(p1.x); bv[5]=dup2(p1.y); bv[6]=dup2(p1.z); bv[7]=dup2(p1.w);
            #pragma unroll
            for (int j = 0; j < 8; j++) {
                fma2(acc[0][j], av0, bv[j]);
                fma2(acc[1][j], av1, bv[j]);
                fma2(acc[2][j], av2, bv[j]);
                fma2(acc[3][j], av3, bv[j]);
            }
        }
    }
    const float dn = 0.35355339059327373f;  // 64^-0.25
    float* Cb = DD + (long)bh * NPIX * MP;
    const int col0 = bn + tx * 4, col1 = bn + 32 + tx * 4;
    float mx = -1e30f;
    const bool fullblk = (bn + 64 <= MFEAT);
    #pragma unroll
    for (int i = 0; i < 4; i++) {
        int r0 = bm + ty * 8 + 2 * i;
        float o0[8], o1[8];
        #pragma unroll
        for (int j = 0; j < 8; j++) {
            float2 p = unp2(acc[i][j]);
            o0[j] = dn * p.x; o1[j] = dn * p.y;
        }
        float* c0 = Cb + (long)r0 * MP;
        float* c1 = c0 + MP;
        if (fullblk) {
            *(float4*)(c0 + col0) = make_float4(o0[0], o0[1], o0[2], o0[3]);
            *(float4*)(c0 + col1) = make_float4(o0[4], o0[5], o0[6], o0[7]);
            *(float4*)(c1 + col0) = make_float4(o1[0], o1[1], o1[2], o1[3]);
            *(float4*)(c1 + col1) = make_float4(o1[4], o1[5], o1[6], o1[7]);
            if (DO_MAX) {
                #pragma unroll
                for (int j = 0; j < 8; j++) mx = fmaxf(mx, fmaxf(o0[j], o1[j]));
            }
        } else {
            #pragma unroll
            for (int j = 0; j < 4; j++) {
                int ca = col0 + j, cb2 = col1 + j;
                if (ca < MP) { c0[ca] = o0[j]; c1[ca] = o1[j]; }
                if (cb2 < MP) { c0[cb2] = o0[4+j]; c1[cb2] = o1[4+j]; }
                if (DO_MAX) {
                    if (ca < MFEAT) mx = fmaxf(mx, fmaxf(o0[j], o1[j]));
                    if (cb2 < MFEAT) mx = fmaxf(mx, fmaxf(o0[4+j], o1[4+j]));
                }
            }
        }
    }
    if (DO_MAX) {
        __shared__ float sm[8];
        mx = warpMax(mx);
        int lane = tid & 31, wid = tid >> 5;
        if (lane == 0) sm[wid] = mx;
        __syncthreads();
        if (tid == 0) {
            float m = sm[0];
            #pragma unroll
            for (int w = 1; w < 8; w++) m = fmaxf(m, sm[w]);
            maxpart[bh * 80 + blockIdx.x * 5 + blockIdx.y] = m;
        }
    }
}

__global__ void kmax_fin2(const float* __restrict__ part, float* __restrict__ kmax) {
    int bh = blockIdx.x;
    float v = -1e30f;
    for (int i = threadIdx.x; i < 80; i += 32) v = fmaxf(v, part[bh * 80 + i]);
    v = warpMax(v);
    if (threadIdx.x == 0) kmax[bh] = v;
}

// ---------------- finalize features ----------------
template<bool IS_QUERY>
__global__ void finalize_kernel(const float* __restrict__ QKV, float* __restrict__ DD,
                                const float* __restrict__ KM) {
    int w = (blockIdx.x * blockDim.x + threadIdx.x) >> 5;
    int lane = threadIdx.x & 31;
    int bh = w >> 12, n = w & (NPIX - 1);
    int b = bh >> 3, hh = bh & 7;
    const float* q = QKV + ((long)(b * NPIX + n)) * INNER + hh * DH;
    float ss = 0.f;
    #pragma unroll
    for (int d = lane; d < DH; d += 32) { float v = q[d]; ss += v * v; }
    ss = warpSum(ss);
    float diag = 0.0625f * ss;
    float* row = DD + (long)bh * NPIX * MP + (long)n * MP;
    float vals[9];
    float mx = -1e30f;
    #pragma unroll
    for (int i = 0; i < 9; i++) {
        int m = lane + i * 32;
        if (m < MFEAT) { vals[i] = row[m]; mx = fmaxf(mx, vals[i]); }
    }
    if (IS_QUERY) mx = warpMax(mx);
    else          mx = KM[bh];
    const float ratio = 0.06131393394849658f;
    #pragma unroll
    for (int i = 0; i < 9; i++) {
        int m = lane + i * 32;
        if (m < MP)
            row[m] = (m < MFEAT) ? ratio * (expf(vals[i] - diag - mx) + 1e-4f) : 0.f;
    }
}

// =============================================================================
// context split-K: CTP[sl][bh][m][d] = sum_{n in slice} kp[n,m] * v[n,d]
// tile m=64 x d=64, 128 threads, per-thread 4 m-rows (2 u64) x 8 d-cols.
// grid (5, CTX_SPLIT, 32)
// =============================================================================
__global__ void __launch_bounds__(128) gemm_ctx2(
    const float* __restrict__ KP, const float* __restrict__ V, float* __restrict__ CTP) {
    __shared__ float As[16][64];   // [n][m]
    __shared__ float Bs[16][64];   // [n][d]
    const int tid = threadIdx.x;
    const int bh = blockIdx.z;
    const int b = bh >> 3, hh = bh & 7;
    const int m0 = blockIdx.x * 64;
    const int sl = blockIdx.y;
    const int n0base = sl * (NPIX / CTX_SPLIT);
    const int tx = tid & 7, ty = tid >> 3;
    u64t acc[2][8];
    #pragma unroll
    for (int i = 0; i < 2; i++)
        #pragma unroll
        for (int j = 0; j < 8; j++) acc[i][j] = 0ull;

    const int lr = tid >> 3;          // n-row within tile (0..15)
    const int lq = (tid & 7) * 8;     // col offset (0..56)
    const float* kpB = KP + (long)bh * NPIX * MP;
    const float* vB = V + ((long)b * NPIX) * INNER + hh * DH;
    const bool mvalid = (m0 + lq) < MP;

    for (int n0 = n0base; n0 < n0base + NPIX / CTX_SPLIT; n0 += 16) {
        float4 a0 = make_float4(0.f,0.f,0.f,0.f), a1 = a0;
        if (mvalid) {
            const float* ar = kpB + (long)(n0 + lr) * MP + m0 + lq;
            a0 = *(const float4*)(ar);
            a1 = *(const float4*)(ar + 4);
        }
        const float* br = vB + (long)(n0 + lr) * INNER + lq;
        float4 b0 = *(const float4*)(br);
        float4 b1 = *(const float4*)(br + 4);
        __syncthreads();
        *(float4*)&As[lr][lq] = a0;
        *(float4*)&As[lr][lq + 4] = a1;
        *(float4*)&Bs[lr][lq] = b0;
        *(float4*)&Bs[lr][lq + 4] = b1;
        __syncthreads();
        #pragma unroll
        for (int kk = 0; kk < 16; kk++) {
            const u64t* ap = (const u64t*)&As[kk][ty * 4];
            u64t av0 = ap[0], av1 = ap[1];
            float4 p0 = *(const float4*)&Bs[kk][tx * 4];
            float4 p1 = *(const float4*)&Bs[kk][32 + tx * 4];
            u64t bv[8];
            bv[0]=dup2(p0.x); bv[1]=dup2(p0.y); bv[2]=dup2(p0.z); bv[3]=dup2(p0.w);
            bv[4]=dup2(p1.x); bv[5]=dup2(p1.y); bv[6]=dup2(p1.z); bv[7]=dup2(p1.w);
            #pragma unroll
            for (int j = 0; j < 8; j++) {
                fma2(acc[0][j], av0, bv[j]);
                fma2(acc[1][j], av1, bv[j]);
            }
        }
    }
    float* Cb = CTP + ((long)sl * BHN + bh) * MP * DH;
    const int col0 = tx * 4, col1 = 32 + tx * 4;
    #pragma unroll
    for (int i = 0; i < 2; i++) {
        int m = m0 + ty * 4 + 2 * i;
        if (m < MP) {
            float o0[8], o1[8];
            #pragma unroll
            for (int j = 0; j < 8; j++) { float2 p = unp2(acc[i][j]); o0[j]=p.x; o1[j]=p.y; }
            float* c0 = Cb + (long)m * DH;
            float* c1 = c0 + DH;
            *(float4*)(c0 + col0) = make_float4(o0[0],o0[1],o0[2],o0[3]);
            *(float4*)(c0 + col1) = make_float4(o0[4],o0[5],o0[6],o0[7]);
            *(float4*)(c1 + col0) = make_float4(o1[0],o1[1],o1[2],o1[3]);
            *(float4*)(c1 + col1) = make_float4(o1[4],o1[5],o1[6],o1[7]);
        }
    }
}

__global__ void ctx_reduce_kernel(const float* __restrict__ P, float* __restrict__ C) {
    long i = (long)blockIdx.x * 256 + threadIdx.x;
    const long TOT = (long)BHN * MP * DH;
    if (i < TOT) {
        float s = 0.f;
        #pragma unroll
        for (int sl = 0; sl < CTX_SPLIT; sl++) s += P[(long)sl * TOT + i];
        C[i] = s;
    }
}

// ---------------- ksum (2-stage deterministic) ----------------
__global__ void ksum_part_kernel(const float* __restrict__ KP, float* __restrict__ part) {
    int bh = blockIdx.y, sl = blockIdx.x;
    int m = threadIdx.x;
    const float* p = KP + (long)bh * NPIX * MP + (long)sl * 512 * MP + m;
    float s = 0.f;
    #pragma unroll 4
    for (int n = 0; n < 512; n++) s += p[(long)n * MP];
    part[((long)bh * 8 + sl) * MP + m] = s;
}
__global__ void ksum_fin_kernel(const float* __restrict__ part, float* __restrict__ ksum) {
    int bh = blockIdx.x, m = threadIdx.x;
    float s = 0.f;
    #pragma unroll
    for (int sl = 0; sl < 8; sl++) s += part[((long)bh * 8 + sl) * MP + m];
    ksum[bh * MP + m] = s;
}

// ---------------- denom ----------------
__global__ void denom_kernel(const float* __restrict__ QP, const float* __restrict__ KS,
                             float* __restrict__ D) {
    int w = (blockIdx.x * blockDim.x + threadIdx.x) >> 5;
    int lane = threadIdx.x & 31;
    int bh = w >> 12, n = w & (NPIX - 1);
    const float* row = QP + (long)bh * NPIX * MP + (long)n * MP;
    const float* ks = KS + bh * MP;
    float s = 0.f;
    #pragma unroll
    for (int i = 0; i < 9; i++) {
        int m = lane + i * 32;
        if (m < MP) s += row[m] * ks[m];
    }
    s = warpSum(s);
    if (lane == 0) D[bh * NPIX + n] = s;
}

// =============================================================================
// out GEMM: out[n,d] = (sum_m qp[n,m] ctx[m,d]) / denom[n]
// BM=256, N=64, K=MP=272. grid (16, 1, 32). B is [K][N] so no transpose needed.
// =============================================================================
__global__ void __launch_bounds__(256) gemm_out2(
    const float* __restrict__ QP, const float* __restrict__ CT,
    const float* __restrict__ D, float* __restrict__ AT) {
    __shared__ float As[16][256];
    __shared__ float Bs[16][64];   // [k][d] natural
    const int tid = threadIdx.x;
    const int bh = blockIdx.z;
    const int b = bh >> 3, hh = bh & 7;
    const int bm = blockIdx.x * 256;
    const int tx = tid & 7, ty = tid >> 3;
    u64t acc[4][8];
    #pragma unroll
    for (int i = 0; i < 4; i++)
        #pragma unroll
        for (int j = 0; j < 8; j++) acc[i][j] = 0ull;

    const float* Arow = QP + (long)bh * NPIX * MP + (long)(bm + tid) * MP;
    const float* Bb = CT + (long)bh * MP * DH;
    const int lr = tid >> 4, lq = (tid & 15) * 4;   // B loader: 16 k-rows x 64 d

    for (int k0 = 0; k0 < MP; k0 += 16) {
        float4 a[4];
        a[0] = *(const float4*)(Arow + k0);
        a[1] = *(const float4*)(Arow + k0 + 4);
        a[2] = *(const float4*)(Arow + k0 + 8);
        a[3] = *(const float4*)(Arow + k0 + 12);
        float4 bb = *(const float4*)(Bb + (long)(k0 + lr) * DH + lq);
        __syncthreads();
        #pragma unroll
        for (int q = 0; q < 4; q++) {
            As[q*4+0][tid]=a[q].x; As[q*4+1][tid]=a[q].y;
            As[q*4+2][tid]=a[q].z; As[q*4+3][tid]=a[q].w;
        }
        *(float4*)&Bs[lr][lq] = bb;
        __syncthreads();
        #pragma unroll
        for (int kk = 0; kk < 16; kk++) {
            const u64t* ap = (const u64t*)&As[kk][ty * 8];
            u64t av0 = ap[0], av1 = ap[1], av2 = ap[2], av3 = ap[3];
            float4 p0 = *(const float4*)&Bs[kk][tx * 4];
            float4 p1 = *(const float4*)&Bs[kk][32 + tx * 4];
            u64t bv[8];
            bv[0]=dup2(p0.x); bv[1]=dup2(p0.y); bv[2]=dup2(p0.z); bv[3]=dup2(p0.w);
            bv[4]=dup2(p1.x); bv[5]=dup2(p1.y); bv[6]=dup2(p1.z); bv[7]=dup2(p1.w);
            #pragma unroll
            for (int j = 0; j < 8; j++) {
                fma2(acc[0][j], av0, bv[j]);
                fma2(acc[1][j], av1, bv[j]);
                fma2(acc[2][j], av2, bv[j]);
                fma2(acc[3][j], av3, bv[j]);
            }
        }
    }
    const int col0 = tx * 4, col1 = 32 + tx * 4;
    #pragma unroll
    for (int i = 0; i < 4; i++) {
        int n0 = bm + ty * 8 + 2 * i;
        float rd0 = 1.0f / D[bh * NPIX + n0];
        float rd1 = 1.0f / D[bh * NPIX + n0 + 1];
        float o0[8], o1[8];
        #pragma unroll
        for (int j = 0; j < 8; j++) {
            float2 p = unp2(acc[i][j]);
            o0[j] = p.x * rd0; o1[j] = p.y * rd1;
        }
        float* c0 = AT + ((long)(b * NPIX + n0)) * INNER + hh * DH;
        float* c1 = c0 + INNER;
        *(float4*)(c0 + col0) = make_float4(o0[0],o0[1],o0[2],o0[3]);
        *(float4*)(c0 + col1) = make_float4(o0[4],o0[5],o0[6],o0[7]);
        *(float4*)(c1 + col0) = make_float4(o1[0],o1[1],o1[2],o1[3]);
        *(float4*)(c1 + col1) = make_float4(o1[4],o1[5],o1[6],o1[7]);
    }
}

// ---------------- group norm + NHWC -> NCHW ----------------
__global__ void groupnorm_kernel(const float* __restrict__ Y, const float* __restrict__ G,
                                 const float* __restrict__ Bt, float* __restrict__ Z) {
    int b = blockIdx.x >> 3, grp = blockIdx.x & 7;
    const int CPG = 24, NELEM = CPG * NPIX;
    float s = 0.f, s2 = 0.f;
    for (int t = threadIdx.x; t < NELEM; t += 256) {
        int c = grp * CPG + (t % CPG);
        int pix = t / CPG;
        float v = Y[((long)b * NPIX + pix) * DIM + c];
        s += v; s2 += v * v;
    }
    __shared__ float ssum[8], ssq[8];
    int lane = threadIdx.x & 31, wid = threadIdx.x >> 5;
    s = warpSum(s); s2 = warpSum(s2);
    if (lane == 0) { ssum[wid] = s; ssq[wid] = s2; }
    __syncthreads();
    if (wid == 0) {
        float a = (lane < 8) ? ssum[lane] : 0.f;
        float b2 = (lane < 8) ? ssq[lane] : 0.f;
        a = warpSum(a); b2 = warpSum(b2);
        if (lane == 0) { ssum[0] = a; ssq[0] = b2; }
    }
    __syncthreads();
    float mu = ssum[0] / NELEM;
    float var = ssq[0] / NELEM - mu * mu;
    float rstd = rsqrtf(var + 1e-5f);
    for (int t = threadIdx.x; t < NELEM; t += 256) {
        int c = grp * CPG + (t % CPG);
        int pix = t / CPG;
        float v = Y[((long)b * NPIX + pix) * DIM + c];
        Z[((long)(b * DIM + c)) * NPIX + pix] = (v - mu) * rstd * G[c] + Bt[c];
    }
}

// ---------------- circular grouped conv + gelu ----------------
template<int CIN_G, int COUT_G, int KS, int CIN_TOTAL, int COUT_TOTAL, bool DO_GELU>
__global__ void __launch_bounds__(256) conv_circ(
    const float* __restrict__ IN, const float* __restrict__ W,
    const float* __restrict__ Bi, float* __restrict__ OUT) {
    const int PAD = KS / 2;
    const int HALO = 16 + 2 * PAD;
    __shared__ float s_in[HALO * HALO];
    __shared__ float s_w[COUT_G * KS * KS];
    int tile = blockIdx.x;
    int ty0 = (tile >> 2) * 16, tx0 = (tile & 3) * 16;
    int g = blockIdx.y, b = blockIdx.z;
    int tid = threadIdx.x;
    int tx = tid & 15, ty = tid >> 4;
    float acc[COUT_G];
    #pragma unroll
    for (int co = 0; co < COUT_G; co++) acc[co] = Bi[g * COUT_G + co];
    for (int ci = 0; ci < CIN_G; ci++) {
        for (int t = tid; t < HALO * HALO; t += 256) {
            int r = t / HALO, c = t % HALO;
            int gy = (ty0 + r - PAD) & 63;
            int gx = (tx0 + c - PAD) & 63;
            s_in[t] = IN[(((long)b * CIN_TOTAL + g * CIN_G + ci) * 64 + gy) * 64 + gx];
        }
        for (int t = tid; t < COUT_G * KS * KS; t += 256) {
            int co = t / (KS * KS), r = t % (KS * KS);
            s_w[t] = W[(((long)(g * COUT_G + co)) * CIN_G + ci) * (KS * KS) + r];
        }
        __syncthreads();
        #pragma unroll
        for (int ky = 0; ky < KS; ky++) {
            #pragma unroll
            for (int kx = 0; kx < KS; kx++) {
                float v = s_in[(ty + ky) * HALO + tx + kx];
                #pragma unroll
                for (int co = 0; co < COUT_G; co++)
                    acc[co] = fmaf(v, s_w[co * KS * KS + ky * KS + kx], acc[co]);
            }
        }
        __syncthreads();
    }
    #pragma unroll
    for (int co = 0; co < COUT_G; co++) {
        float v = DO_GELU ? gelu_exact(acc[co]) : acc[co];
        OUT[(((long)b * COUT_TOTAL + g * COUT_G + co) * 64 + ty0 + ty) * 64 + tx0 + tx] = v;
    }
}

// ---------------- 1x1 conv 48->3 ----------------
__global__ void conv1_kernel(const float* __restrict__ IN, const float* __restrict__ W,
                             const float* __restrict__ Bi, float* __restrict__ OUT) {
    int b = blockIdx.y;
    int pix = blockIdx.x * 256 + threadIdx.x;
    float a0 = Bi[0], a1 = Bi[1], a2 = Bi[2];
    #pragma unroll
    for (int c = 0; c < 48; c++) {
        float v = IN[((long)b * 48 + c) * NPIX + pix];
        a0 = fmaf(v, W[0 * 48 + c], a0);
        a1 = fmaf(v, W[1 * 48 + c], a1);
        a2 = fmaf(v, W[2 * 48 + c], a2);
    }
    long base = ((long)b * NPIX + pix) * 3;
    OUT[base + 0] = a0; OUT[base + 1] = a1; OUT[base + 2] = a2;
}

// ---------------- host ----------------
extern "C" void kernel_launch(void* const* d_in, const int* in_sizes, int n_in,
                              void* d_out, int out_size) {
    const float* x        = (const float*)d_in[0];
    const float* to_in_w  = (const float*)d_in[1];
    const float* to_in_b  = (const float*)d_in[2];
    const float* pos_emb  = (const float*)d_in[3];
    const float* proj     = (const float*)d_in[4];
    const float* sn_attn_g= (const float*)d_in[5];
    const float* wq       = (const float*)d_in[6];
    const float* wk       = (const float*)d_in[7];
    const float* wv       = (const float*)d_in[8];
    const float* wo       = (const float*)d_in[9];
    const float* bo       = (const float*)d_in[10];
    const float* sn_ff_g  = (const float*)d_in[11];
    const float* w1       = (const float*)d_in[12];
    const float* b1       = (const float*)d_in[13];
    const float* w2       = (const float*)d_in[14];
    const float* b2       = (const float*)d_in[15];
    const float* expand_w = (const float*)d_in[16];
    const float* fwd_w    = (const float*)d_in[17];
    const float* dec_lin_w= (const float*)d_in[18];
    const float* dec_lin_b= (const float*)d_in[19];
    const float* gn_g     = (const float*)d_in[20];
    const float* gn_b     = (const float*)d_in[21];
    const float* c9_w     = (const float*)d_in[22];
    const float* c9_b     = (const float*)d_in[23];
    const float* c7_w     = (const float*)d_in[24];
    const float* c7_b     = (const float*)d_in[25];
    const float* c5_w     = (const float*)d_in[26];
    const float* c5_b     = (const float*)d_in[27];
    const float* c1_w     = (const float*)d_in[28];
    const float* c1_b     = (const float*)d_in[29];
    float* out = (float*)d_out;

    float *ph, *phn, *pq, *pk, *pv, *pqp, *pkp, *pctx, *pctxp, *pksum, *pkmax, *pkmp,
          *pksp, *pden, *pattn, *pff, *pt1, *pt2, *py, *pnchw, *pc9, *pc7, *pc5;
    cudaGetSymbolAddress((void**)&ph, g_h);
    cudaGetSymbolAddress((void**)&phn, g_hn);
    cudaGetSymbolAddress((void**)&pq, g_q);
    cudaGetSymbolAddress((void**)&pk, g_k);
    cudaGetSymbolAddress((void**)&pv, g_v);
    cudaGetSymbolAddress((void**)&pqp, g_qp);
    cudaGetSymbolAddress((void**)&pkp, g_kp);
    cudaGetSymbolAddress((void**)&pctx, g_ctx);
    cudaGetSymbolAddress((void**)&pctxp, g_ctxp);
    cudaGetSymbolAddress((void**)&pksum, g_ksum);
    cudaGetSymbolAddress((void**)&pkmax, g_kmax);
    cudaGetSymbolAddress((void**)&pkmp, g_kmpart);
    cudaGetSymbolAddress((void**)&pksp, g_kspart);
    cudaGetSymbolAddress((void**)&pden, g_denom);
    cudaGetSymbolAddress((void**)&pattn, g_attn);
    cudaGetSymbolAddress((void**)&pff, g_ff);
    cudaGetSymbolAddress((void**)&pt1, g_t1);
    cudaGetSymbolAddress((void**)&pt2, g_t2);
    cudaGetSymbolAddress((void**)&py, g_y);
    cudaGetSymbolAddress((void**)&pnchw, g_nchw);
    cudaGetSymbolAddress((void**)&pc9, g_c9o);
    cudaGetSymbolAddress((void**)&pc7, g_c7o);
    cudaGetSymbolAddress((void**)&pc5, g_c5o);

    embed_kernel<<<ROWS, DIM>>>(x, to_in_w, to_in_b, pos_emb, ph);

    const long CTOT = (long)BHN * MP * DH;
    for (int i = 0; i < DEPTH; i++) {
        const float* proj_i = proj + (long)i * MFEAT * DH;
        scalenorm_kernel<<<2048, 256>>>(ph, phn, sn_attn_g, i);
        gemm_f2n128<0><<<dim3(128, 4), 256>>>(phn, wq + (long)i * INNER * DIM, nullptr, nullptr, pq, ROWS, INNER, DIM);
        gemm_f2n128<0><<<dim3(128, 4), 256>>>(phn, wk + (long)i * INNER * DIM, nullptr, nullptr, pk, ROWS, INNER, DIM);
        gemm_f2n128<0><<<dim3(128, 4), 256>>>(phn, wv + (long)i * INNER * DIM, nullptr, nullptr, pv, ROWS, INNER, DIM);
        gemm_dd2<false><<<dim3(16, 5, BHN), 256>>>(pq, proj_i, pqp, nullptr);
        gemm_dd2<true ><<<dim3(16, 5, BHN), 256>>>(pk, proj_i, pkp, pkmp);
        kmax_fin2<<<BHN, 32>>>(pkmp, pkmax);
        finalize_kernel<true ><<<16384, 256>>>(pq, pqp, nullptr);
        finalize_kernel<false><<<16384, 256>>>(pk, pkp, pkmax);
        gemm_ctx2<<<dim3(5, CTX_SPLIT, BHN), 128>>>(pkp, pv, pctxp);
        ctx_reduce_kernel<<<(int)((CTOT + 255) / 256), 256>>>(pctxp, pctx);
        ksum_part_kernel<<<dim3(8, BHN), MP>>>(pkp, pksp);
        ksum_fin_kernel<<<BHN, MP>>>(pksp, pksum);
        denom_kernel<<<16384, 256>>>(pqp, pksum, pden);
        gemm_out2<<<dim3(16, 1, BHN), 256>>>(pqp, pctx, pden, pattn);
        gemm_f2n64<3><<<dim3(64, 3), 256>>>(pattn, wo + (long)i * DIM * INNER, bo + (long)i * DIM, ph, ph, ROWS, DIM, INNER);
        scalenorm_kernel<<<2048, 256>>>(ph, phn, sn_ff_g, i);
        gemm_f2n128<2><<<dim3(128, 6), 256>>>(phn, w1 + (long)i * FF * DIM, b1 + (long)i * FF, nullptr, pff, ROWS, FF, DIM);
        gemm_f2n64<3><<<dim3(64, 3), 256>>>(pff, w2 + (long)i * DIM * FF, b2 + (long)i * DIM, ph, ph, ROWS, DIM, FF);
    }

    gemm_f2n64<0><<<dim3(64, 3), 256>>>(ph, expand_w, nullptr, nullptr, pt1, ROWS, DIM, DIM);
    gemm_f2n64<0><<<dim3(64, 3), 256>>>(pt1, fwd_w, nullptr, nullptr, pt2, ROWS, DIM, DIM);
    gemm_f2n64<1><<<dim3(64, 3), 256>>>(pt2, dec_lin_w, dec_lin_b, nullptr, py, ROWS, DIM, DIM);

    groupnorm_kernel<<<32, 256>>>(py, gn_g, gn_b, pnchw);
    conv_circ<24, 24, 9, 192, 192, true><<<dim3(16, 8, 4), 256>>>(pnchw, c9_w, c9_b, pc9);
    conv_circ<24, 12, 7, 192,  96, true><<<dim3(16, 8, 4), 256>>>(pc9, c7_w, c7_b, pc7);
    conv_circ<12,  6, 5,  96,  48, true><<<dim3(16, 8, 4), 256>>>(pc7, c5_w, c5_b, pc5);
    conv1_kernel<<<dim3(16, 4), 256>>>(pc5, c1_w, c1_b, out);
}

// round 7
// speedup vs baseline: 2.5784x; 1.0838x over previous
#include <cuda_runtime.h>
#include <cuda_bf16.h>
#include <math.h>

// ---------------- constants ----------------
#define BATCH 4
#define NPIX  4096          // 64*64
#define ROWS  16384         // BATCH*NPIX
#define DIM   192
#define DEPTH 6
#define HEADS 8
#define DH    64
#define INNER 512
#define FF    768
#define MFEAT 266
#define MP    272           // padded feature dim (mult of 16)
#define BHN   32            // BATCH*HEADS
#define CTX_SPLIT 8         // split-K slices for context GEMM

typedef unsigned long long u64t;

__device__ __forceinline__ float gelu_exact(float x) {
    return 0.5f * x * (1.0f + erff(x * 0.70710678118654752f));
}
__device__ __forceinline__ float warpSum(float v) {
    #pragma unroll
    for (int o = 16; o; o >>= 1) v += __shfl_xor_sync(0xffffffffu, v, o);
    return v;
}
__device__ __forceinline__ float warpMax(float v) {
    #pragma unroll
    for (int o = 16; o; o >>= 1) v = fmaxf(v, __shfl_xor_sync(0xffffffffu, v, o));
    return v;
}
// packed fp32x2 helpers (Blackwell FFMA2 — bitwise identical to 2x scalar fmaf)
__device__ __forceinline__ void fma2(u64t& d, u64t a, u64t b) {
    asm("fma.rn.f32x2 %0, %1, %2, %3;" : "=l"(d) : "l"(a), "l"(b), "l"(d));
}
__device__ __forceinline__ u64t dup2(float v) {
    u64t r; asm("mov.b64 %0, {%1, %1};" : "=l"(r) : "f"(v)); return r;
}
__device__ __forceinline__ float2 unp2(u64t v) {
    float2 r; asm("mov.b64 {%0, %1}, %2;" : "=f"(r.x), "=f"(r.y) : "l"(v)); return r;
}

// ---------------- scratch (device globals; no allocs allowed) ----------------
__device__ float g_h   [ROWS * DIM];
__device__ float g_hn  [ROWS * DIM];
__device__ float g_q   [ROWS * INNER];
__device__ float g_k   [ROWS * INNER];
__device__ float g_v   [ROWS * INNER];
__device__ float g_qp  [(long)BHN * NPIX * MP];
__device__ float g_kp  [(long)BHN * NPIX * MP];
__device__ float g_ctx [BHN * MP * DH];
__device__ float g_ctxp[(long)CTX_SPLIT * BHN * MP * DH];
__device__ float g_ksum[BHN * MP];
__device__ float g_kmax[BHN];
__device__ float g_kmpart[BHN * 160];
__device__ float g_kspart[BHN * 8 * MP];
__device__ float g_denom[BHN * NPIX];
__device__ float g_attn[ROWS * INNER];
__device__ float g_ff  [ROWS * FF];
__device__ float g_t1  [ROWS * DIM];
__device__ float g_t2  [ROWS * DIM];
__device__ float g_y   [ROWS * DIM];
__device__ float g_nchw[BATCH * 192 * 64 * 64];
__device__ float g_c9o [BATCH * 192 * 64 * 64];
__device__ float g_c7o [BATCH * 96 * 64 * 64];
__device__ float g_c5o [BATCH * 48 * 64 * 64];

// ---------------- embed ----------------
__global__ void embed_kernel(const float* __restrict__ x, const float* __restrict__ W,
                             const float* __restrict__ bias, const float* __restrict__ pos,
                             float* __restrict__ H) {
    int row = blockIdx.x;
    int c = threadIdx.x;
    int n = row & (NPIX - 1);
    const float* xr = x + (long)row * 3;
    float v = bias[c] + xr[0] * W[c * 3 + 0] + xr[1] * W[c * 3 + 1] + xr[2] * W[c * 3 + 2]
            + pos[(long)n * DIM + c];
    H[(long)row * DIM + c] = v;
}

// ---------------- scalenorm ----------------
__global__ void scalenorm_kernel(const float* __restrict__ in, float* __restrict__ out,
                                 const float* __restrict__ gArr, int gIdx) {
    int w = (blockIdx.x * blockDim.x + threadIdx.x) >> 5;
    int lane = threadIdx.x & 31;
    if (w >= ROWS) return;
    const float* r = in + (long)w * DIM;
    float ss = 0.f;
    #pragma unroll
    for (int c = lane; c < DIM; c += 32) { float v = r[c]; ss += v * v; }
    ss = warpSum(ss);
    float nrm = sqrtf(ss) * 0.07216878364870323f;
    float s = gArr[gIdx] / fmaxf(nrm, 1e-5f);
    #pragma unroll
    for (int c = lane; c < DIM; c += 32) out[(long)w * DIM + c] = r[c] * s;
}

// =============================================================================
// Double-buffered FFMA2 GEMM body, BN=128: C[M,N]=A[M,K]@B[N,K]^T.
// 256 threads, BM=128 BN=128 BK=16, one __syncthreads per k-tile.
// EPI: 0 none, 1 +bias, 2 gelu(+bias), 3 +bias+resid
// =============================================================================
template<int EPI>
__device__ __forceinline__ void gemm_n128_body(
    const float* __restrict__ A, const float* __restrict__ B,
    const float* __restrict__ bias, const float* __restrict__ resid,
    float* __restrict__ C, int N, int K) {
    __shared__ float As[2][16][128];
    __shared__ float Bs[2][16][128];
    const int tid = threadIdx.x;
    const int bm = blockIdx.x * 128, bn = blockIdx.y * 128;
    const int tx = tid & 15, ty = tid >> 4;
    u64t acc[4][8];
    #pragma unroll
    for (int i = 0; i < 4; i++)
        #pragma unroll
        for (int j = 0; j < 8; j++) acc[i][j] = 0ull;

    const int lr = tid >> 1, lk = (tid & 1) * 8;
    const float* Arow = A + (long)(bm + lr) * K + lk;
    const float* Brow = B + (long)(bn + lr) * K + lk;

    {
        float4 a0 = *(const float4*)(Arow),     a1 = *(const float4*)(Arow + 4);
        float4 b0 = *(const float4*)(Brow),     b1 = *(const float4*)(Brow + 4);
        As[0][lk+0][lr]=a0.x; As[0][lk+1][lr]=a0.y; As[0][lk+2][lr]=a0.z; As[0][lk+3][lr]=a0.w;
        As[0][lk+4][lr]=a1.x; As[0][lk+5][lr]=a1.y; As[0][lk+6][lr]=a1.z; As[0][lk+7][lr]=a1.w;
        Bs[0][lk+0][lr]=b0.x; Bs[0][lk+1][lr]=b0.y; Bs[0][lk+2][lr]=b0.z; Bs[0][lk+3][lr]=b0.w;
        Bs[0][lk+4][lr]=b1.x; Bs[0][lk+5][lr]=b1.y; Bs[0][lk+6][lr]=b1.z; Bs[0][lk+7][lr]=b1.w;
    }
    __syncthreads();
    int buf = 0;
    for (int k0 = 16; k0 <= K; k0 += 16) {
        const bool more = (k0 < K);
        float4 a0, a1, b0, b1;
        if (more) {
            a0 = *(const float4*)(Arow + k0); a1 = *(const float4*)(Arow + k0 + 4);
            b0 = *(const float4*)(Brow + k0); b1 = *(const float4*)(Brow + k0 + 4);
        }
        const float (*Ac)[128] = As[buf];
        const float (*Bc)[128] = Bs[buf];
        #pragma unroll
        for (int kk = 0; kk < 16; kk++) {
            const u64t* ap = (const u64t*)&Ac[kk][ty * 8];
            u64t av0 = ap[0], av1 = ap[1], av2 = ap[2], av3 = ap[3];
            float4 p0 = *(const float4*)&Bc[kk][tx * 4];
            float4 p1 = *(const float4*)&Bc[kk][64 + tx * 4];
            u64t bv[8];
            bv[0]=dup2(p0.x); bv[1]=dup2(p0.y); bv[2]=dup2(p0.z); bv[3]=dup2(p0.w);
            bv[4]=dup2(p1.x); bv[5]=dup2(p1.y); bv[6]=dup2(p1.z); bv[7]=dup2(p1.w);
            #pragma unroll
            for (int j = 0; j < 8; j++) {
                fma2(acc[0][j], av0, bv[j]);
                fma2(acc[1][j], av1, bv[j]);
                fma2(acc[2][j], av2, bv[j]);
                fma2(acc[3][j], av3, bv[j]);
            }
        }
        if (more) {
            float (*An)[128] = As[buf ^ 1];
            float (*Bn)[128] = Bs[buf ^ 1];
            An[lk+0][lr]=a0.x; An[lk+1][lr]=a0.y; An[lk+2][lr]=a0.z; An[lk+3][lr]=a0.w;
            An[lk+4][lr]=a1.x; An[lk+5][lr]=a1.y; An[lk+6][lr]=a1.z; An[lk+7][lr]=a1.w;
            Bn[lk+0][lr]=b0.x; Bn[lk+1][lr]=b0.y; Bn[lk+2][lr]=b0.z; Bn[lk+3][lr]=b0.w;
            Bn[lk+4][lr]=b1.x; Bn[lk+5][lr]=b1.y; Bn[lk+6][lr]=b1.z; Bn[lk+7][lr]=b1.w;
        }
        __syncthreads();
        buf ^= 1;
    }
    const int col0 = bn + tx * 4, col1 = bn + 64 + tx * 4;
    float bcol[8];
    if (EPI >= 1) {
        #pragma unroll
        for (int j = 0; j < 4; j++) { bcol[j] = bias[col0 + j]; bcol[4 + j] = bias[col1 + j]; }
    }
    #pragma unroll
    for (int i = 0; i < 4; i++) {
        int r0 = bm + ty * 8 + 2 * i;
        float o0[8], o1[8];
        #pragma unroll
        for (int j = 0; j < 8; j++) { float2 p = unp2(acc[i][j]); o0[j] = p.x; o1[j] = p.y; }
        if (EPI >= 1) {
            #pragma unroll
            for (int j = 0; j < 8; j++) { o0[j] += bcol[j]; o1[j] += bcol[j]; }
        }
        if (EPI == 2) {
            #pragma unroll
            for (int j = 0; j < 8; j++) { o0[j] = gelu_exact(o0[j]); o1[j] = gelu_exact(o1[j]); }
        }
        if (EPI == 3) {
            const float* rr0 = resid + (long)r0 * N;
            const float* rr1 = rr0 + N;
            #pragma unroll
            for (int j = 0; j < 4; j++) {
                o0[j] += rr0[col0 + j]; o0[4+j] += rr0[col1 + j];
                o1[j] += rr1[col0 + j]; o1[4+j] += rr1[col1 + j];
            }
        }
        float* c0 = C + (long)r0 * N;
        *(float4*)(c0 + col0) = make_float4(o0[0], o0[1], o0[2], o0[3]);
        *(float4*)(c0 + col1) = make_float4(o0[4], o0[5], o0[6], o0[7]);
        float* c1 = c0 + N;
        *(float4*)(c1 + col0) = make_float4(o1[0], o1[1], o1[2], o1[3]);
        *(float4*)(c1 + col1) = make_float4(o1[4], o1[5], o1[6], o1[7]);
    }
}

// fused QKV (same A; B/C selected by blockIdx.z)
__global__ void __launch_bounds__(256, 2) gemm_qkv_f2(
    const float* __restrict__ A, const float* __restrict__ Bq,
    const float* __restrict__ Bk, const float* __restrict__ Bv,
    float* __restrict__ Cq, float* __restrict__ Ck, float* __restrict__ Cv) {
    const float* B = (blockIdx.z == 0) ? Bq : (blockIdx.z == 1) ? Bk : Bv;
    float* C = (blockIdx.z == 0) ? Cq : (blockIdx.z == 1) ? Ck : Cv;
    gemm_n128_body<0>(A, B, nullptr, nullptr, C, INNER, DIM);
}

template<int EPI>
__global__ void __launch_bounds__(256, 2) gemm_f2n128k(
    const float* __restrict__ A, const float* __restrict__ B,
    const float* __restrict__ bias, const float* __restrict__ resid,
    float* __restrict__ C, int N, int K) {
    gemm_n128_body<EPI>(A, B, bias, resid, C, N, K);
}

// =============================================================================
// Double-buffered FFMA2 GEMM body, BN=64: BM=128, 256 threads,
// per-thread 4 rows (2 u64) x 8 cols. ~70 regs -> 3 CTAs/SM.
// =============================================================================
template<int EPI>
__device__ __forceinline__ void gemm_n64_body(
    const float* __restrict__ A, const float* __restrict__ B,
    const float* __restrict__ bias, const float* __restrict__ resid,
    float* __restrict__ C, int N, int K) {
    __shared__ float As[2][16][128];
    __shared__ float Bs[2][16][64];
    const int tid = threadIdx.x;
    const int bm = blockIdx.x * 128, bn = blockIdx.y * 64;
    const int tx = tid & 7, ty = tid >> 3;
    u64t acc[2][8];
    #pragma unroll
    for (int i = 0; i < 2; i++)
        #pragma unroll
        for (int j = 0; j < 8; j++) acc[i][j] = 0ull;

    const int lr = tid >> 1, lk = (tid & 1) * 8;
    const float* Arow = A + (long)(bm + lr) * K + lk;
    const int br = tid >> 2, bk = (tid & 3) * 4;
    const float* Brow = B + (long)(bn + br) * K + bk;

    {
        float4 a0 = *(const float4*)(Arow), a1 = *(const float4*)(Arow + 4);
        float4 bb = *(const float4*)(Brow);
        As[0][lk+0][lr]=a0.x; As[0][lk+1][lr]=a0.y; As[0][lk+2][lr]=a0.z; As[0][lk+3][lr]=a0.w;
        As[0][lk+4][lr]=a1.x; As[0][lk+5][lr]=a1.y; As[0][lk+6][lr]=a1.z; As[0][lk+7][lr]=a1.w;
        Bs[0][bk+0][br]=bb.x; Bs[0][bk+1][br]=bb.y; Bs[0][bk+2][br]=bb.z; Bs[0][bk+3][br]=bb.w;
    }
    __syncthreads();
    int buf = 0;
    for (int k0 = 16; k0 <= K; k0 += 16) {
        const bool more = (k0 < K);
        float4 a0, a1, bb;
        if (more) {
            a0 = *(const float4*)(Arow + k0); a1 = *(const float4*)(Arow + k0 + 4);
            bb = *(const float4*)(Brow + k0);
        }
        const float (*Ac)[128] = As[buf];
        const float (*Bc)[64] = Bs[buf];
        #pragma unroll
        for (int kk = 0; kk < 16; kk++) {
            const u64t* ap = (const u64t*)&Ac[kk][ty * 4];
            u64t av0 = ap[0], av1 = ap[1];
            float4 p0 = *(const float4*)&Bc[kk][tx * 4];
            float4 p1 = *(const float4*)&Bc[kk][32 + tx * 4];
            u64t bv[8];
            bv[0]=dup2(p0.x); bv[1]=dup2(p0.y); bv[2]=dup2(p0.z); bv[3]=dup2(p0.w);
            bv[4]=dup2(p1.x); bv[5]=dup2(p1.y); bv[6]=dup2(p1.z); bv[7]=dup2(p1.w);
            #pragma unroll
            for (int j = 0; j < 8; j++) {
                fma2(acc[0][j], av0, bv[j]);
                fma2(acc[1][j], av1, bv[j]);
            }
        }
        if (more) {
            float (*An)[128] = As[buf ^ 1];
            float (*Bn)[64] = Bs[buf ^ 1];
            An[lk+0][lr]=a0.x; An[lk+1][lr]=a0.y; An[lk+2][lr]=a0.z; An[lk+3][lr]=a0.w;
            An[lk+4][lr]=a1.x; An[lk+5][lr]=a1.y; An[lk+6][lr]=a1.z; An[lk+7][lr]=a1.w;
            Bn[bk+0][br]=bb.x; Bn[bk+1][br]=bb.y; Bn[bk+2][br]=bb.z; Bn[bk+3][br]=bb.w;
        }
        __syncthreads();
        buf ^= 1;
    }
    const int col0 = bn + tx * 4, col1 = bn + 32 + tx * 4;
    float bcol[8];
    if (EPI >= 1) {
        #pragma unroll
        for (int j = 0; j < 4; j++) { bcol[j] = bias[col0 + j]; bcol[4 + j] = bias[col1 + j]; }
    }
    #pragma unroll
    for (int i = 0; i < 2; i++) {
        int r0 = bm + ty * 4 + 2 * i;
        float o0[8], o1[8];
        #pragma unroll
        for (int j = 0; j < 8; j++) { float2 p = unp2(acc[i][j]); o0[j] = p.x; o1[j] = p.y; }
        if (EPI >= 1) {
            #pragma unroll
            for (int j = 0; j < 8; j++) { o0[j] += bcol[j]; o1[j] += bcol[j]; }
        }
        if (EPI == 2) {
            #pragma unroll
            for (int j = 0; j < 8; j++) { o0[j] = gelu_exact(o0[j]); o1[j] = gelu_exact(o1[j]); }
        }
        if (EPI == 3) {
            const float* rr0 = resid + (long)r0 * N;
            const float* rr1 = rr0 + N;
            #pragma unroll
            for (int j = 0; j < 4; j++) {
                o0[j] += rr0[col0 + j]; o0[4+j] += rr0[col1 + j];
                o1[j] += rr1[col0 + j]; o1[4+j] += rr1[col1 + j];
            }
        }
        float* c0 = C + (long)r0 * N;
        *(float4*)(c0 + col0) = make_float4(o0[0], o0[1], o0[2], o0[3]);
        *(float4*)(c0 + col1) = make_float4(o0[4], o0[5], o0[6], o0[7]);
        float* c1 = c0 + N;
        *(float4*)(c1 + col0) = make_float4(o1[0], o1[1], o1[2], o1[3]);
        *(float4*)(c1 + col1) = make_float4(o1[4], o1[5], o1[6], o1[7]);
    }
}

template<int EPI>
__global__ void __launch_bounds__(256, 2) gemm_f2n64k(
    const float* __restrict__ A, const float* __restrict__ B,
    const float* __restrict__ bias, const float* __restrict__ resid,
    float* __restrict__ C, int N, int K) {
    gemm_n64_body<EPI>(A, B, bias, resid, C, N, K);
}

// =============================================================================
// dd GEMM (batched b,h), BM=128 BN=64, K=64, double-buffered, fused k-max.
// grid (32, 5, 32)
// =============================================================================
template<bool DO_MAX>
__global__ void __launch_bounds__(256, 2) gemm_dd2(
    const float* __restrict__ Q, const float* __restrict__ P,
    float* __restrict__ DD, float* __restrict__ maxpart) {
    __shared__ float As[2][16][128];
    __shared__ float Bs[2][16][64];
    const int tid = threadIdx.x;
    const int bh = blockIdx.z;
    const int b = bh >> 3, hh = bh & 7;
    const int bm = blockIdx.x * 128, bn = blockIdx.y * 64;
    const int tx = tid & 7, ty = tid >> 3;
    u64t acc[2][8];
    #pragma unroll
    for (int i = 0; i < 2; i++)
        #pragma unroll
        for (int j = 0; j < 8; j++) acc[i][j] = 0ull;

    const int lr = tid >> 1, lk = (tid & 1) * 8;
    const float* Arow = Q + ((long)b * NPIX + bm + lr) * INNER + hh * DH + lk;
    const int br = tid >> 2, bk = (tid & 3) * 4;
    const int mB = bn + br;
    const float* Brow = P + (long)mB * DH + bk;
    const bool bval = (mB < MFEAT);

    {
        float4 a0 = *(const float4*)(Arow), a1 = *(const float4*)(Arow + 4);
        float4 bb = make_float4(0.f, 0.f, 0.f, 0.f);
        if (bval) bb = *(const float4*)(Brow);
        As[0][lk+0][lr]=a0.x; As[0][lk+1][lr]=a0.y; As[0][lk+2][lr]=a0.z; As[0][lk+3][lr]=a0.w;
        As[0][lk+4][lr]=a1.x; As[0][lk+5][lr]=a1.y; As[0][lk+6][lr]=a1.z; As[0][lk+7][lr]=a1.w;
        Bs[0][bk+0][br]=bb.x; Bs[0][bk+1][br]=bb.y; Bs[0][bk+2][br]=bb.z; Bs[0][bk+3][br]=bb.w;
    }
    __syncthreads();
    int buf = 0;
    for (int k0 = 16; k0 <= DH; k0 += 16) {
        const bool more = (k0 < DH);
        float4 a0, a1, bb;
        if (more) {
            a0 = *(const float4*)(Arow + k0); a1 = *(const float4*)(Arow + k0 + 4);
            bb = make_float4(0.f, 0.f, 0.f, 0.f);
            if (bval) bb = *(const float4*)(Brow + k0);
        }
        const float (*Ac)[128] = As[buf];
        const float (*Bc)[64] = Bs[buf];
        #pragma unroll
        for (int kk = 0; kk < 16; kk++) {
            const u64t* ap = (const u64t*)&Ac[kk][ty * 4];
            u64t av0 = ap[0], av1 = ap[1];
            float4 p0 = *(const float4*)&Bc[kk][tx * 4];
            float4 p1 = *(const float4*)&Bc[kk][32 + tx * 4];
            u64t bv[8];
            bv[0]=dup2(p0.x); bv[1]=dup2(p0.y); bv[2]=dup2(p0.z); bv[3]=dup2(p0.w);
            bv[4]=dup2(p1.x); bv[5]=dup2(p1.y); bv[6]=dup2(p1.z); bv[7]=dup2(p1.w);
            #pragma unroll
            for (int j = 0; j < 8; j++) {
                fma2(acc[0][j], av0, bv[j]);
                fma2(acc[1][j], av1, bv[j]);
            }
        }
        if (more) {
            float (*An)[128] = As[buf ^ 1];
            float (*Bn)[64] = Bs[buf ^ 1];
            An[lk+0][lr]=a0.x; An[lk+1][lr]=a0.y; An[lk+2][lr]=a0.z; An[lk+3][lr]=a0.w;
            An[lk+4][lr]=a1.x; An[lk+5][lr]=a1.y; An[lk+6][lr]=a1.z; An[lk+7][lr]=a1.w;
            Bn[bk+0][br]=bb.x; Bn[bk+1][br]=bb.y; Bn[bk+2][br]=bb.z; Bn[bk+3][br]=bb.w;
        }
        __syncthreads();
        buf ^= 1;
    }
    const float dn = 0.35355339059327373f;  // 64^-0.25
    float* Cb = DD + (long)bh * NPIX * MP;
    const int col0 = bn + tx * 4, col1 = bn + 32 + tx * 4;
    float mx = -1e30f;
    const bool fullblk = (bn + 64 <= MFEAT);
    #pragma unroll
    for (int i = 0; i < 2; i++) {
        int r0 = bm + ty * 4 + 2 * i;
        float o0[8], o1[8];
        #pragma unroll
        for (int j = 0; j < 8; j++) {
            float2 p = unp2(acc[i][j]);
            o0[j] = dn * p.x; o1[j] = dn * p.y;
        }
        float* c0 = Cb + (long)r0 * MP;
        float* c1 = c0 + MP;
        if (fullblk) {
            *(float4*)(c0 + col0) = make_float4(o0[0], o0[1], o0[2], o0[3]);
            *(float4*)(c0 + col1) = make_float4(o0[4], o0[5], o0[6], o0[7]);
            *(float4*)(c1 + col0) = make_float4(o1[0], o1[1], o1[2], o1[3]);
            *(float4*)(c1 + col1) = make_float4(o1[4], o1[5], o1[6], o1[7]);
            if (DO_MAX) {
                #pragma unroll
                for (int j = 0; j < 8; j++) mx = fmaxf(mx, fmaxf(o0[j], o1[j]));
            }
        } else {
            #pragma unroll
            for (int j = 0; j < 4; j++) {
                int ca = col0 + j, cb2 = col1 + j;
                if (ca < MP) { c0[ca] = o0[j]; c1[ca] = o1[j]; }
                if (cb2 < MP) { c0[cb2] = o0[4+j]; c1[cb2] = o1[4+j]; }
                if (DO_MAX) {
                    if (ca < MFEAT) mx = fmaxf(mx, fmaxf(o0[j], o1[j]));
                    if (cb2 < MFEAT) mx = fmaxf(mx, fmaxf(o0[4+j], o1[4+j]));
                }
            }
        }
    }
    if (DO_MAX) {
        __shared__ float sm[8];
        mx = warpMax(mx);
        int lane = tid & 31, wid = tid >> 5;
        if (lane == 0) sm[wid] = mx;
        __syncthreads();
        if (tid == 0) {
            float m = sm[0];
            #pragma unroll
            for (int w = 1; w < 8; w++) m = fmaxf(m, sm[w]);
            maxpart[bh * 160 + blockIdx.x * 5 + blockIdx.y] = m;
        }
    }
}

__global__ void kmax_fin2(const float* __restrict__ part, float* __restrict__ kmax) {
    int bh = blockIdx.x;
    float v = -1e30f;
    for (int i = threadIdx.x; i < 160; i += 32) v = fmaxf(v, part[bh * 160 + i]);
    v = warpMax(v);
    if (threadIdx.x == 0) kmax[bh] = v;
}

// ---------------- finalize features ----------------
template<bool IS_QUERY>
__global__ void finalize_kernel(const float* __restrict__ QKV, float* __restrict__ DD,
                                const float* __restrict__ KM) {
    int w = (blockIdx.x * blockDim.x + threadIdx.x) >> 5;
    int lane = threadIdx.x & 31;
    int bh = w >> 12, n = w & (NPIX - 1);
    int b = bh >> 3, hh = bh & 7;
    const float* q = QKV + ((long)(b * NPIX + n)) * INNER + hh * DH;
    float ss = 0.f;
    #pragma unroll
    for (int d = lane; d < DH; d += 32) { float v = q[d]; ss += v * v; }
    ss = warpSum(ss);
    float diag = 0.0625f * ss;
    float* row = DD + (long)bh * NPIX * MP + (long)n * MP;
    float vals[9];
    float mx = -1e30f;
    #pragma unroll
    for (int i = 0; i < 9; i++) {
        int m = lane + i * 32;
        if (m < MFEAT) { vals[i] = row[m]; mx = fmaxf(mx, vals[i]); }
    }
    if (IS_QUERY) mx = warpMax(mx);
    else          mx = KM[bh];
    const float ratio = 0.06131393394849658f;
    #pragma unroll
    for (int i = 0; i < 9; i++) {
        int m = lane + i * 32;
        if (m < MP)
            row[m] = (m < MFEAT) ? ratio * (expf(vals[i] - diag - mx) + 1e-4f) : 0.f;
    }
}

// =============================================================================
// context split-K (double-buffered): CTP[sl][bh][m][d] = sum_n kp[n,m] v[n,d]
// tile m=64 x d=64, 128 threads. grid (5, CTX_SPLIT, 32)
// =============================================================================
__global__ void __launch_bounds__(128, 4) gemm_ctx2(
    const float* __restrict__ KP, const float* __restrict__ V, float* __restrict__ CTP) {
    __shared__ float As[2][16][64];   // [n][m]
    __shared__ float Bs[2][16][64];   // [n][d]
    const int tid = threadIdx.x;
    const int bh = blockIdx.z;
    const int b = bh >> 3, hh = bh & 7;
    const int m0 = blockIdx.x * 64;
    const int sl = blockIdx.y;
    const int n0base = sl * (NPIX / CTX_SPLIT);
    const int nend = n0base + NPIX / CTX_SPLIT;
    const int tx = tid & 7, ty = tid >> 3;
    u64t acc[2][8];
    #pragma unroll
    for (int i = 0; i < 2; i++)
        #pragma unroll
        for (int j = 0; j < 8; j++) acc[i][j] = 0ull;

    const int lr = tid >> 3;          // n-row (0..15)
    const int lq = (tid & 7) * 8;     // col offset
    const float* kpB = KP + (long)bh * NPIX * MP;
    const float* vB = V + ((long)b * NPIX) * INNER + hh * DH;
    const bool mvalid = (m0 + lq) < MP;

    {
        float4 a0 = make_float4(0.f,0.f,0.f,0.f), a1 = a0;
        if (mvalid) {
            const float* ar = kpB + (long)(n0base + lr) * MP + m0 + lq;
            a0 = *(const float4*)(ar); a1 = *(const float4*)(ar + 4);
        }
        const float* brp = vB + (long)(n0base + lr) * INNER + lq;
        float4 b0 = *(const float4*)(brp), b1 = *(const float4*)(brp + 4);
        *(float4*)&As[0][lr][lq] = a0; *(float4*)&As[0][lr][lq + 4] = a1;
        *(float4*)&Bs[0][lr][lq] = b0; *(float4*)&Bs[0][lr][lq + 4] = b1;
    }
    __syncthreads();
    int buf = 0;
    for (int n0 = n0base + 16; n0 <= nend; n0 += 16) {
        const bool more = (n0 < nend);
        float4 a0, a1, b0, b1;
        if (more) {
            a0 = make_float4(0.f,0.f,0.f,0.f); a1 = a0;
            if (mvalid) {
                const float* ar = kpB + (long)(n0 + lr) * MP + m0 + lq;
                a0 = *(const float4*)(ar); a1 = *(const float4*)(ar + 4);
            }
            const float* brp = vB + (long)(n0 + lr) * INNER + lq;
            b0 = *(const float4*)(brp); b1 = *(const float4*)(brp + 4);
        }
        const float (*Ac)[64] = As[buf];
        const float (*Bc)[64] = Bs[buf];
        #pragma unroll
        for (int kk = 0; kk < 16; kk++) {
            const u64t* ap = (const u64t*)&Ac[kk][ty * 4];
            u64t av0 = ap[0], av1 = ap[1];
            float4 p0 = *(const float4*)&Bc[kk][tx * 4];
            float4 p1 = *(const float4*)&Bc[kk][32 + tx * 4];
            u64t bv[8];
            bv[0]=dup2(p0.x); bv[1]=dup2(p0.y); bv[2]=dup2(p0.z); bv[3]=dup2(p0.w);
            bv[4]=dup2(p1.x); bv[5]=dup2(p1.y); bv[6]=dup2(p1.z); bv[7]=dup2(p1.w);
            #pragma unroll
            for (int j = 0; j < 8; j++) {
                fma2(acc[0][j], av0, bv[j]);
                fma2(acc[1][j], av1, bv[j]);
            }
        }
        if (more) {
            *(float4*)&As[buf^1][lr][lq] = a0; *(float4*)&As[buf^1][lr][lq + 4] = a1;
            *(float4*)&Bs[buf^1][lr][lq] = b0; *(float4*)&Bs[buf^1][lr][lq + 4] = b1;
        }
        __syncthreads();
        buf ^= 1;
    }
    float* Cb = CTP + ((long)sl * BHN + bh) * MP * DH;
    const int col0 = tx * 4, col1 = 32 + tx * 4;
    #pragma unroll
    for (int i = 0; i < 2; i++) {
        int m = m0 + ty * 4 + 2 * i;
        if (m < MP) {
            float o0[8], o1[8];
            #pragma unroll
            for (int j = 0; j < 8; j++) { float2 p = unp2(acc[i][j]); o0[j]=p.x; o1[j]=p.y; }
            float* c0 = Cb + (long)m * DH;
            float* c1 = c0 + DH;
            *(float4*)(c0 + col0) = make_float4(o0[0],o0[1],o0[2],o0[3]);
            *(float4*)(c0 + col1) = make_float4(o0[4],o0[5],o0[6],o0[7]);
            *(float4*)(c1 + col0) = make_float4(o1[0],o1[1],o1[2],o1[3]);
            *(float4*)(c1 + col1) = make_float4(o1[4],o1[5],o1[6],o1[7]);
        }
    }
}

__global__ void ctx_reduce_kernel(const float* __restrict__ P, float* __restrict__ C) {
    long i = (long)blockIdx.x * 256 + threadIdx.x;
    const long TOT = (long)BHN * MP * DH;
    if (i < TOT) {
        float s = 0.f;
        #pragma unroll
        for (int sl = 0; sl < CTX_SPLIT; sl++) s += P[(long)sl * TOT + i];
        C[i] = s;
    }
}

// ---------------- ksum (2-stage deterministic) ----------------
__global__ void ksum_part_kernel(const float* __restrict__ KP, float* __restrict__ part) {
    int bh = blockIdx.y, sl = blockIdx.x;
    int m = threadIdx.x;
    const float* p = KP + (long)bh * NPIX * MP + (long)sl * 512 * MP + m;
    float s = 0.f;
    #pragma unroll 4
    for (int n = 0; n < 512; n++) s += p[(long)n * MP];
    part[((long)bh * 8 + sl) * MP + m] = s;
}
__global__ void ksum_fin_kernel(const float* __restrict__ part, float* __restrict__ ksum) {
    int bh = blockIdx.x, m = threadIdx.x;
    float s = 0.f;
    #pragma unroll
    for (int sl = 0; sl < 8; sl++) s += part[((long)bh * 8 + sl) * MP + m];
    ksum[bh * MP + m] = s;
}

// ---------------- denom ----------------
__global__ void denom_kernel(const float* __restrict__ QP, const float* __restrict__ KS,
                             float* __restrict__ D) {
    int w = (blockIdx.x * blockDim.x + threadIdx.x) >> 5;
    int lane = threadIdx.x & 31;
    int bh = w >> 12, n = w & (NPIX - 1);
    const float* row = QP + (long)bh * NPIX * MP + (long)n * MP;
    const float* ks = KS + bh * MP;
    float s = 0.f;
    #pragma unroll
    for (int i = 0; i < 9; i++) {
        int m = lane + i * 32;
        if (m < MP) s += row[m] * ks[m];
    }
    s = warpSum(s);
    if (lane == 0) D[bh * NPIX + n] = s;
}

// =============================================================================
// out GEMM (double-buffered): out[n,d] = (sum_m qp[n,m] ctx[m,d]) / denom[n]
// BM=128, N=64, K=MP=272. grid (32, 1, 32), 256 threads.
// =============================================================================
__global__ void __launch_bounds__(256, 2) gemm_out2(
    const float* __restrict__ QP, const float* __restrict__ CT,
    const float* __restrict__ D, float* __restrict__ AT) {
    __shared__ float As[2][16][128];
    __shared__ float Bs[2][16][64];   // [k][d] natural
    const int tid = threadIdx.x;
    const int bh = blockIdx.z;
    const int b = bh >> 3, hh = bh & 7;
    const int bm = blockIdx.x * 128;
    const int tx = tid & 7, ty = tid >> 3;
    u64t acc[2][8];
    #pragma unroll
    for (int i = 0; i < 2; i++)
        #pragma unroll
        for (int j = 0; j < 8; j++) acc[i][j] = 0ull;

    const int lr = tid >> 1, lk = (tid & 1) * 8;
    const float* Arow = QP + (long)bh * NPIX * MP + (long)(bm + lr) * MP + lk;
    const float* Bb = CT + (long)bh * MP * DH;
    const int lr2 = tid >> 4, lq = (tid & 15) * 4;   // B loader: 16 k-rows x 64 d

    {
        float4 a0 = *(const float4*)(Arow), a1 = *(const float4*)(Arow + 4);
        float4 bb = *(const float4*)(Bb + (long)lr2 * DH + lq);
        As[0][lk+0][lr]=a0.x; As[0][lk+1][lr]=a0.y; As[0][lk+2][lr]=a0.z; As[0][lk+3][lr]=a0.w;
        As[0][lk+4][lr]=a1.x; As[0][lk+5][lr]=a1.y; As[0][lk+6][lr]=a1.z; As[0][lk+7][lr]=a1.w;
        *(float4*)&Bs[0][lr2][lq] = bb;
    }
    __syncthreads();
    int buf = 0;
    for (int k0 = 16; k0 <= MP; k0 += 16) {
        const bool more = (k0 < MP);
        float4 a0, a1, bb;
        if (more) {
            a0 = *(const float4*)(Arow + k0); a1 = *(const float4*)(Arow + k0 + 4);
            bb = *(const float4*)(Bb + (long)(k0 + lr2) * DH + lq);
        }
        const float (*Ac)[128] = As[buf];
        const float (*Bc)[64] = Bs[buf];
        #pragma unroll
        for (int kk = 0; kk < 16; kk++) {
            const u64t* ap = (const u64t*)&Ac[kk][ty * 4];
            u64t av0 = ap[0], av1 = ap[1];
            float4 p0 = *(const float4*)&Bc[kk][tx * 4];
            float4 p1 = *(const float4*)&Bc[kk][32 + tx * 4];
            u64t bv[8];
            bv[0]=dup2(p0.x); bv[1]=dup2(p0.y); bv[2]=dup2(p0.z); bv[3]=dup2(p0.w);
            bv[4]=dup2(p1.x); bv[5]=dup2(p1.y); bv[6]=dup2(p1.z); bv[7]=dup2(p1.w);
            #pragma unroll
            for (int j = 0; j < 8; j++) {
                fma2(acc[0][j], av0, bv[j]);
                fma2(acc[1][j], av1, bv[j]);
            }
        }
        if (more) {
            float (*An)[128] = As[buf ^ 1];
            An[lk+0][lr]=a0.x; An[lk+1][lr]=a0.y; An[lk+2][lr]=a0.z; An[lk+3][lr]=a0.w;
            An[lk+4][lr]=a1.x; An[lk+5][lr]=a1.y; An[lk+6][lr]=a1.z; An[lk+7][lr]=a1.w;
            *(float4*)&Bs[buf ^ 1][lr2][lq] = bb;
        }
        __syncthreads();
        buf ^= 1;
    }
    const int col0 = tx * 4, col1 = 32 + tx * 4;
    #pragma unroll
    for (int i = 0; i < 2; i++) {
        int n0 = bm + ty * 4 + 2 * i;
        float rd0 = 1.0f / D[bh * NPIX + n0];
        float rd1 = 1.0f / D[bh * NPIX + n0 + 1];
        float o0[8], o1[8];
        #pragma unroll
        for (int j = 0; j < 8; j++) {
            float2 p = unp2(acc[i][j]);
            o0[j] = p.x * rd0; o1[j] = p.y * rd1;
        }
        float* c0 = AT + ((long)(b * NPIX + n0)) * INNER + hh * DH;
        float* c1 = c0 + INNER;
        *(float4*)(c0 + col0) = make_float4(o0[0],o0[1],o0[2],o0[3]);
        *(float4*)(c0 + col1) = make_float4(o0[4],o0[5],o0[6],o0[7]);
        *(float4*)(c1 + col0) = make_float4(o1[0],o1[1],o1[2],o1[3]);
        *(float4*)(c1 + col1) = make_float4(o1[4],o1[5],o1[6],o1[7]);
    }
}

// ---------------- group norm + NHWC -> NCHW ----------------
__global__ void groupnorm_kernel(const float* __restrict__ Y, const float* __restrict__ G,
                                 const float* __restrict__ Bt, float* __restrict__ Z) {
    int b = blockIdx.x >> 3, grp = blockIdx.x & 7;
    const int CPG = 24, NELEM = CPG * NPIX;
    float s = 0.f, s2 = 0.f;
    for (int t = threadIdx.x; t < NELEM; t += 256) {
        int c = grp * CPG + (t % CPG);
        int pix = t / CPG;
        float v = Y[((long)b * NPIX + pix) * DIM + c];
        s += v; s2 += v * v;
    }
    __shared__ float ssum[8], ssq[8];
    int lane = threadIdx.x & 31, wid = threadIdx.x >> 5;
    s = warpSum(s); s2 = warpSum(s2);
    if (lane == 0) { ssum[wid] = s; ssq[wid] = s2; }
    __syncthreads();
    if (wid == 0) {
        float a = (lane < 8) ? ssum[lane] : 0.f;
        float b2 = (lane < 8) ? ssq[lane] : 0.f;
        a = warpSum(a); b2 = warpSum(b2);
        if (lane == 0) { ssum[0] = a; ssq[0] = b2; }
    }
    __syncthreads();
    float mu = ssum[0] / NELEM;
    float var = ssq[0] / NELEM - mu * mu;
    float rstd = rsqrtf(var + 1e-5f);
    for (int t = threadIdx.x; t < NELEM; t += 256) {
        int c = grp * CPG + (t % CPG);
        int pix = t / CPG;
        float v = Y[((long)b * NPIX + pix) * DIM + c];
        Z[((long)(b * DIM + c)) * NPIX + pix] = (v - mu) * rstd * G[c] + Bt[c];
    }
}

// ---------------- circular grouped conv + gelu ----------------
template<int CIN_G, int COUT_G, int KS, int CIN_TOTAL, int COUT_TOTAL, bool DO_GELU>
__global__ void __launch_bounds__(256) conv_circ(
    const float* __restrict__ IN, const float* __restrict__ W,
    const float* __restrict__ Bi, float* __restrict__ OUT) {
    const int PAD = KS / 2;
    const int HALO = 16 + 2 * PAD;
    __shared__ float s_in[HALO * HALO];
    __shared__ float s_w[COUT_G * KS * KS];
    int tile = blockIdx.x;
    int ty0 = (tile >> 2) * 16, tx0 = (tile & 3) * 16;
    int g = blockIdx.y, b = blockIdx.z;
    int tid = threadIdx.x;
    int tx = tid & 15, ty = tid >> 4;
    float acc[COUT_G];
    #pragma unroll
    for (int co = 0; co < COUT_G; co++) acc[co] = Bi[g * COUT_G + co];
    for (int ci = 0; ci < CIN_G; ci++) {
        for (int t = tid; t < HALO * HALO; t += 256) {
            int r = t / HALO, c = t % HALO;
            int gy = (ty0 + r - PAD) & 63;
            int gx = (tx0 + c - PAD) & 63;
            s_in[t] = IN[(((long)b * CIN_TOTAL + g * CIN_G + ci) * 64 + gy) * 64 + gx];
        }
        for (int t = tid; t < COUT_G * KS * KS; t += 256) {
            int co = t / (KS * KS), r = t % (KS * KS);
            s_w[t] = W[(((long)(g * COUT_G + co)) * CIN_G + ci) * (KS * KS) + r];
        }
        __syncthreads();
        #pragma unroll
        for (int ky = 0; ky < KS; ky++) {
            #pragma unroll
            for (int kx = 0; kx < KS; kx++) {
                float v = s_in[(ty + ky) * HALO + tx + kx];
                #pragma unroll
                for (int co = 0; co < COUT_G; co++)
                    acc[co] = fmaf(v, s_w[co * KS * KS + ky * KS + kx], acc[co]);
            }
        }
        __syncthreads();
    }
    #pragma unroll
    for (int co = 0; co < COUT_G; co++) {
        float v = DO_GELU ? gelu_exact(acc[co]) : acc[co];
        OUT[(((long)b * COUT_TOTAL + g * COUT_G + co) * 64 + ty0 + ty) * 64 + tx0 + tx] = v;
    }
}

// ---------------- 1x1 conv 48->3 ----------------
__global__ void conv1_kernel(const float* __restrict__ IN, const float* __restrict__ W,
                             const float* __restrict__ Bi, float* __restrict__ OUT) {
    int b = blockIdx.y;
    int pix = blockIdx.x * 256 + threadIdx.x;
    float a0 = Bi[0], a1 = Bi[1], a2 = Bi[2];
    #pragma unroll
    for (int c = 0; c < 48; c++) {
        float v = IN[((long)b * 48 + c) * NPIX + pix];
        a0 = fmaf(v, W[0 * 48 + c], a0);
        a1 = fmaf(v, W[1 * 48 + c], a1);
        a2 = fmaf(v, W[2 * 48 + c], a2);
    }
    long base = ((long)b * NPIX + pix) * 3;
    OUT[base + 0] = a0; OUT[base + 1] = a1; OUT[base + 2] = a2;
}

// ---------------- host ----------------
extern "C" void kernel_launch(void* const* d_in, const int* in_sizes, int n_in,
                              void* d_out, int out_size) {
    const float* x        = (const float*)d_in[0];
    const float* to_in_w  = (const float*)d_in[1];
    const float* to_in_b  = (const float*)d_in[2];
    const float* pos_emb  = (const float*)d_in[3];
    const float* proj     = (const float*)d_in[4];
    const float* sn_attn_g= (const float*)d_in[5];
    const float* wq       = (const float*)d_in[6];
    const float* wk       = (const float*)d_in[7];
    const float* wv       = (const float*)d_in[8];
    const float* wo       = (const float*)d_in[9];
    const float* bo       = (const float*)d_in[10];
    const float* sn_ff_g  = (const float*)d_in[11];
    const float* w1       = (const float*)d_in[12];
    const float* b1       = (const float*)d_in[13];
    const float* w2       = (const float*)d_in[14];
    const float* b2       = (const float*)d_in[15];
    const float* expand_w = (const float*)d_in[16];
    const float* fwd_w    = (const float*)d_in[17];
    const float* dec_lin_w= (const float*)d_in[18];
    const float* dec_lin_b= (const float*)d_in[19];
    const float* gn_g     = (const float*)d_in[20];
    const float* gn_b     = (const float*)d_in[21];
    const float* c9_w     = (const float*)d_in[22];
    const float* c9_b     = (const float*)d_in[23];
    const float* c7_w     = (const float*)d_in[24];
    const float* c7_b     = (const float*)d_in[25];
    const float* c5_w     = (const float*)d_in[26];
    const float* c5_b     = (const float*)d_in[27];
    const float* c1_w     = (const float*)d_in[28];
    const float* c1_b     = (const float*)d_in[29];
    float* out = (float*)d_out;

    float *ph, *phn, *pq, *pk, *pv, *pqp, *pkp, *pctx, *pctxp, *pksum, *pkmax, *pkmp,
          *pksp, *pden, *pattn, *pff, *pt1, *pt2, *py, *pnchw, *pc9, *pc7, *pc5;
    cudaGetSymbolAddress((void**)&ph, g_h);
    cudaGetSymbolAddress((void**)&phn, g_hn);
    cudaGetSymbolAddress((void**)&pq, g_q);
    cudaGetSymbolAddress((void**)&pk, g_k);
    cudaGetSymbolAddress((void**)&pv, g_v);
    cudaGetSymbolAddress((void**)&pqp, g_qp);
    cudaGetSymbolAddress((void**)&pkp, g_kp);
    cudaGetSymbolAddress((void**)&pctx, g_ctx);
    cudaGetSymbolAddress((void**)&pctxp, g_ctxp);
    cudaGetSymbolAddress((void**)&pksum, g_ksum);
    cudaGetSymbolAddress((void**)&pkmax, g_kmax);
    cudaGetSymbolAddress((void**)&pkmp, g_kmpart);
    cudaGetSymbolAddress((void**)&pksp, g_kspart);
    cudaGetSymbolAddress((void**)&pden, g_denom);
    cudaGetSymbolAddress((void**)&pattn, g_attn);
    cudaGetSymbolAddress((void**)&pff, g_ff);
    cudaGetSymbolAddress((void**)&pt1, g_t1);
    cudaGetSymbolAddress((void**)&pt2, g_t2);
    cudaGetSymbolAddress((void**)&py, g_y);
    cudaGetSymbolAddress((void**)&pnchw, g_nchw);
    cudaGetSymbolAddress((void**)&pc9, g_c9o);
    cudaGetSymbolAddress((void**)&pc7, g_c7o);
    cudaGetSymbolAddress((void**)&pc5, g_c5o);

    embed_kernel<<<ROWS, DIM>>>(x, to_in_w, to_in_b, pos_emb, ph);

    const long CTOT = (long)BHN * MP * DH;
    for (int i = 0; i < DEPTH; i++) {
        const float* proj_i = proj + (long)i * MFEAT * DH;
        scalenorm_kernel<<<2048, 256>>>(ph, phn, sn_attn_g, i);
        gemm_qkv_f2<<<dim3(128, 4, 3), 256>>>(phn,
            wq + (long)i * INNER * DIM, wk + (long)i * INNER * DIM, wv + (long)i * INNER * DIM,
            pq, pk, pv);
        gemm_dd2<false><<<dim3(32, 5, BHN), 256>>>(pq, proj_i, pqp, nullptr);
        gemm_dd2<true ><<<dim3(32, 5, BHN), 256>>>(pk, proj_i, pkp, pkmp);
        kmax_fin2<<<BHN, 32>>>(pkmp, pkmax);
        finalize_kernel<true ><<<16384, 256>>>(pq, pqp, nullptr);
        finalize_kernel<false><<<16384, 256>>>(pk, pkp, pkmax);
        gemm_ctx2<<<dim3(5, CTX_SPLIT, BHN), 128>>>(pkp, pv, pctxp);
        ctx_reduce_kernel<<<(int)((CTOT + 255) / 256), 256>>>(pctxp, pctx);
        ksum_part_kernel<<<dim3(8, BHN), MP>>>(pkp, pksp);
        ksum_fin_kernel<<<BHN, MP>>>(pksp, pksum);
        denom_kernel<<<16384, 256>>>(pqp, pksum, pden);
        gemm_out2<<<dim3(32, 1, BHN), 256>>>(pqp, pctx, pden, pattn);
        gemm_f2n64k<3><<<dim3(128, 3), 256>>>(pattn, wo + (long)i * DIM * INNER, bo + (long)i * DIM, ph, ph, DIM, INNER);
        scalenorm_kernel<<<2048, 256>>>(ph, phn, sn_ff_g, i);
        gemm_f2n128k<2><<<dim3(128, 6), 256>>>(phn, w1 + (long)i * FF * DIM, b1 + (long)i * FF, nullptr, pff, FF, DIM);
        gemm_f2n64k<3><<<dim3(128, 3), 256>>>(pff, w2 + (long)i * DIM * FF, b2 + (long)i * DIM, ph, ph, DIM, FF);
    }

    gemm_f2n64k<0><<<dim3(128, 3), 256>>>(ph, expand_w, nullptr, nullptr, pt1, DIM, DIM);
    gemm_f2n64k<0><<<dim3(128, 3), 256>>>(pt1, fwd_w, nullptr, nullptr, pt2, DIM, DIM);
    gemm_f2n64k<1><<<dim3(128, 3), 256>>>(pt2, dec_lin_w, dec_lin_b, nullptr, py, DIM, DIM);

    groupnorm_kernel<<<32, 256>>>(py, gn_g, gn_b, pnchw);
    conv_circ<24, 24, 9, 192, 192, true><<<dim3(16, 8, 4), 256>>>(pnchw, c9_w, c9_b, pc9);
    conv_circ<24, 12, 7, 192,  96, true><<<dim3(16, 8, 4), 256>>>(pc9, c7_w, c7_b, pc7);
    conv_circ<12,  6, 5,  96,  48, true><<<dim3(16, 8, 4), 256>>>(pc7, c5_w, c5_b, pc5);
    conv1_kernel<<<dim3(16, 4), 256>>>(pc5, c1_w, c1_b, out);
}

// round 8
// speedup vs baseline: 2.8146x; 1.0916x over previous
#include <cuda_runtime.h>
#include <cuda_bf16.h>
#include <math.h>

// ---------------- constants ----------------
#define BATCH 4
#define NPIX  4096          // 64*64
#define ROWS  16384         // BATCH*NPIX
#define DIM   192
#define DEPTH 6
#define HEADS 8
#define DH    64
#define INNER 512
#define FF    768
#define MFEAT 266
#define MP    272           // padded feature dim (mult of 16)
#define BHN   32            // BATCH*HEADS
#define CTX_SPLIT 8         // split-K slices for context GEMM

typedef unsigned long long u64t;

__device__ __forceinline__ float gelu_exact(float x) {
    return 0.5f * x * (1.0f + erff(x * 0.70710678118654752f));
}
__device__ __forceinline__ float warpSum(float v) {
    #pragma unroll
    for (int o = 16; o; o >>= 1) v += __shfl_xor_sync(0xffffffffu, v, o);
    return v;
}
__device__ __forceinline__ float warpMax(float v) {
    #pragma unroll
    for (int o = 16; o; o >>= 1) v = fmaxf(v, __shfl_xor_sync(0xffffffffu, v, o));
    return v;
}
// packed fp32x2 helpers (Blackwell FFMA2 — bitwise identical to 2x scalar fmaf)
__device__ __forceinline__ void fma2(u64t& d, u64t a, u64t b) {
    asm("fma.rn.f32x2 %0, %1, %2, %3;" : "=l"(d) : "l"(a), "l"(b), "l"(d));
}
__device__ __forceinline__ u64t dup2(float v) {
    u64t r; asm("mov.b64 %0, {%1, %1};" : "=l"(r) : "f"(v)); return r;
}
__device__ __forceinline__ u64t pack2(float lo, float hi) {
    u64t r; asm("mov.b64 %0, {%1, %2};" : "=l"(r) : "f"(lo), "f"(hi)); return r;
}
__device__ __forceinline__ float2 unp2(u64t v) {
    float2 r; asm("mov.b64 {%0, %1}, %2;" : "=f"(r.x), "=f"(r.y) : "l"(v)); return r;
}

// ---------------- scratch (device globals; no allocs allowed) ----------------
__device__ float g_h   [ROWS * DIM];
__device__ float g_hn  [ROWS * DIM];
__device__ float g_q   [ROWS * INNER];     // head-major [bh][n][64]
__device__ float g_k   [ROWS * INNER];     // head-major
__device__ float g_v   [ROWS * INNER];     // head-major
__device__ float g_qp  [(long)BHN * NPIX * MP];
__device__ float g_kp  [(long)BHN * NPIX * MP];
__device__ float g_ctx [BHN * MP * DH];
__device__ float g_ctxp[(long)CTX_SPLIT * BHN * MP * DH];
__device__ float g_ksum[BHN * MP];
__device__ float g_kmax[BHN];
__device__ float g_kmpart[BHN * 160];
__device__ float g_kspart[(long)CTX_SPLIT * BHN * MP];
__device__ float g_attn[ROWS * INNER];     // n-major [b][n][512]
__device__ float g_ff  [ROWS * FF];
__device__ float g_t1  [ROWS * DIM];
__device__ float g_t2  [ROWS * DIM];
__device__ float g_y   [ROWS * DIM];
__device__ float g_nchw[BATCH * 192 * 64 * 64];
__device__ float g_c9o [BATCH * 192 * 64 * 64];
__device__ float g_c7o [BATCH * 96 * 64 * 64];
__device__ float g_c5o [BATCH * 48 * 64 * 64];

// ---------------- embed ----------------
__global__ void embed_kernel(const float* __restrict__ x, const float* __restrict__ W,
                             const float* __restrict__ bias, const float* __restrict__ pos,
                             float* __restrict__ H) {
    int row = blockIdx.x;
    int c = threadIdx.x;
    int n = row & (NPIX - 1);
    const float* xr = x + (long)row * 3;
    float v = bias[c] + xr[0] * W[c * 3 + 0] + xr[1] * W[c * 3 + 1] + xr[2] * W[c * 3 + 2]
            + pos[(long)n * DIM + c];
    H[(long)row * DIM + c] = v;
}

// ---------------- scalenorm ----------------
__global__ void scalenorm_kernel(const float* __restrict__ in, float* __restrict__ out,
                                 const float* __restrict__ gArr, int gIdx) {
    int w = (blockIdx.x * blockDim.x + threadIdx.x) >> 5;
    int lane = threadIdx.x & 31;
    if (w >= ROWS) return;
    const float* r = in + (long)w * DIM;
    float ss = 0.f;
    #pragma unroll
    for (int c = lane; c < DIM; c += 32) { float v = r[c]; ss += v * v; }
    ss = warpSum(ss);
    float nrm = sqrtf(ss) * 0.07216878364870323f;
    float s = gArr[gIdx] / fmaxf(nrm, 1e-5f);
    #pragma unroll
    for (int c = lane; c < DIM; c += 32) out[(long)w * DIM + c] = r[c] * s;
}

// =============================================================================
// Double-buffered FFMA2 GEMM body, BN=128: C[M,N]=A[M,K]@B[N,K]^T.
// 256 threads, BM=128 BN=128 BK=16.
// EPI: 0 none, 1 +bias, 2 gelu(+bias), 3 +bias+resid
// HM:  1 -> head-major output C[bh][n][64] (for Q/K/V)
// =============================================================================
template<int EPI, int HM>
__device__ __forceinline__ void gemm_n128_body(
    const float* __restrict__ A, const float* __restrict__ B,
    const float* __restrict__ bias, const float* __restrict__ resid,
    float* __restrict__ C, int N, int K) {
    __shared__ float As[2][16][128];
    __shared__ float Bs[2][16][128];
    const int tid = threadIdx.x;
    const int bm = blockIdx.x * 128, bn = blockIdx.y * 128;
    const int tx = tid & 15, ty = tid >> 4;
    u64t acc[4][8];
    #pragma unroll
    for (int i = 0; i < 4; i++)
        #pragma unroll
        for (int j = 0; j < 8; j++) acc[i][j] = 0ull;

    const int lr = tid >> 1, lk = (tid & 1) * 8;
    const float* Arow = A + (long)(bm + lr) * K + lk;
    const float* Brow = B + (long)(bn + lr) * K + lk;

    {
        float4 a0 = *(const float4*)(Arow),     a1 = *(const float4*)(Arow + 4);
        float4 b0 = *(const float4*)(Brow),     b1 = *(const float4*)(Brow + 4);
        As[0][lk+0][lr]=a0.x; As[0][lk+1][lr]=a0.y; As[0][lk+2][lr]=a0.z; As[0][lk+3][lr]=a0.w;
        As[0][lk+4][lr]=a1.x; As[0][lk+5][lr]=a1.y; As[0][lk+6][lr]=a1.z; As[0][lk+7][lr]=a1.w;
        Bs[0][lk+0][lr]=b0.x; Bs[0][lk+1][lr]=b0.y; Bs[0][lk+2][lr]=b0.z; Bs[0][lk+3][lr]=b0.w;
        Bs[0][lk+4][lr]=b1.x; Bs[0][lk+5][lr]=b1.y; Bs[0][lk+6][lr]=b1.z; Bs[0][lk+7][lr]=b1.w;
    }
    __syncthreads();
    int buf = 0;
    for (int k0 = 16; k0 <= K; k0 += 16) {
        const bool more = (k0 < K);
        float4 a0, a1, b0, b1;
        if (more) {
            a0 = *(const float4*)(Arow + k0); a1 = *(const float4*)(Arow + k0 + 4);
            b0 = *(const float4*)(Brow + k0); b1 = *(const float4*)(Brow + k0 + 4);
        }
        const float (*Ac)[128] = As[buf];
        const float (*Bc)[128] = Bs[buf];
        #pragma unroll
        for (int kk = 0; kk < 16; kk++) {
            const u64t* ap = (const u64t*)&Ac[kk][ty * 8];
            u64t av0 = ap[0], av1 = ap[1], av2 = ap[2], av3 = ap[3];
            float4 p0 = *(const float4*)&Bc[kk][tx * 4];
            float4 p1 = *(const float4*)&Bc[kk][64 + tx * 4];
            u64t bv[8];
            bv[0]=dup2(p0.x); bv[1]=dup2(p0.y); bv[2]=dup2(p0.z); bv[3]=dup2(p0.w);
            bv[4]=dup2(p1.x); bv[5]=dup2(p1.y); bv[6]=dup2(p1.z); bv[7]=dup2(p1.w);
            #pragma unroll
            for (int j = 0; j < 8; j++) {
                fma2(acc[0][j], av0, bv[j]);
                fma2(acc[1][j], av1, bv[j]);
                fma2(acc[2][j], av2, bv[j]);
                fma2(acc[3][j], av3, bv[j]);
            }
        }
        if (more) {
            float (*An)[128] = As[buf ^ 1];
            float (*Bn)[128] = Bs[buf ^ 1];
            An[lk+0][lr]=a0.x; An[lk+1][lr]=a0.y; An[lk+2][lr]=a0.z; An[lk+3][lr]=a0.w;
            An[lk+4][lr]=a1.x; An[lk+5][lr]=a1.y; An[lk+6][lr]=a1.z; An[lk+7][lr]=a1.w;
            Bn[lk+0][lr]=b0.x; Bn[lk+1][lr]=b0.y; Bn[lk+2][lr]=b0.z; Bn[lk+3][lr]=b0.w;
            Bn[lk+4][lr]=b1.x; Bn[lk+5][lr]=b1.y; Bn[lk+6][lr]=b1.z; Bn[lk+7][lr]=b1.w;
        }
        __syncthreads();
        buf ^= 1;
    }
    const int col0 = bn + tx * 4, col1 = bn + 64 + tx * 4;
    float bcol[8];
    if (EPI >= 1) {
        #pragma unroll
        for (int j = 0; j < 4; j++) { bcol[j] = bias[col0 + j]; bcol[4 + j] = bias[col1 + j]; }
    }
    #pragma unroll
    for (int i = 0; i < 4; i++) {
        int r0 = bm + ty * 8 + 2 * i;
        float o0[8], o1[8];
        #pragma unroll
        for (int j = 0; j < 8; j++) { float2 p = unp2(acc[i][j]); o0[j] = p.x; o1[j] = p.y; }
        if (EPI >= 1) {
            #pragma unroll
            for (int j = 0; j < 8; j++) { o0[j] += bcol[j]; o1[j] += bcol[j]; }
        }
        if (EPI == 2) {
            #pragma unroll
            for (int j = 0; j < 8; j++) { o0[j] = gelu_exact(o0[j]); o1[j] = gelu_exact(o1[j]); }
        }
        if (EPI == 3) {
            const float* rr0 = resid + (long)r0 * N;
            const float* rr1 = rr0 + N;
            #pragma unroll
            for (int j = 0; j < 4; j++) {
                o0[j] += rr0[col0 + j]; o0[4+j] += rr0[col1 + j];
                o1[j] += rr1[col0 + j]; o1[4+j] += rr1[col1 + j];
            }
        }
        if (HM) {
            // head-major write: row -> (b, n); col -> (h, d)
            int bb = r0 >> 12, nn = r0 & (NPIX - 1);
            long base0 = ((long)(bb * HEADS + (col0 >> 6)) * NPIX + nn) * DH + (col0 & 63);
            long base1 = ((long)(bb * HEADS + (col1 >> 6)) * NPIX + nn) * DH + (col1 & 63);
            *(float4*)(C + base0)      = make_float4(o0[0], o0[1], o0[2], o0[3]);
            *(float4*)(C + base1)      = make_float4(o0[4], o0[5], o0[6], o0[7]);
            *(float4*)(C + base0 + DH) = make_float4(o1[0], o1[1], o1[2], o1[3]);
            *(float4*)(C + base1 + DH) = make_float4(o1[4], o1[5], o1[6], o1[7]);
        } else {
            float* c0 = C + (long)r0 * N;
            *(float4*)(c0 + col0) = make_float4(o0[0], o0[1], o0[2], o0[3]);
            *(float4*)(c0 + col1) = make_float4(o0[4], o0[5], o0[6], o0[7]);
            float* c1 = c0 + N;
            *(float4*)(c1 + col0) = make_float4(o1[0], o1[1], o1[2], o1[3]);
            *(float4*)(c1 + col1) = make_float4(o1[4], o1[5], o1[6], o1[7]);
        }
    }
}

// fused QKV (same A; B/C selected by blockIdx.z); head-major outputs
__global__ void __launch_bounds__(256, 2) gemm_qkv_f2(
    const float* __restrict__ A, const float* __restrict__ Bq,
    const float* __restrict__ Bk, const float* __restrict__ Bv,
    float* __restrict__ Cq, float* __restrict__ Ck, float* __restrict__ Cv) {
    const float* B = (blockIdx.z == 0) ? Bq : (blockIdx.z == 1) ? Bk : Bv;
    float* C = (blockIdx.z == 0) ? Cq : (blockIdx.z == 1) ? Ck : Cv;
    gemm_n128_body<0, 1>(A, B, nullptr, nullptr, C, INNER, DIM);
}

template<int EPI>
__global__ void __launch_bounds__(256, 2) gemm_f2n128k(
    const float* __restrict__ A, const float* __restrict__ B,
    const float* __restrict__ bias, const float* __restrict__ resid,
    float* __restrict__ C, int N, int K) {
    gemm_n128_body<EPI, 0>(A, B, bias, resid, C, N, K);
}

// =============================================================================
// Double-buffered FFMA2 GEMM body, BN=64: BM=128, 256 threads.
// =============================================================================
template<int EPI>
__device__ __forceinline__ void gemm_n64_body(
    const float* __restrict__ A, const float* __restrict__ B,
    const float* __restrict__ bias, const float* __restrict__ resid,
    float* __restrict__ C, int N, int K) {
    __shared__ float As[2][16][128];
    __shared__ float Bs[2][16][64];
    const int tid = threadIdx.x;
    const int bm = blockIdx.x * 128, bn = blockIdx.y * 64;
    const int tx = tid & 7, ty = tid >> 3;
    u64t acc[2][8];
    #pragma unroll
    for (int i = 0; i < 2; i++)
        #pragma unroll
        for (int j = 0; j < 8; j++) acc[i][j] = 0ull;

    const int lr = tid >> 1, lk = (tid & 1) * 8;
    const float* Arow = A + (long)(bm + lr) * K + lk;
    const int br = tid >> 2, bk = (tid & 3) * 4;
    const float* Brow = B + (long)(bn + br) * K + bk;

    {
        float4 a0 = *(const float4*)(Arow), a1 = *(const float4*)(Arow + 4);
        float4 bb = *(const float4*)(Brow);
        As[0][lk+0][lr]=a0.x; As[0][lk+1][lr]=a0.y; As[0][lk+2][lr]=a0.z; As[0][lk+3][lr]=a0.w;
        As[0][lk+4][lr]=a1.x; As[0][lk+5][lr]=a1.y; As[0][lk+6][lr]=a1.z; As[0][lk+7][lr]=a1.w;
        Bs[0][bk+0][br]=bb.x; Bs[0][bk+1][br]=bb.y; Bs[0][bk+2][br]=bb.z; Bs[0][bk+3][br]=bb.w;
    }
    __syncthreads();
    int buf = 0;
    for (int k0 = 16; k0 <= K; k0 += 16) {
        const bool more = (k0 < K);
        float4 a0, a1, bb;
        if (more) {
            a0 = *(const float4*)(Arow + k0); a1 = *(const float4*)(Arow + k0 + 4);
            bb = *(const float4*)(Brow + k0);
        }
        const float (*Ac)[128] = As[buf];
        const float (*Bc)[64] = Bs[buf];
        #pragma unroll
        for (int kk = 0; kk < 16; kk++) {
            const u64t* ap = (const u64t*)&Ac[kk][ty * 4];
            u64t av0 = ap[0], av1 = ap[1];
            float4 p0 = *(const float4*)&Bc[kk][tx * 4];
            float4 p1 = *(const float4*)&Bc[kk][32 + tx * 4];
            u64t bv[8];
            bv[0]=dup2(p0.x); bv[1]=dup2(p0.y); bv[2]=dup2(p0.z); bv[3]=dup2(p0.w);
            bv[4]=dup2(p1.x); bv[5]=dup2(p1.y); bv[6]=dup2(p1.z); bv[7]=dup2(p1.w);
            #pragma unroll
            for (int j = 0; j < 8; j++) {
                fma2(acc[0][j], av0, bv[j]);
                fma2(acc[1][j], av1, bv[j]);
            }
        }
        if (more) {
            float (*An)[128] = As[buf ^ 1];
            float (*Bn)[64] = Bs[buf ^ 1];
            An[lk+0][lr]=a0.x; An[lk+1][lr]=a0.y; An[lk+2][lr]=a0.z; An[lk+3][lr]=a0.w;
            An[lk+4][lr]=a1.x; An[lk+5][lr]=a1.y; An[lk+6][lr]=a1.z; An[lk+7][lr]=a1.w;
            Bn[bk+0][br]=bb.x; Bn[bk+1][br]=bb.y; Bn[bk+2][br]=bb.z; Bn[bk+3][br]=bb.w;
        }
        __syncthreads();
        buf ^= 1;
    }
    const int col0 = bn + tx * 4, col1 = bn + 32 + tx * 4;
    float bcol[8];
    if (EPI >= 1) {
        #pragma unroll
        for (int j = 0; j < 4; j++) { bcol[j] = bias[col0 + j]; bcol[4 + j] = bias[col1 + j]; }
    }
    #pragma unroll
    for (int i = 0; i < 2; i++) {
        int r0 = bm + ty * 4 + 2 * i;
        float o0[8], o1[8];
        #pragma unroll
        for (int j = 0; j < 8; j++) { float2 p = unp2(acc[i][j]); o0[j] = p.x; o1[j] = p.y; }
        if (EPI >= 1) {
            #pragma unroll
            for (int j = 0; j < 8; j++) { o0[j] += bcol[j]; o1[j] += bcol[j]; }
        }
        if (EPI == 2) {
            #pragma unroll
            for (int j = 0; j < 8; j++) { o0[j] = gelu_exact(o0[j]); o1[j] = gelu_exact(o1[j]); }
        }
        if (EPI == 3) {
            const float* rr0 = resid + (long)r0 * N;
            const float* rr1 = rr0 + N;
            #pragma unroll
            for (int j = 0; j < 4; j++) {
                o0[j] += rr0[col0 + j]; o0[4+j] += rr0[col1 + j];
                o1[j] += rr1[col0 + j]; o1[4+j] += rr1[col1 + j];
            }
        }
        float* c0 = C + (long)r0 * N;
        *(float4*)(c0 + col0) = make_float4(o0[0], o0[1], o0[2], o0[3]);
        *(float4*)(c0 + col1) = make_float4(o0[4], o0[5], o0[6], o0[7]);
        float* c1 = c0 + N;
        *(float4*)(c1 + col0) = make_float4(o1[0], o1[1], o1[2], o1[3]);
        *(float4*)(c1 + col1) = make_float4(o1[4], o1[5], o1[6], o1[7]);
    }
}

template<int EPI>
__global__ void __launch_bounds__(256, 2) gemm_f2n64k(
    const float* __restrict__ A, const float* __restrict__ B,
    const float* __restrict__ bias, const float* __restrict__ resid,
    float* __restrict__ C, int N, int K) {
    gemm_n64_body<EPI>(A, B, bias, resid, C, N, K);
}

// =============================================================================
// dd GEMM merged q+k (head-major A): z in [0,64): z<32 -> q (no max), else k.
// BM=128 BN=64, K=64, double-buffered. grid (32, 5, 64)
// =============================================================================
__global__ void __launch_bounds__(256, 2) gemm_dd2(
    const float* __restrict__ Q, const float* __restrict__ Kh,
    const float* __restrict__ P,
    float* __restrict__ QP, float* __restrict__ KP, float* __restrict__ maxpart) {
    __shared__ float As[2][16][128];
    __shared__ float Bs[2][16][64];
    const int tid = threadIdx.x;
    const bool isK = (blockIdx.z >= 32);
    const int bh = blockIdx.z & 31;
    const float* Ain = isK ? Kh : Q;
    float* DD = isK ? KP : QP;
    const int bm = blockIdx.x * 128, bn = blockIdx.y * 64;
    const int tx = tid & 7, ty = tid >> 3;
    u64t acc[2][8];
    #pragma unroll
    for (int i = 0; i < 2; i++)
        #pragma unroll
        for (int j = 0; j < 8; j++) acc[i][j] = 0ull;

    const int lr = tid >> 1, lk = (tid & 1) * 8;
    const float* Arow = Ain + ((long)bh * NPIX + bm + lr) * DH + lk;
    const int br = tid >> 2, bk = (tid & 3) * 4;
    const int mB = bn + br;
    const float* Brow = P + (long)mB * DH + bk;
    const bool bval = (mB < MFEAT);

    {
        float4 a0 = *(const float4*)(Arow), a1 = *(const float4*)(Arow + 4);
        float4 bb = make_float4(0.f, 0.f, 0.f, 0.f);
        if (bval) bb = *(const float4*)(Brow);
        As[0][lk+0][lr]=a0.x; As[0][lk+1][lr]=a0.y; As[0][lk+2][lr]=a0.z; As[0][lk+3][lr]=a0.w;
        As[0][lk+4][lr]=a1.x; As[0][lk+5][lr]=a1.y; As[0][lk+6][lr]=a1.z; As[0][lk+7][lr]=a1.w;
        Bs[0][bk+0][br]=bb.x; Bs[0][bk+1][br]=bb.y; Bs[0][bk+2][br]=bb.z; Bs[0][bk+3][br]=bb.w;
    }
    __syncthreads();
    int buf = 0;
    for (int k0 = 16; k0 <= DH; k0 += 16) {
        const bool more = (k0 < DH);
        float4 a0, a1, bb;
        if (more) {
            a0 = *(const float4*)(Arow + k0); a1 = *(const float4*)(Arow + k0 + 4);
            bb = make_float4(0.f, 0.f, 0.f, 0.f);
            if (bval) bb = *(const float4*)(Brow + k0);
        }
        const float (*Ac)[128] = As[buf];
        const float (*Bc)[64] = Bs[buf];
        #pragma unroll
        for (int kk = 0; kk < 16; kk++) {
            const u64t* ap = (const u64t*)&Ac[kk][ty * 4];
            u64t av0 = ap[0], av1 = ap[1];
            float4 p0 = *(const float4*)&Bc[kk][tx * 4];
            float4 p1 = *(const float4*)&Bc[kk][32 + tx * 4];
            u64t bv[8];
            bv[0]=dup2(p0.x); bv[1]=dup2(p0.y); bv[2]=dup2(p0.z); bv[3]=dup2(p0.w);
            bv[4]=dup2(p1.x); bv[5]=dup2(p1.y); bv[6]=dup2(p1.z); bv[7]=dup2(p1.w);
            #pragma unroll
            for (int j = 0; j < 8; j++) {
                fma2(acc[0][j], av0, bv[j]);
                fma2(acc[1][j], av1, bv[j]);
            }
        }
        if (more) {
            float (*An)[128] = As[buf ^ 1];
            float (*Bn)[64] = Bs[buf ^ 1];
            An[lk+0][lr]=a0.x; An[lk+1][lr]=a0.y; An[lk+2][lr]=a0.z; An[lk+3][lr]=a0.w;
            An[lk+4][lr]=a1.x; An[lk+5][lr]=a1.y; An[lk+6][lr]=a1.z; An[lk+7][lr]=a1.w;
            Bn[bk+0][br]=bb.x; Bn[bk+1][br]=bb.y; Bn[bk+2][br]=bb.z; Bn[bk+3][br]=bb.w;
        }
        __syncthreads();
        buf ^= 1;
    }
    const float dn = 0.35355339059327373f;  // 64^-0.25
    float* Cb = DD + (long)bh * NPIX * MP;
    const int col0 = bn + tx * 4, col1 = bn + 32 + tx * 4;
    float mx = -1e30f;
    const bool fullblk = (bn + 64 <= MFEAT);
    #pragma unroll
    for (int i = 0; i < 2; i++) {
        int r0 = bm + ty * 4 + 2 * i;
        float o0[8], o1[8];
        #pragma unroll
        for (int j = 0; j < 8; j++) {
            float2 p = unp2(acc[i][j]);
            o0[j] = dn * p.x; o1[j] = dn * p.y;
        }
        float* c0 = Cb + (long)r0 * MP;
        float* c1 = c0 + MP;
        if (fullblk) {
            *(float4*)(c0 + col0) = make_float4(o0[0], o0[1], o0[2], o0[3]);
            *(float4*)(c0 + col1) = make_float4(o0[4], o0[5], o0[6], o0[7]);
            *(float4*)(c1 + col0) = make_float4(o1[0], o1[1], o1[2], o1[3]);
            *(float4*)(c1 + col1) = make_float4(o1[4], o1[5], o1[6], o1[7]);
            if (isK) {
                #pragma unroll
                for (int j = 0; j < 8; j++) mx = fmaxf(mx, fmaxf(o0[j], o1[j]));
            }
        } else {
            #pragma unroll
            for (int j = 0; j < 4; j++) {
                int ca = col0 + j, cb2 = col1 + j;
                if (ca < MP) { c0[ca] = o0[j]; c1[ca] = o1[j]; }
                if (cb2 < MP) { c0[cb2] = o0[4+j]; c1[cb2] = o1[4+j]; }
                if (isK) {
                    if (ca < MFEAT) mx = fmaxf(mx, fmaxf(o0[j], o1[j]));
                    if (cb2 < MFEAT) mx = fmaxf(mx, fmaxf(o0[4+j], o1[4+j]));
                }
            }
        }
    }
    if (isK) {
        __shared__ float sm[8];
        mx = warpMax(mx);
        int lane = tid & 31, wid = tid >> 5;
        if (lane == 0) sm[wid] = mx;
        __syncthreads();
        if (tid == 0) {
            float m = sm[0];
            #pragma unroll
            for (int w = 1; w < 8; w++) m = fmaxf(m, sm[w]);
            maxpart[bh * 160 + blockIdx.x * 5 + blockIdx.y] = m;
        }
    }
}

__global__ void kmax_fin2(const float* __restrict__ part, float* __restrict__ kmax) {
    int bh = blockIdx.x;
    float v = -1e30f;
    for (int i = threadIdx.x; i < 160; i += 32) v = fmaxf(v, part[bh * 160 + i]);
    v = warpMax(v);
    if (threadIdx.x == 0) kmax[bh] = v;
}

// ---------------- finalize features (head-major q/k read) ----------------
template<bool IS_QUERY>
__global__ void finalize_kernel(const float* __restrict__ QKV, float* __restrict__ DD,
                                const float* __restrict__ KM) {
    int w = (blockIdx.x * blockDim.x + threadIdx.x) >> 5;
    int lane = threadIdx.x & 31;
    int bh = w >> 12, n = w & (NPIX - 1);
    const float* q = QKV + ((long)bh * NPIX + n) * DH;
    float ss = 0.f;
    #pragma unroll
    for (int d = lane; d < DH; d += 32) { float v = q[d]; ss += v * v; }
    ss = warpSum(ss);
    float diag = 0.0625f * ss;
    float* row = DD + (long)bh * NPIX * MP + (long)n * MP;
    float vals[9];
    float mx = -1e30f;
    #pragma unroll
    for (int i = 0; i < 9; i++) {
        int m = lane + i * 32;
        if (m < MFEAT) { vals[i] = row[m]; mx = fmaxf(mx, vals[i]); }
    }
    if (IS_QUERY) mx = warpMax(mx);
    else          mx = KM[bh];
    const float ratio = 0.06131393394849658f;
    #pragma unroll
    for (int i = 0; i < 9; i++) {
        int m = lane + i * 32;
        if (m < MP)
            row[m] = (m < MFEAT) ? ratio * (expf(vals[i] - diag - mx) + 1e-4f) : 0.f;
    }
}

// =============================================================================
// context split-K + fused ksum partials (double-buffered).
// CTP[sl][bh][m][d] = sum_{n in slice} kp[n,m] v[n,d]; KSP[sl][bh][m] = sum kp.
// tile m=64 x d=64, 128 threads. grid (5, CTX_SPLIT, 32). V head-major.
// =============================================================================
__global__ void __launch_bounds__(128, 4) gemm_ctx2(
    const float* __restrict__ KP, const float* __restrict__ V,
    float* __restrict__ CTP, float* __restrict__ KSP) {
    __shared__ float As[2][16][64];   // [n][m]
    __shared__ float Bs[2][16][64];   // [n][d]
    const int tid = threadIdx.x;
    const int bh = blockIdx.z;
    const int m0 = blockIdx.x * 64;
    const int sl = blockIdx.y;
    const int n0base = sl * (NPIX / CTX_SPLIT);
    const int nend = n0base + NPIX / CTX_SPLIT;
    const int tx = tid & 7, ty = tid >> 3;
    u64t acc[2][8];
    u64t ksacc[2];
    ksacc[0] = 0ull; ksacc[1] = 0ull;
    #pragma unroll
    for (int i = 0; i < 2; i++)
        #pragma unroll
        for (int j = 0; j < 8; j++) acc[i][j] = 0ull;
    const u64t ONE2 = dup2(1.0f);

    const int lr = tid >> 3;          // n-row (0..15)
    const int lq = (tid & 7) * 8;     // col offset
    const float* kpB = KP + (long)bh * NPIX * MP;
    const float* vB = V + (long)bh * NPIX * DH;
    const bool mvalid = (m0 + lq) < MP;

    {
        float4 a0 = make_float4(0.f,0.f,0.f,0.f), a1 = a0;
        if (mvalid) {
            const float* ar = kpB + (long)(n0base + lr) * MP + m0 + lq;
            a0 = *(const float4*)(ar); a1 = *(const float4*)(ar + 4);
        }
        const float* brp = vB + (long)(n0base + lr) * DH + lq;
        float4 b0 = *(const float4*)(brp), b1 = *(const float4*)(brp + 4);
        *(float4*)&As[0][lr][lq] = a0; *(float4*)&As[0][lr][lq + 4] = a1;
        *(float4*)&Bs[0][lr][lq] = b0; *(float4*)&Bs[0][lr][lq + 4] = b1;
    }
    __syncthreads();
    int buf = 0;
    for (int n0 = n0base + 16; n0 <= nend; n0 += 16) {
        const bool more = (n0 < nend);
        float4 a0, a1, b0, b1;
        if (more) {
            a0 = make_float4(0.f,0.f,0.f,0.f); a1 = a0;
            if (mvalid) {
                const float* ar = kpB + (long)(n0 + lr) * MP + m0 + lq;
                a0 = *(const float4*)(ar); a1 = *(const float4*)(ar + 4);
            }
            const float* brp = vB + (long)(n0 + lr) * DH + lq;
            b0 = *(const float4*)(brp); b1 = *(const float4*)(brp + 4);
        }
        const float (*Ac)[64] = As[buf];
        const float (*Bc)[64] = Bs[buf];
        #pragma unroll
        for (int kk = 0; kk < 16; kk++) {
            const u64t* ap = (const u64t*)&Ac[kk][ty * 4];
            u64t av0 = ap[0], av1 = ap[1];
            float4 p0 = *(const float4*)&Bc[kk][tx * 4];
            float4 p1 = *(const float4*)&Bc[kk][32 + tx * 4];
            u64t bv[8];
            bv[0]=dup2(p0.x); bv[1]=dup2(p0.y); bv[2]=dup2(p0.z); bv[3]=dup2(p0.w);
            bv[4]=dup2(p1.x); bv[5]=dup2(p1.y); bv[6]=dup2(p1.z); bv[7]=dup2(p1.w);
            #pragma unroll
            for (int j = 0; j < 8; j++) {
                fma2(acc[0][j], av0, bv[j]);
                fma2(acc[1][j], av1, bv[j]);
            }
            fma2(ksacc[0], av0, ONE2);
            fma2(ksacc[1], av1, ONE2);
        }
        if (more) {
            *(float4*)&As[buf^1][lr][lq] = a0; *(float4*)&As[buf^1][lr][lq + 4] = a1;
            *(float4*)&Bs[buf^1][lr][lq] = b0; *(float4*)&Bs[buf^1][lr][lq + 4] = b1;
        }
        __syncthreads();
        buf ^= 1;
    }
    float* Cb = CTP + ((long)sl * BHN + bh) * MP * DH;
    const int col0 = tx * 4, col1 = 32 + tx * 4;
    #pragma unroll
    for (int i = 0; i < 2; i++) {
        int m = m0 + ty * 4 + 2 * i;
        if (m < MP) {
            float o0[8], o1[8];
            #pragma unroll
            for (int j = 0; j < 8; j++) { float2 p = unp2(acc[i][j]); o0[j]=p.x; o1[j]=p.y; }
            float* c0 = Cb + (long)m * DH;
            float* c1 = c0 + DH;
            *(float4*)(c0 + col0) = make_float4(o0[0],o0[1],o0[2],o0[3]);
            *(float4*)(c0 + col1) = make_float4(o0[4],o0[5],o0[6],o0[7]);
            *(float4*)(c1 + col0) = make_float4(o1[0],o1[1],o1[2],o1[3]);
            *(float4*)(c1 + col1) = make_float4(o1[4],o1[5],o1[6],o1[7]);
            if (tx == 0) {
                float2 ks = unp2(ksacc[i]);
                float* kp = KSP + ((long)sl * BHN + bh) * MP + m;
                kp[0] = ks.x; kp[1] = ks.y;
            }
        }
    }
}

__global__ void ctx_reduce_kernel(const float* __restrict__ P, float* __restrict__ C) {
    long i = (long)blockIdx.x * 256 + threadIdx.x;
    const long TOT = (long)BHN * MP * DH;
    if (i < TOT) {
        float s = 0.f;
        #pragma unroll
        for (int sl = 0; sl < CTX_SPLIT; sl++) s += P[(long)sl * TOT + i];
        C[i] = s;
    }
}

__global__ void ksum_fin_kernel(const float* __restrict__ part, float* __restrict__ ksum) {
    int bh = blockIdx.x, m = threadIdx.x;
    float s = 0.f;
    #pragma unroll
    for (int sl = 0; sl < CTX_SPLIT; sl++) s += part[((long)sl * BHN + bh) * MP + m];
    ksum[bh * MP + m] = s;
}

// =============================================================================
// out GEMM + fused denom: out[n,d] = (sum_m qp[n,m] ctx[m,d]) / (sum_m qp[n,m] ksum[m])
// BM=128, N=64, K=MP=272. grid (32, 1, 32), 256 threads.
// =============================================================================
__global__ void __launch_bounds__(256, 2) gemm_out2(
    const float* __restrict__ QP, const float* __restrict__ CT,
    const float* __restrict__ KSUM, float* __restrict__ AT) {
    __shared__ float As[2][16][128];
    __shared__ float Bs[2][16][64];   // [k][d] natural
    __shared__ float ks_s[MP];
    const int tid = threadIdx.x;
    const int bh = blockIdx.z;
    const int b = bh >> 3, hh = bh & 7;
    const int bm = blockIdx.x * 128;
    const int tx = tid & 7, ty = tid >> 3;
    u64t acc[2][8];
    u64t dacc[2];
    dacc[0] = 0ull; dacc[1] = 0ull;
    #pragma unroll
    for (int i = 0; i < 2; i++)
        #pragma unroll
        for (int j = 0; j < 8; j++) acc[i][j] = 0ull;

    const int lr = tid >> 1, lk = (tid & 1) * 8;
    const float* Arow = QP + (long)bh * NPIX * MP + (long)(bm + lr) * MP + lk;
    const float* Bb = CT + (long)bh * MP * DH;
    const int lr2 = tid >> 4, lq = (tid & 15) * 4;   // B loader: 16 k-rows x 64 d

    {
        float4 a0 = *(const float4*)(Arow), a1 = *(const float4*)(Arow + 4);
        float4 bb = *(const float4*)(Bb + (long)lr2 * DH + lq);
        As[0][lk+0][lr]=a0.x; As[0][lk+1][lr]=a0.y; As[0][lk+2][lr]=a0.z; As[0][lk+3][lr]=a0.w;
        As[0][lk+4][lr]=a1.x; As[0][lk+5][lr]=a1.y; As[0][lk+6][lr]=a1.z; As[0][lk+7][lr]=a1.w;
        *(float4*)&Bs[0][lr2][lq] = bb;
        for (int i = tid; i < MP; i += 256) ks_s[i] = KSUM[bh * MP + i];
    }
    __syncthreads();
    int buf = 0;
    for (int k0 = 16; k0 <= MP; k0 += 16) {
        const bool more = (k0 < MP);
        float4 a0, a1, bb;
        if (more) {
            a0 = *(const float4*)(Arow + k0); a1 = *(const float4*)(Arow + k0 + 4);
            bb = *(const float4*)(Bb + (long)(k0 + lr2) * DH + lq);
        }
        const float (*Ac)[128] = As[buf];
        const float (*Bc)[64] = Bs[buf];
        const int kbase = k0 - 16;
        #pragma unroll
        for (int kk = 0; kk < 16; kk++) {
            const u64t* ap = (const u64t*)&Ac[kk][ty * 4];
            u64t av0 = ap[0], av1 = ap[1];
            float4 p0 = *(const float4*)&Bc[kk][tx * 4];
            float4 p1 = *(const float4*)&Bc[kk][32 + tx * 4];
            u64t bv[8];
            bv[0]=dup2(p0.x); bv[1]=dup2(p0.y); bv[2]=dup2(p0.z); bv[3]=dup2(p0.w);
            bv[4]=dup2(p1.x); bv[5]=dup2(p1.y); bv[6]=dup2(p1.z); bv[7]=dup2(p1.w);
            #pragma unroll
            for (int j = 0; j < 8; j++) {
                fma2(acc[0][j], av0, bv[j]);
                fma2(acc[1][j], av1, bv[j]);
            }
            u64t kzd = dup2(ks_s[kbase + kk]);
            fma2(dacc[0], av0, kzd);
            fma2(dacc[1], av1, kzd);
        }
        if (more) {
            float (*An)[128] = As[buf ^ 1];
            An[lk+0][lr]=a0.x; An[lk+1][lr]=a0.y; An[lk+2][lr]=a0.z; An[lk+3][lr]=a0.w;
            An[lk+4][lr]=a1.x; An[lk+5][lr]=a1.y; An[lk+6][lr]=a1.z; An[lk+7][lr]=a1.w;
            *(float4*)&Bs[buf ^ 1][lr2][lq] = bb;
        }
        __syncthreads();
        buf ^= 1;
    }
    const int col0 = tx * 4, col1 = 32 + tx * 4;
    #pragma unroll
    for (int i = 0; i < 2; i++) {
        int n0 = bm + ty * 4 + 2 * i;
        float2 dp = unp2(dacc[i]);
        float rd0 = 1.0f / dp.x;
        float rd1 = 1.0f / dp.y;
        float o0[8], o1[8];
        #pragma unroll
        for (int j = 0; j < 8; j++) {
            float2 p = unp2(acc[i][j]);
            o0[j] = p.x * rd0; o1[j] = p.y * rd1;
        }
        float* c0 = AT + ((long)(b * NPIX + n0)) * INNER + hh * DH;
        float* c1 = c0 + INNER;
        *(float4*)(c0 + col0) = make_float4(o0[0],o0[1],o0[2],o0[3]);
        *(float4*)(c0 + col1) = make_float4(o0[4],o0[5],o0[6],o0[7]);
        *(float4*)(c1 + col0) = make_float4(o1[0],o1[1],o1[2],o1[3]);
        *(float4*)(c1 + col1) = make_float4(o1[4],o1[5],o1[6],o1[7]);
    }
}

// ---------------- group norm + NHWC -> NCHW ----------------
__global__ void groupnorm_kernel(const float* __restrict__ Y, const float* __restrict__ G,
                                 const float* __restrict__ Bt, float* __restrict__ Z) {
    int b = blockIdx.x >> 3, grp = blockIdx.x & 7;
    const int CPG = 24, NELEM = CPG * NPIX;
    float s = 0.f, s2 = 0.f;
    for (int t = threadIdx.x; t < NELEM; t += 256) {
        int c = grp * CPG + (t % CPG);
        int pix = t / CPG;
        float v = Y[((long)b * NPIX + pix) * DIM + c];
        s += v; s2 += v * v;
    }
    __shared__ float ssum[8], ssq[8];
    int lane = threadIdx.x & 31, wid = threadIdx.x >> 5;
    s = warpSum(s); s2 = warpSum(s2);
    if (lane == 0) { ssum[wid] = s; ssq[wid] = s2; }
    __syncthreads();
    if (wid == 0) {
        float a = (lane < 8) ? ssum[lane] : 0.f;
        float b2 = (lane < 8) ? ssq[lane] : 0.f;
        a = warpSum(a); b2 = warpSum(b2);
        if (lane == 0) { ssum[0] = a; ssq[0] = b2; }
    }
    __syncthreads();
    float mu = ssum[0] / NELEM;
    float var = ssq[0] / NELEM - mu * mu;
    float rstd = rsqrtf(var + 1e-5f);
    for (int t = threadIdx.x; t < NELEM; t += 256) {
        int c = grp * CPG + (t % CPG);
        int pix = t / CPG;
        float v = Y[((long)b * NPIX + pix) * DIM + c];
        Z[((long)(b * DIM + c)) * NPIX + pix] = (v - mu) * rstd * G[c] + Bt[c];
    }
}

// ---------------- circular grouped conv + gelu, FFMA2 channel pairs ----------------
template<int CIN_G, int COUT_G, int KS, int CIN_TOTAL, int COUT_TOTAL, bool DO_GELU>
__global__ void __launch_bounds__(256) conv_circ(
    const float* __restrict__ IN, const float* __restrict__ W,
    const float* __restrict__ Bi, float* __restrict__ OUT) {
    const int PAD = KS / 2;
    const int HALO = 16 + 2 * PAD;
    const int COP = COUT_G / 2;
    __shared__ float s_in[HALO * HALO];
    __shared__ __align__(8) float s_w[KS * KS * COUT_G];  // [tap][co], co contiguous
    int tile = blockIdx.x;
    int ty0 = (tile >> 2) * 16, tx0 = (tile & 3) * 16;
    int g = blockIdx.y, b = blockIdx.z;
    int tid = threadIdx.x;
    int tx = tid & 15, ty = tid >> 4;
    u64t acc2[COP];
    #pragma unroll
    for (int cp = 0; cp < COP; cp++)
        acc2[cp] = pack2(Bi[g * COUT_G + 2 * cp], Bi[g * COUT_G + 2 * cp + 1]);
    for (int ci = 0; ci < CIN_G; ci++) {
        for (int t = tid; t < HALO * HALO; t += 256) {
            int r = t / HALO, c = t % HALO;
            int gy = (ty0 + r - PAD) & 63;
            int gx = (tx0 + c - PAD) & 63;
            s_in[t] = IN[(((long)b * CIN_TOTAL + g * CIN_G + ci) * 64 + gy) * 64 + gx];
        }
        for (int t = tid; t < COUT_G * KS * KS; t += 256) {
            int co = t % COUT_G, r = t / COUT_G;
            s_w[r * COUT_G + co] = W[(((long)(g * COUT_G + co)) * CIN_G + ci) * (KS * KS) + r];
        }
        __syncthreads();
        #pragma unroll
        for (int ky = 0; ky < KS; ky++) {
            #pragma unroll
            for (int kx = 0; kx < KS; kx++) {
                u64t vd = dup2(s_in[(ty + ky) * HALO + tx + kx]);
                const u64t* wrow = (const u64t*)&s_w[(ky * KS + kx) * COUT_G];
                #pragma unroll
                for (int cp = 0; cp < COP; cp++)
                    fma2(acc2[cp], vd, wrow[cp]);
            }
        }
        __syncthreads();
    }
    #pragma unroll
    for (int cp = 0; cp < COP; cp++) {
        float2 p = unp2(acc2[cp]);
        float v0 = DO_GELU ? gelu_exact(p.x) : p.x;
        float v1 = DO_GELU ? gelu_exact(p.y) : p.y;
        long base = (((long)b * COUT_TOTAL + g * COUT_G + 2 * cp) * 64 + ty0 + ty) * 64 + tx0 + tx;
        OUT[base] = v0;
        OUT[base + NPIX] = v1;
    }
}

// ---------------- 1x1 conv 48->3 ----------------
__global__ void conv1_kernel(const float* __restrict__ IN, const float* __restrict__ W,
                             const float* __restrict__ Bi, float* __restrict__ OUT) {
    int b = blockIdx.y;
    int pix = blockIdx.x * 256 + threadIdx.x;
    float a0 = Bi[0], a1 = Bi[1], a2 = Bi[2];
    #pragma unroll
    for (int c = 0; c < 48; c++) {
        float v = IN[((long)b * 48 + c) * NPIX + pix];
        a0 = fmaf(v, W[0 * 48 + c], a0);
        a1 = fmaf(v, W[1 * 48 + c], a1);
        a2 = fmaf(v, W[2 * 48 + c], a2);
    }
    long base = ((long)b * NPIX + pix) * 3;
    OUT[base + 0] = a0; OUT[base + 1] = a1; OUT[base + 2] = a2;
}

// ---------------- host ----------------
extern "C" void kernel_launch(void* const* d_in, const int* in_sizes, int n_in,
                              void* d_out, int out_size) {
    const float* x        = (const float*)d_in[0];
    const float* to_in_w  = (const float*)d_in[1];
    const float* to_in_b  = (const float*)d_in[2];
    const float* pos_emb  = (const float*)d_in[3];
    const float* proj     = (const float*)d_in[4];
    const float* sn_attn_g= (const float*)d_in[5];
    const float* wq       = (const float*)d_in[6];
    const float* wk       = (const float*)d_in[7];
    const float* wv       = (const float*)d_in[8];
    const float* wo       = (const float*)d_in[9];
    const float* bo       = (const float*)d_in[10];
    const float* sn_ff_g  = (const float*)d_in[11];
    const float* w1       = (const float*)d_in[12];
    const float* b1       = (const float*)d_in[13];
    const float* w2       = (const float*)d_in[14];
    const float* b2       = (const float*)d_in[15];
    const float* expand_w = (const float*)d_in[16];
    const float* fwd_w    = (const float*)d_in[17];
    const float* dec_lin_w= (const float*)d_in[18];
    const float* dec_lin_b= (const float*)d_in[19];
    const float* gn_g     = (const float*)d_in[20];
    const float* gn_b     = (const float*)d_in[21];
    const float* c9_w     = (const float*)d_in[22];
    const float* c9_b     = (const float*)d_in[23];
    const float* c7_w     = (const float*)d_in[24];
    const float* c7_b     = (const float*)d_in[25];
    const float* c5_w     = (const float*)d_in[26];
    const float* c5_b     = (const float*)d_in[27];
    const float* c1_w     = (const float*)d_in[28];
    const float* c1_b     = (const float*)d_in[29];
    float* out = (float*)d_out;

    float *ph, *phn, *pq, *pk, *pv, *pqp, *pkp, *pctx, *pctxp, *pksum, *pkmax, *pkmp,
          *pksp, *pattn, *pff, *pt1, *pt2, *py, *pnchw, *pc9, *pc7, *pc5;
    cudaGetSymbolAddress((void**)&ph, g_h);
    cudaGetSymbolAddress((void**)&phn, g_hn);
    cudaGetSymbolAddress((void**)&pq, g_q);
    cudaGetSymbolAddress((void**)&pk, g_k);
    cudaGetSymbolAddress((void**)&pv, g_v);
    cudaGetSymbolAddress((void**)&pqp, g_qp);
    cudaGetSymbolAddress((void**)&pkp, g_kp);
    cudaGetSymbolAddress((void**)&pctx, g_ctx);
    cudaGetSymbolAddress((void**)&pctxp, g_ctxp);
    cudaGetSymbolAddress((void**)&pksum, g_ksum);
    cudaGetSymbolAddress((void**)&pkmax, g_kmax);
    cudaGetSymbolAddress((void**)&pkmp, g_kmpart);
    cudaGetSymbolAddress((void**)&pksp, g_kspart);
    cudaGetSymbolAddress((void**)&pattn, g_attn);
    cudaGetSymbolAddress((void**)&pff, g_ff);
    cudaGetSymbolAddress((void**)&pt1, g_t1);
    cudaGetSymbolAddress((void**)&pt2, g_t2);
    cudaGetSymbolAddress((void**)&py, g_y);
    cudaGetSymbolAddress((void**)&pnchw, g_nchw);
    cudaGetSymbolAddress((void**)&pc9, g_c9o);
    cudaGetSymbolAddress((void**)&pc7, g_c7o);
    cudaGetSymbolAddress((void**)&pc5, g_c5o);

    embed_kernel<<<ROWS, DIM>>>(x, to_in_w, to_in_b, pos_emb, ph);

    const long CTOT = (long)BHN * MP * DH;
    for (int i = 0; i < DEPTH; i++) {
        const float* proj_i = proj + (long)i * MFEAT * DH;
        scalenorm_kernel<<<2048, 256>>>(ph, phn, sn_attn_g, i);
        gemm_qkv_f2<<<dim3(128, 4, 3), 256>>>(phn,
            wq + (long)i * INNER * DIM, wk + (long)i * INNER * DIM, wv + (long)i * INNER * DIM,
            pq, pk, pv);
        gemm_dd2<<<dim3(32, 5, 64), 256>>>(pq, pk, proj_i, pqp, pkp, pkmp);
        kmax_fin2<<<BHN, 32>>>(pkmp, pkmax);
        finalize_kernel<true ><<<16384, 256>>>(pq, pqp, nullptr);
        finalize_kernel<false><<<16384, 256>>>(pk, pkp, pkmax);
        gemm_ctx2<<<dim3(5, CTX_SPLIT, BHN), 128>>>(pkp, pv, pctxp, pksp);
        ctx_reduce_kernel<<<(int)((CTOT + 255) / 256), 256>>>(pctxp, pctx);
        ksum_fin_kernel<<<BHN, MP>>>(pksp, pksum);
        gemm_out2<<<dim3(32, 1, BHN), 256>>>(pqp, pctx, pksum, pattn);
        gemm_f2n64k<3><<<dim3(128, 3), 256>>>(pattn, wo + (long)i * DIM * INNER, bo + (long)i * DIM, ph, ph, DIM, INNER);
        scalenorm_kernel<<<2048, 256>>>(ph, phn, sn_ff_g, i);
        gemm_f2n128k<2><<<dim3(128, 6), 256>>>(phn, w1 + (long)i * FF * DIM, b1 + (long)i * FF, nullptr, pff, FF, DIM);
        gemm_f2n64k<3><<<dim3(128, 3), 256>>>(pff, w2 + (long)i * DIM * FF, b2 + (long)i * DIM, ph, ph, DIM, FF);
    }

    gemm_f2n64k<0><<<dim3(128, 3), 256>>>(ph, expand_w, nullptr, nullptr, pt1, DIM, DIM);
    gemm_f2n64k<0><<<dim3(128, 3), 256>>>(pt1, fwd_w, nullptr, nullptr, pt2, DIM, DIM);
    gemm_f2n64k<1><<<dim3(128, 3), 256>>>(pt2, dec_lin_w, dec_lin_b, nullptr, py, DIM, DIM);

    groupnorm_kernel<<<32, 256>>>(py, gn_g, gn_b, pnchw);
    conv_circ<24, 24, 9, 192, 192, true><<<dim3(16, 8, 4), 256>>>(pnchw, c9_w, c9_b, pc9);
    conv_circ<24, 12, 7, 192,  96, true><<<dim3(16, 8, 4), 256>>>(pc9, c7_w, c7_b, pc7);
    conv_circ<12,  6, 5,  96,  48, true><<<dim3(16, 8, 4), 256>>>(pc7, c5_w, c5_b, pc5);
    conv1_kernel<<<dim3(16, 4), 256>>>(pc5, c1_w, c1_b, out);
}

// round 10
// speedup vs baseline: 2.9505x; 1.0483x over previous
#include <cuda_runtime.h>
#include <cuda_bf16.h>
#include <math.h>

// ---------------- constants ----------------
#define BATCH 4
#define NPIX  4096          // 64*64
#define ROWS  16384         // BATCH*NPIX
#define DIM   192
#define DEPTH 6
#define HEADS 8
#define DH    64
#define INNER 512
#define FF    768
#define MFEAT 266
#define MP    272           // padded feature dim (mult of 16)
#define BHN   32            // BATCH*HEADS
#define CTX_SPLIT 8         // split-K slices for context GEMM

typedef unsigned long long u64t;

__device__ __forceinline__ float gelu_exact(float x) {
    return 0.5f * x * (1.0f + erff(x * 0.70710678118654752f));
}
__device__ __forceinline__ float warpSum(float v) {
    #pragma unroll
    for (int o = 16; o; o >>= 1) v += __shfl_xor_sync(0xffffffffu, v, o);
    return v;
}
__device__ __forceinline__ float warpMax(float v) {
    #pragma unroll
    for (int o = 16; o; o >>= 1) v = fmaxf(v, __shfl_xor_sync(0xffffffffu, v, o));
    return v;
}
// packed fp32x2 helpers (Blackwell FFMA2 — bitwise identical to 2x scalar fmaf)
__device__ __forceinline__ void fma2(u64t& d, u64t a, u64t b) {
    asm("fma.rn.f32x2 %0, %1, %2, %3;" : "=l"(d) : "l"(a), "l"(b), "l"(d));
}
__device__ __forceinline__ u64t dup2(float v) {
    u64t r; asm("mov.b64 %0, {%1, %1};" : "=l"(r) : "f"(v)); return r;
}
__device__ __forceinline__ u64t pack2(float lo, float hi) {
    u64t r; asm("mov.b64 %0, {%1, %2};" : "=l"(r) : "f"(lo), "f"(hi)); return r;
}
__device__ __forceinline__ float2 unp2(u64t v) {
    float2 r; asm("mov.b64 {%0, %1}, %2;" : "=f"(r.x), "=f"(r.y) : "l"(v)); return r;
}
// FAVOR+ feature transform applied at consumer load time (was finalize pass)
__device__ __forceinline__ float feat_xf(float v, int m, float sub) {
    const float ratio = 0.06131393394849658f;   // 266^-0.5
    return (m < MFEAT) ? ratio * (expf(v - sub) + 1e-4f) : 0.f;
}

// ---------------- scratch (device globals; no allocs allowed) ----------------
__device__ float g_h   [ROWS * DIM];
__device__ float g_hn  [ROWS * DIM];
__device__ float g_q   [ROWS * INNER];     // head-major [bh][n][64]
__device__ float g_k   [ROWS * INNER];     // head-major
__device__ float g_v   [ROWS * INNER];     // head-major
__device__ float g_qp  [(long)BHN * NPIX * MP];   // RAW dd_q (dn-scaled)
__device__ float g_kp  [(long)BHN * NPIX * MP];   // RAW dd_k (dn-scaled)
__device__ float g_ctx [BHN * MP * DH];
__device__ float g_ctxp[(long)CTX_SPLIT * BHN * MP * DH];
__device__ float g_ksum[BHN * MP];
__device__ float g_kmax[BHN];
__device__ float g_kmpart[BHN * 160];
__device__ float g_kspart[(long)CTX_SPLIT * BHN * MP];
__device__ float g_diagq[BHN * NPIX];
__device__ float g_diagk[BHN * NPIX];
__device__ float g_qmaxp[(long)BHN * 5 * NPIX];
__device__ float g_qmax [BHN * NPIX];
__device__ float g_attn[ROWS * INNER];     // n-major [b][n][512]
__device__ float g_ff  [ROWS * FF];
__device__ float g_t1  [ROWS * DIM];
__device__ float g_t2  [ROWS * DIM];
__device__ float g_y   [ROWS * DIM];
__device__ float g_nchw[BATCH * 192 * 64 * 64];
__device__ float g_c9o [BATCH * 192 * 64 * 64];
__device__ float g_c7o [BATCH * 96 * 64 * 64];
__device__ float g_c5o [BATCH * 48 * 64 * 64];

// ---------------- embed ----------------
__global__ void embed_kernel(const float* __restrict__ x, const float* __restrict__ W,
                             const float* __restrict__ bias, const float* __restrict__ pos,
                             float* __restrict__ H) {
    int row = blockIdx.x;
    int c = threadIdx.x;
    int n = row & (NPIX - 1);
    const float* xr = x + (long)row * 3;
    float v = bias[c] + xr[0] * W[c * 3 + 0] + xr[1] * W[c * 3 + 1] + xr[2] * W[c * 3 + 2]
            + pos[(long)n * DIM + c];
    H[(long)row * DIM + c] = v;
}

// ---------------- scalenorm ----------------
__global__ void scalenorm_kernel(const float* __restrict__ in, float* __restrict__ out,
                                 const float* __restrict__ gArr, int gIdx) {
    int w = (blockIdx.x * blockDim.x + threadIdx.x) >> 5;
    int lane = threadIdx.x & 31;
    if (w >= ROWS) return;
    const float* r = in + (long)w * DIM;
    float ss = 0.f;
    #pragma unroll
    for (int c = lane; c < DIM; c += 32) { float v = r[c]; ss += v * v; }
    ss = warpSum(ss);
    float nrm = sqrtf(ss) * 0.07216878364870323f;
    float s = gArr[gIdx] / fmaxf(nrm, 1e-5f);
    #pragma unroll
    for (int c = lane; c < DIM; c += 32) out[(long)w * DIM + c] = r[c] * s;
}

// =============================================================================
// Double-buffered FFMA2 GEMM body, BN=128.
// EPI: 0 none, 1 +bias, 2 gelu(+bias), 3 +bias+resid; HM: head-major output
// =============================================================================
template<int EPI, int HM>
__device__ __forceinline__ void gemm_n128_body(
    const float* __restrict__ A, const float* __restrict__ B,
    const float* __restrict__ bias, const float* __restrict__ resid,
    float* __restrict__ C, int N, int K) {
    __shared__ float As[2][16][128];
    __shared__ float Bs[2][16][128];
    const int tid = threadIdx.x;
    const int bm = blockIdx.x * 128, bn = blockIdx.y * 128;
    const int tx = tid & 15, ty = tid >> 4;
    u64t acc[4][8];
    #pragma unroll
    for (int i = 0; i < 4; i++)
        #pragma unroll
        for (int j = 0; j < 8; j++) acc[i][j] = 0ull;

    const int lr = tid >> 1, lk = (tid & 1) * 8;
    const float* Arow = A + (long)(bm + lr) * K + lk;
    const float* Brow = B + (long)(bn + lr) * K + lk;

    {
        float4 a0 = *(const float4*)(Arow),     a1 = *(const float4*)(Arow + 4);
        float4 b0 = *(const float4*)(Brow),     b1 = *(const float4*)(Brow + 4);
        As[0][lk+0][lr]=a0.x; As[0][lk+1][lr]=a0.y; As[0][lk+2][lr]=a0.z; As[0][lk+3][lr]=a0.w;
        As[0][lk+4][lr]=a1.x; As[0][lk+5][lr]=a1.y; As[0][lk+6][lr]=a1.z; As[0][lk+7][lr]=a1.w;
        Bs[0][lk+0][lr]=b0.x; Bs[0][lk+1][lr]=b0.y; Bs[0][lk+2][lr]=b0.z; Bs[0][lk+3][lr]=b0.w;
        Bs[0][lk+4][lr]=b1.x; Bs[0][lk+5][lr]=b1.y; Bs[0][lk+6][lr]=b1.z; Bs[0][lk+7][lr]=b1.w;
    }
    __syncthreads();
    int buf = 0;
    for (int k0 = 16; k0 <= K; k0 += 16) {
        const bool more = (k0 < K);
        float4 a0, a1, b0, b1;
        if (more) {
            a0 = *(const float4*)(Arow + k0); a1 = *(const float4*)(Arow + k0 + 4);
            b0 = *(const float4*)(Brow + k0); b1 = *(const float4*)(Brow + k0 + 4);
        }
        const float (*Ac)[128] = As[buf];
        const float (*Bc)[128] = Bs[buf];
        #pragma unroll
        for (int kk = 0; kk < 16; kk++) {
            const u64t* ap = (const u64t*)&Ac[kk][ty * 8];
            u64t av0 = ap[0], av1 = ap[1], av2 = ap[2], av3 = ap[3];
            float4 p0 = *(const float4*)&Bc[kk][tx * 4];
            float4 p1 = *(const float4*)&Bc[kk][64 + tx * 4];
            u64t bv[8];
            bv[0]=dup2(p0.x); bv[1]=dup2(p0.y); bv[2]=dup2(p0.z); bv[3]=dup2(p0.w);
            bv[4]=dup2(p1.x); bv[5]=dup2(p1.y); bv[6]=dup2(p1.z); bv[7]=dup2(p1.w);
            #pragma unroll
            for (int j = 0; j < 8; j++) {
                fma2(acc[0][j], av0, bv[j]);
                fma2(acc[1][j], av1, bv[j]);
                fma2(acc[2][j], av2, bv[j]);
                fma2(acc[3][j], av3, bv[j]);
            }
        }
        if (more) {
            float (*An)[128] = As[buf ^ 1];
            float (*Bn)[128] = Bs[buf ^ 1];
            An[lk+0][lr]=a0.x; An[lk+1][lr]=a0.y; An[lk+2][lr]=a0.z; An[lk+3][lr]=a0.w;
            An[lk+4][lr]=a1.x; An[lk+5][lr]=a1.y; An[lk+6][lr]=a1.z; An[lk+7][lr]=a1.w;
            Bn[lk+0][lr]=b0.x; Bn[lk+1][lr]=b0.y; Bn[lk+2][lr]=b0.z; Bn[lk+3][lr]=b0.w;
            Bn[lk+4][lr]=b1.x; Bn[lk+5][lr]=b1.y; Bn[lk+6][lr]=b1.z; Bn[lk+7][lr]=b1.w;
        }
        __syncthreads();
        buf ^= 1;
    }
    const int col0 = bn + tx * 4, col1 = bn + 64 + tx * 4;
    float bcol[8];
    if (EPI >= 1) {
        #pragma unroll
        for (int j = 0; j < 4; j++) { bcol[j] = bias[col0 + j]; bcol[4 + j] = bias[col1 + j]; }
    }
    #pragma unroll
    for (int i = 0; i < 4; i++) {
        int r0 = bm + ty * 8 + 2 * i;
        float o0[8], o1[8];
        #pragma unroll
        for (int j = 0; j < 8; j++) { float2 p = unp2(acc[i][j]); o0[j] = p.x; o1[j] = p.y; }
        if (EPI >= 1) {
            #pragma unroll
            for (int j = 0; j < 8; j++) { o0[j] += bcol[j]; o1[j] += bcol[j]; }
        }
        if (EPI == 2) {
            #pragma unroll
            for (int j = 0; j < 8; j++) { o0[j] = gelu_exact(o0[j]); o1[j] = gelu_exact(o1[j]); }
        }
        if (EPI == 3) {
            const float* rr0 = resid + (long)r0 * N;
            const float* rr1 = rr0 + N;
            #pragma unroll
            for (int j = 0; j < 4; j++) {
                o0[j] += rr0[col0 + j]; o0[4+j] += rr0[col1 + j];
                o1[j] += rr1[col0 + j]; o1[4+j] += rr1[col1 + j];
            }
        }
        if (HM) {
            int bb = r0 >> 12, nn = r0 & (NPIX - 1);
            long base0 = ((long)(bb * HEADS + (col0 >> 6)) * NPIX + nn) * DH + (col0 & 63);
            long base1 = ((long)(bb * HEADS + (col1 >> 6)) * NPIX + nn) * DH + (col1 & 63);
            *(float4*)(C + base0)      = make_float4(o0[0], o0[1], o0[2], o0[3]);
            *(float4*)(C + base1)      = make_float4(o0[4], o0[5], o0[6], o0[7]);
            *(float4*)(C + base0 + DH) = make_float4(o1[0], o1[1], o1[2], o1[3]);
            *(float4*)(C + base1 + DH) = make_float4(o1[4], o1[5], o1[6], o1[7]);
        } else {
            float* c0 = C + (long)r0 * N;
            *(float4*)(c0 + col0) = make_float4(o0[0], o0[1], o0[2], o0[3]);
            *(float4*)(c0 + col1) = make_float4(o0[4], o0[5], o0[6], o0[7]);
            float* c1 = c0 + N;
            *(float4*)(c1 + col0) = make_float4(o1[0], o1[1], o1[2], o1[3]);
            *(float4*)(c1 + col1) = make_float4(o1[4], o1[5], o1[6], o1[7]);
        }
    }
}

// fused QKV (same A; B/C selected by blockIdx.z); head-major outputs
__global__ void __launch_bounds__(256, 2) gemm_qkv_f2(
    const float* __restrict__ A, const float* __restrict__ Bq,
    const float* __restrict__ Bk, const float* __restrict__ Bv,
    float* __restrict__ Cq, float* __restrict__ Ck, float* __restrict__ Cv) {
    const float* B = (blockIdx.z == 0) ? Bq : (blockIdx.z == 1) ? Bk : Bv;
    float* C = (blockIdx.z == 0) ? Cq : (blockIdx.z == 1) ? Ck : Cv;
    gemm_n128_body<0, 1>(A, B, nullptr, nullptr, C, INNER, DIM);
}

template<int EPI>
__global__ void __launch_bounds__(256, 2) gemm_f2n128k(
    const float* __restrict__ A, const float* __restrict__ B,
    const float* __restrict__ bias, const float* __restrict__ resid,
    float* __restrict__ C, int N, int K) {
    gemm_n128_body<EPI, 0>(A, B, bias, resid, C, N, K);
}

// =============================================================================
// Double-buffered FFMA2 GEMM body, BN=64: BM=128, 256 threads.
// =============================================================================
template<int EPI>
__device__ __forceinline__ void gemm_n64_body(
    const float* __restrict__ A, const float* __restrict__ B,
    const float* __restrict__ bias, const float* __restrict__ resid,
    float* __restrict__ C, int N, int K) {
    __shared__ float As[2][16][128];
    __shared__ float Bs[2][16][64];
    const int tid = threadIdx.x;
    const int bm = blockIdx.x * 128, bn = blockIdx.y * 64;
    const int tx = tid & 7, ty = tid >> 3;
    u64t acc[2][8];
    #pragma unroll
    for (int i = 0; i < 2; i++)
        #pragma unroll
        for (int j = 0; j < 8; j++) acc[i][j] = 0ull;

    const int lr = tid >> 1, lk = (tid & 1) * 8;
    const float* Arow = A + (long)(bm + lr) * K + lk;
    const int br = tid >> 2, bk = (tid & 3) * 4;
    const float* Brow = B + (long)(bn + br) * K + bk;

    {
        float4 a0 = *(const float4*)(Arow), a1 = *(const float4*)(Arow + 4);
        float4 bb = *(const float4*)(Brow);
        As[0][lk+0][lr]=a0.x; As[0][lk+1][lr]=a0.y; As[0][lk+2][lr]=a0.z; As[0][lk+3][lr]=a0.w;
        As[0][lk+4][lr]=a1.x; As[0][lk+5][lr]=a1.y; As[0][lk+6][lr]=a1.z; As[0][lk+7][lr]=a1.w;
        Bs[0][bk+0][br]=bb.x; Bs[0][bk+1][br]=bb.y; Bs[0][bk+2][br]=bb.z; Bs[0][bk+3][br]=bb.w;
    }
    __syncthreads();
    int buf = 0;
    for (int k0 = 16; k0 <= K; k0 += 16) {
        const bool more = (k0 < K);
        float4 a0, a1, bb;
        if (more) {
            a0 = *(const float4*)(Arow + k0); a1 = *(const float4*)(Arow + k0 + 4);
            bb = *(const float4*)(Brow + k0);
        }
        const float (*Ac)[128] = As[buf];
        const float (*Bc)[64] = Bs[buf];
        #pragma unroll
        for (int kk = 0; kk < 16; kk++) {
            const u64t* ap = (const u64t*)&Ac[kk][ty * 4];
            u64t av0 = ap[0], av1 = ap[1];
            float4 p0 = *(const float4*)&Bc[kk][tx * 4];
            float4 p1 = *(const float4*)&Bc[kk][32 + tx * 4];
            u64t bv[8];
            bv[0]=dup2(p0.x); bv[1]=dup2(p0.y); bv[2]=dup2(p0.z); bv[3]=dup2(p0.w);
            bv[4]=dup2(p1.x); bv[5]=dup2(p1.y); bv[6]=dup2(p1.z); bv[7]=dup2(p1.w);
            #pragma unroll
            for (int j = 0; j < 8; j++) {
                fma2(acc[0][j], av0, bv[j]);
                fma2(acc[1][j], av1, bv[j]);
            }
        }
        if (more) {
            float (*An)[128] = As[buf ^ 1];
            float (*Bn)[64] = Bs[buf ^ 1];
            An[lk+0][lr]=a0.x; An[lk+1][lr]=a0.y; An[lk+2][lr]=a0.z; An[lk+3][lr]=a0.w;
            An[lk+4][lr]=a1.x; An[lk+5][lr]=a1.y; An[lk+6][lr]=a1.z; An[lk+7][lr]=a1.w;
            Bn[bk+0][br]=bb.x; Bn[bk+1][br]=bb.y; Bn[bk+2][br]=bb.z; Bn[bk+3][br]=bb.w;
        }
        __syncthreads();
        buf ^= 1;
    }
    const int col0 = bn + tx * 4, col1 = bn + 32 + tx * 4;
    float bcol[8];
    if (EPI >= 1) {
        #pragma unroll
        for (int j = 0; j < 4; j++) { bcol[j] = bias[col0 + j]; bcol[4 + j] = bias[col1 + j]; }
    }
    #pragma unroll
    for (int i = 0; i < 2; i++) {
        int r0 = bm + ty * 4 + 2 * i;
        float o0[8], o1[8];
        #pragma unroll
        for (int j = 0; j < 8; j++) { float2 p = unp2(acc[i][j]); o0[j] = p.x; o1[j] = p.y; }
        if (EPI >= 1) {
            #pragma unroll
            for (int j = 0; j < 8; j++) { o0[j] += bcol[j]; o1[j] += bcol[j]; }
        }
        if (EPI == 2) {
            #pragma unroll
            for (int j = 0; j < 8; j++) { o0[j] = gelu_exact(o0[j]); o1[j] = gelu_exact(o1[j]); }
        }
        if (EPI == 3) {
            const float* rr0 = resid + (long)r0 * N;
            const float* rr1 = rr0 + N;
            #pragma unroll
            for (int j = 0; j < 4; j++) {
                o0[j] += rr0[col0 + j]; o0[4+j] += rr0[col1 + j];
                o1[j] += rr1[col0 + j]; o1[4+j] += rr1[col1 + j];
            }
        }
        float* c0 = C + (long)r0 * N;
        *(float4*)(c0 + col0) = make_float4(o0[0], o0[1], o0[2], o0[3]);
        *(float4*)(c0 + col1) = make_float4(o0[4], o0[5], o0[6], o0[7]);
        float* c1 = c0 + N;
        *(float4*)(c1 + col0) = make_float4(o1[0], o1[1], o1[2], o1[3]);
        *(float4*)(c1 + col1) = make_float4(o1[4], o1[5], o1[6], o1[7]);
    }
}

template<int EPI>
__global__ void __launch_bounds__(256, 2) gemm_f2n64k(
    const float* __restrict__ A, const float* __restrict__ B,
    const float* __restrict__ bias, const float* __restrict__ resid,
    float* __restrict__ C, int N, int K) {
    gemm_n64_body<EPI>(A, B, bias, resid, C, N, K);
}

// =============================================================================
// dd GEMM merged q+k (head-major A): z<32 -> q, else k. Writes RAW dd (dn-scaled),
// plus: diag[bh][n] (fused, free from A regs), q per-row max partials, k global
// max partials. grid (32, 5, 64)
// =============================================================================
__global__ void __launch_bounds__(256, 2) gemm_dd2(
    const float* __restrict__ Q, const float* __restrict__ Kh,
    const float* __restrict__ P,
    float* __restrict__ QP, float* __restrict__ KP,
    float* __restrict__ maxpart, float* __restrict__ qmaxp,
    float* __restrict__ diagq, float* __restrict__ diagk) {
    __shared__ float As[2][16][128];
    __shared__ float Bs[2][16][64];
    const int tid = threadIdx.x;
    const bool isK = (blockIdx.z >= 32);
    const int bh = blockIdx.z & 31;
    const float* Ain = isK ? Kh : Q;
    float* DD = isK ? KP : QP;
    const int bm = blockIdx.x * 128, bn = blockIdx.y * 64;
    const int tx = tid & 7, ty = tid >> 3;
    u64t acc[2][8];
    u64t dacc[2];
    dacc[0] = 0ull; dacc[1] = 0ull;
    #pragma unroll
    for (int i = 0; i < 2; i++)
        #pragma unroll
        for (int j = 0; j < 8; j++) acc[i][j] = 0ull;

    const int lr = tid >> 1, lk = (tid & 1) * 8;
    const float* Arow = Ain + ((long)bh * NPIX + bm + lr) * DH + lk;
    const int br = tid >> 2, bk = (tid & 3) * 4;
    const int mB = bn + br;
    const float* Brow = P + (long)mB * DH + bk;
    const bool bval = (mB < MFEAT);

    {
        float4 a0 = *(const float4*)(Arow), a1 = *(const float4*)(Arow + 4);
        float4 bb = make_float4(0.f, 0.f, 0.f, 0.f);
        if (bval) bb = *(const float4*)(Brow);
        As[0][lk+0][lr]=a0.x; As[0][lk+1][lr]=a0.y; As[0][lk+2][lr]=a0.z; As[0][lk+3][lr]=a0.w;
        As[0][lk+4][lr]=a1.x; As[0][lk+5][lr]=a1.y; As[0][lk+6][lr]=a1.z; As[0][lk+7][lr]=a1.w;
        Bs[0][bk+0][br]=bb.x; Bs[0][bk+1][br]=bb.y; Bs[0][bk+2][br]=bb.z; Bs[0][bk+3][br]=bb.w;
    }
    __syncthreads();
    int buf = 0;
    for (int k0 = 16; k0 <= DH; k0 += 16) {
        const bool more = (k0 < DH);
        float4 a0, a1, bb;
        if (more) {
            a0 = *(const float4*)(Arow + k0); a1 = *(const float4*)(Arow + k0 + 4);
            bb = make_float4(0.f, 0.f, 0.f, 0.f);
            if (bval) bb = *(const float4*)(Brow + k0);
        }
        const float (*Ac)[128] = As[buf];
        const float (*Bc)[64] = Bs[buf];
        #pragma unroll
        for (int kk = 0; kk < 16; kk++) {
            const u64t* ap = (const u64t*)&Ac[kk][ty * 4];
            u64t av0 = ap[0], av1 = ap[1];
            float4 p0 = *(const float4*)&Bc[kk][tx * 4];
            float4 p1 = *(const float4*)&Bc[kk][32 + tx * 4];
            u64t bv[8];
            bv[0]=dup2(p0.x); bv[1]=dup2(p0.y); bv[2]=dup2(p0.z); bv[3]=dup2(p0.w);
            bv[4]=dup2(p1.x); bv[5]=dup2(p1.y); bv[6]=dup2(p1.z); bv[7]=dup2(p1.w);
            #pragma unroll
            for (int j = 0; j < 8; j++) {
                fma2(acc[0][j], av0, bv[j]);
                fma2(acc[1][j], av1, bv[j]);
            }
            fma2(dacc[0], av0, av0);   // fused diag = sum_k A^2 (per row pair)
            fma2(dacc[1], av1, av1);
        }
        if (more) {
            float (*An)[128] = As[buf ^ 1];
            float (*Bn)[64] = Bs[buf ^ 1];
            An[lk+0][lr]=a0.x; An[lk+1][lr]=a0.y; An[lk+2][lr]=a0.z; An[lk+3][lr]=a0.w;
            An[lk+4][lr]=a1.x; An[lk+5][lr]=a1.y; An[lk+6][lr]=a1.z; An[lk+7][lr]=a1.w;
            Bn[bk+0][br]=bb.x; Bn[bk+1][br]=bb.y; Bn[bk+2][br]=bb.z; Bn[bk+3][br]=bb.w;
        }
        __syncthreads();
        buf ^= 1;
    }
    const float dn = 0.35355339059327373f;  // 64^-0.25
    float* Cb = DD + (long)bh * NPIX * MP;
    const int col0 = bn + tx * 4, col1 = bn + 32 + tx * 4;
    float rmax[4] = {-1e30f, -1e30f, -1e30f, -1e30f};
    const bool fullblk = (bn + 64 <= MFEAT);
    #pragma unroll
    for (int i = 0; i < 2; i++) {
        int r0 = bm + ty * 4 + 2 * i;
        float o0[8], o1[8];
        #pragma unroll
        for (int j = 0; j < 8; j++) {
            float2 p = unp2(acc[i][j]);
            o0[j] = dn * p.x; o1[j] = dn * p.y;
        }
        float* c0 = Cb + (long)r0 * MP;
        float* c1 = c0 + MP;
        if (fullblk) {
            *(float4*)(c0 + col0) = make_float4(o0[0], o0[1], o0[2], o0[3]);
            *(float4*)(c0 + col1) = make_float4(o0[4], o0[5], o0[6], o0[7]);
            *(float4*)(c1 + col0) = make_float4(o1[0], o1[1], o1[2], o1[3]);
            *(float4*)(c1 + col1) = make_float4(o1[4], o1[5], o1[6], o1[7]);
            #pragma unroll
            for (int j = 0; j < 8; j++) {
                rmax[2*i]   = fmaxf(rmax[2*i],   o0[j]);
                rmax[2*i+1] = fmaxf(rmax[2*i+1], o1[j]);
            }
        } else {
            #pragma unroll
            for (int j = 0; j < 4; j++) {
                int ca = col0 + j, cb2 = col1 + j;
                if (ca < MP) { c0[ca] = o0[j]; c1[ca] = o1[j]; }
                if (cb2 < MP) { c0[cb2] = o0[4+j]; c1[cb2] = o1[4+j]; }
                if (ca < MFEAT) {
                    rmax[2*i]   = fmaxf(rmax[2*i],   o0[j]);
                    rmax[2*i+1] = fmaxf(rmax[2*i+1], o1[j]);
                }
                if (cb2 < MFEAT) {
                    rmax[2*i]   = fmaxf(rmax[2*i],   o0[4+j]);
                    rmax[2*i+1] = fmaxf(rmax[2*i+1], o1[4+j]);
                }
            }
        }
    }
    if (isK) {
        __shared__ float sm[8];
        float mx = fmaxf(fmaxf(rmax[0], rmax[1]), fmaxf(rmax[2], rmax[3]));
        mx = warpMax(mx);
        int lane = tid & 31, wid = tid >> 5;
        if (lane == 0) sm[wid] = mx;
        __syncthreads();
        if (tid == 0) {
            float m = sm[0];
            #pragma unroll
            for (int w = 1; w < 8; w++) m = fmaxf(m, sm[w]);
            maxpart[bh * 160 + blockIdx.x * 5 + blockIdx.y] = m;
        }
    } else {
        // per-row max partials: reduce across tx (8-lane groups)
        #pragma unroll
        for (int r = 0; r < 4; r++) {
            #pragma unroll
            for (int o = 1; o < 8; o <<= 1)
                rmax[r] = fmaxf(rmax[r], __shfl_xor_sync(0xffffffffu, rmax[r], o));
        }
        if (tx == 0) {
            float* qp = qmaxp + ((long)(bh * 5 + blockIdx.y)) * NPIX + bm + ty * 4;
            qp[0] = rmax[0]; qp[1] = rmax[1]; qp[2] = rmax[2]; qp[3] = rmax[3];
        }
    }
    // fused diag (write once, from the bn==0 tile)
    if (blockIdx.y == 0 && tx == 0) {
        float2 d0 = unp2(dacc[0]), d1 = unp2(dacc[1]);
        float* dg = (isK ? diagk : diagq) + (long)bh * NPIX + bm + ty * 4;
        dg[0] = 0.0625f * d0.x; dg[1] = 0.0625f * d0.y;
        dg[2] = 0.0625f * d1.x; dg[3] = 0.0625f * d1.y;
    }
}

__global__ void kmax_fin2(const float* __restrict__ part, float* __restrict__ kmax) {
    int bh = blockIdx.x;
    float v = -1e30f;
    for (int i = threadIdx.x; i < 160; i += 32) v = fmaxf(v, part[bh * 160 + i]);
    v = warpMax(v);
    if (threadIdx.x == 0) kmax[bh] = v;
}

__global__ void qmax_fin(const float* __restrict__ part, float* __restrict__ qmax) {
    int idx = blockIdx.x * 256 + threadIdx.x;     // bh*NPIX + n
    int bh = idx >> 12, n = idx & (NPIX - 1);
    float v = -1e30f;
    #pragma unroll
    for (int t = 0; t < 5; t++)
        v = fmaxf(v, part[((long)(bh * 5 + t)) * NPIX + n]);
    qmax[idx] = v;
}

// =============================================================================
// context split-K + fused ksum + FUSED key finalize (exp applied at A-load).
// tile m=64 x d=64, 128 threads. grid (5, CTX_SPLIT, 32). V head-major.
// =============================================================================
__global__ void __launch_bounds__(128, 4) gemm_ctx2(
    const float* __restrict__ KP, const float* __restrict__ V,
    const float* __restrict__ DIAGK, const float* __restrict__ KMAX,
    float* __restrict__ CTP, float* __restrict__ KSP) {
    __shared__ float As[2][16][64];   // [n][m] transformed kp
    __shared__ float Bs[2][16][64];   // [n][d]
    const int tid = threadIdx.x;
    const int bh = blockIdx.z;
    const int m0 = blockIdx.x * 64;
    const int sl = blockIdx.y;
    const int n0base = sl * (NPIX / CTX_SPLIT);
    const int nend = n0base + NPIX / CTX_SPLIT;
    const int tx = tid & 7, ty = tid >> 3;
    u64t acc[2][8];
    u64t ksacc[2];
    ksacc[0] = 0ull; ksacc[1] = 0ull;
    #pragma unroll
    for (int i = 0; i < 2; i++)
        #pragma unroll
        for (int j = 0; j < 8; j++) acc[i][j] = 0ull;
    const u64t ONE2 = dup2(1.0f);

    const int lr = tid >> 3;          // n-row (0..15)
    const int lq = (tid & 7) * 8;     // col offset
    const float* kpB = KP + (long)bh * NPIX * MP;
    const float* vB = V + (long)bh * NPIX * DH;
    const float kmaxv = KMAX[bh];
    const float* diagB = DIAGK + (long)bh * NPIX;
    const bool mvalid = (m0 + lq) < MP;

    {
        float4 a0 = make_float4(0.f,0.f,0.f,0.f), a1 = a0;
        if (mvalid) {
            const float* ar = kpB + (long)(n0base + lr) * MP + m0 + lq;
            a0 = *(const float4*)(ar); a1 = *(const float4*)(ar + 4);
            float sub = diagB[n0base + lr] + kmaxv;
            a0.x = feat_xf(a0.x, m0+lq+0, sub); a0.y = feat_xf(a0.y, m0+lq+1, sub);
            a0.z = feat_xf(a0.z, m0+lq+2, sub); a0.w = feat_xf(a0.w, m0+lq+3, sub);
            a1.x = feat_xf(a1.x, m0+lq+4, sub); a1.y = feat_xf(a1.y, m0+lq+5, sub);
            a1.z = feat_xf(a1.z, m0+lq+6, sub); a1.w = feat_xf(a1.w, m0+lq+7, sub);
        }
        const float* brp = vB + (long)(n0base + lr) * DH + lq;
        float4 b0 = *(const float4*)(brp), b1 = *(const float4*)(brp + 4);
        *(float4*)&As[0][lr][lq] = a0; *(float4*)&As[0][lr][lq + 4] = a1;
        *(float4*)&Bs[0][lr][lq] = b0; *(float4*)&Bs[0][lr][lq + 4] = b1;
    }
    __syncthreads();
    int buf = 0;
    for (int n0 = n0base + 16; n0 <= nend; n0 += 16) {
        const bool more = (n0 < nend);
        float4 a0, a1, b0, b1;
        float sub = 0.f;
        if (more) {
            a0 = make_float4(0.f,0.f,0.f,0.f); a1 = a0;
            if (mvalid) {
                const float* ar = kpB + (long)(n0 + lr) * MP + m0 + lq;
                a0 = *(const float4*)(ar); a1 = *(const float4*)(ar + 4);
                sub = diagB[n0 + lr] + kmaxv;
            }
            const float* brp = vB + (long)(n0 + lr) * DH + lq;
            b0 = *(const float4*)(brp); b1 = *(const float4*)(brp + 4);
        }
        const float (*Ac)[64] = As[buf];
        const float (*Bc)[64] = Bs[buf];
        #pragma unroll
        for (int kk = 0; kk < 16; kk++) {
            const u64t* ap = (const u64t*)&Ac[kk][ty * 4];
            u64t av0 = ap[0], av1 = ap[1];
            float4 p0 = *(const float4*)&Bc[kk][tx * 4];
            float4 p1 = *(const float4*)&Bc[kk][32 + tx * 4];
            u64t bv[8];
            bv[0]=dup2(p0.x); bv[1]=dup2(p0.y); bv[2]=dup2(p0.z); bv[3]=dup2(p0.w);
            bv[4]=dup2(p1.x); bv[5]=dup2(p1.y); bv[6]=dup2(p1.z); bv[7]=dup2(p1.w);
            #pragma unroll
            for (int j = 0; j < 8; j++) {
                fma2(acc[0][j], av0, bv[j]);
                fma2(acc[1][j], av1, bv[j]);
            }
            fma2(ksacc[0], av0, ONE2);
            fma2(ksacc[1], av1, ONE2);
        }
        if (more) {
            if (mvalid) {
                a0.x = feat_xf(a0.x, m0+lq+0, sub); a0.y = feat_xf(a0.y, m0+lq+1, sub);
                a0.z = feat_xf(a0.z, m0+lq+2, sub); a0.w = feat_xf(a0.w, m0+lq+3, sub);
                a1.x = feat_xf(a1.x, m0+lq+4, sub); a1.y = feat_xf(a1.y, m0+lq+5, sub);
                a1.z = feat_xf(a1.z, m0+lq+6, sub); a1.w = feat_xf(a1.w, m0+lq+7, sub);
            }
            *(float4*)&As[buf^1][lr][lq] = a0; *(float4*)&As[buf^1][lr][lq + 4] = a1;
            *(float4*)&Bs[buf^1][lr][lq] = b0; *(float4*)&Bs[buf^1][lr][lq + 4] = b1;
        }
        __syncthreads();
        buf ^= 1;
    }
    float* Cb = CTP + ((long)sl * BHN + bh) * MP * DH;
    const int col0 = tx * 4, col1 = 32 + tx * 4;
    #pragma unroll
    for (int i = 0; i < 2; i++) {
        int m = m0 + ty * 4 + 2 * i;
        if (m < MP) {
            float o0[8], o1[8];
            #pragma unroll
            for (int j = 0; j < 8; j++) { float2 p = unp2(acc[i][j]); o0[j]=p.x; o1[j]=p.y; }
            float* c0 = Cb + (long)m * DH;
            float* c1 = c0 + DH;
            *(float4*)(c0 + col0) = make_float4(o0[0],o0[1],o0[2],o0[3]);
            *(float4*)(c0 + col1) = make_float4(o0[4],o0[5],o0[6],o0[7]);
            *(float4*)(c1 + col0) = make_float4(o1[0],o1[1],o1[2],o1[3]);
            *(float4*)(c1 + col1) = make_float4(o1[4],o1[5],o1[6],o1[7]);
            if (tx == 0) {
                float2 ks = unp2(ksacc[i]);
                float* kp = KSP + ((long)sl * BHN + bh) * MP + m;
                kp[0] = ks.x; kp[1] = ks.y;
            }
        }
    }
}

__global__ void ctx_reduce_kernel(const float* __restrict__ P, float* __restrict__ C) {
    long i = (long)blockIdx.x * 256 + threadIdx.x;
    const long TOT = (long)BHN * MP * DH;
    if (i < TOT) {
        float s = 0.f;
        #pragma unroll
        for (int sl = 0; sl < CTX_SPLIT; sl++) s += P[(long)sl * TOT + i];
        C[i] = s;
    }
}

__global__ void ksum_fin_kernel(const float* __restrict__ part, float* __restrict__ ksum) {
    int bh = blockIdx.x, m = threadIdx.x;
    float s = 0.f;
    #pragma unroll
    for (int sl = 0; sl < CTX_SPLIT; sl++) s += part[((long)sl * BHN + bh) * MP + m];
    ksum[bh * MP + m] = s;
}

// =============================================================================
// out GEMM + fused denom + FUSED query finalize (exp applied at A-load).
// BM=128, N=64, K=MP=272. grid (32, 1, 32), 256 threads.
// =============================================================================
__global__ void __launch_bounds__(256, 2) gemm_out2(
    const float* __restrict__ QP, const float* __restrict__ CT,
    const float* __restrict__ KSUM,
    const float* __restrict__ DIAGQ, const float* __restrict__ QMAX,
    float* __restrict__ AT) {
    __shared__ float As[2][16][128];
    __shared__ float Bs[2][16][64];   // [k][d] natural
    __shared__ float ks_s[MP];
    const int tid = threadIdx.x;
    const int bh = blockIdx.z;
    const int b = bh >> 3, hh = bh & 7;
    const int bm = blockIdx.x * 128;
    const int tx = tid & 7, ty = tid >> 3;
    u64t acc[2][8];
    u64t dacc[2];
    dacc[0] = 0ull; dacc[1] = 0ull;
    #pragma unroll
    for (int i = 0; i < 2; i++)
        #pragma unroll
        for (int j = 0; j < 8; j++) acc[i][j] = 0ull;

    const int lr = tid >> 1, lk = (tid & 1) * 8;
    const float* Arow = QP + (long)bh * NPIX * MP + (long)(bm + lr) * MP + lk;
    const float* Bb = CT + (long)bh * MP * DH;
    const int lr2 = tid >> 4, lq = (tid & 15) * 4;   // B loader: 16 k-rows x 64 d
    const float subq = DIAGQ[(long)bh * NPIX + bm + lr] + QMAX[(long)bh * NPIX + bm + lr];

    {
        float4 a0 = *(const float4*)(Arow), a1 = *(const float4*)(Arow + 4);
        a0.x = feat_xf(a0.x, lk+0, subq); a0.y = feat_xf(a0.y, lk+1, subq);
        a0.z = feat_xf(a0.z, lk+2, subq); a0.w = feat_xf(a0.w, lk+3, subq);
        a1.x = feat_xf(a1.x, lk+4, subq); a1.y = feat_xf(a1.y, lk+5, subq);
        a1.z = feat_xf(a1.z, lk+6, subq); a1.w = feat_xf(a1.w, lk+7, subq);
        float4 bb = *(const float4*)(Bb + (long)lr2 * DH + lq);
        As[0][lk+0][lr]=a0.x; As[0][lk+1][lr]=a0.y; As[0][lk+2][lr]=a0.z; As[0][lk+3][lr]=a0.w;
        As[0][lk+4][lr]=a1.x; As[0][lk+5][lr]=a1.y; As[0][lk+6][lr]=a1.z; As[0][lk+7][lr]=a1.w;
        *(float4*)&Bs[0][lr2][lq] = bb;
        for (int i = tid; i < MP; i += 256) ks_s[i] = KSUM[bh * MP + i];
    }
    __syncthreads();
    int buf = 0;
    for (int k0 = 16; k0 <= MP; k0 += 16) {
        const bool more = (k0 < MP);
        float4 a0, a1, bb;
        if (more) {
            a0 = *(const float4*)(Arow + k0); a1 = *(const float4*)(Arow + k0 + 4);
            bb = *(const float4*)(Bb + (long)(k0 + lr2) * DH + lq);
        }
        const float (*Ac)[128] = As[buf];
        const float (*Bc)[64] = Bs[buf];
        const int kbase = k0 - 16;
        #pragma unroll
        for (int kk = 0; kk < 16; kk++) {
            const u64t* ap = (const u64t*)&Ac[kk][ty * 4];
            u64t av0 = ap[0], av1 = ap[1];
            float4 p0 = *(const float4*)&Bc[kk][tx * 4];
            float4 p1 = *(const float4*)&Bc[kk][32 + tx * 4];
            u64t bv[8];
            bv[0]=dup2(p0.x); bv[1]=dup2(p0.y); bv[2]=dup2(p0.z); bv[3]=dup2(p0.w);
            bv[4]=dup2(p1.x); bv[5]=dup2(p1.y); bv[6]=dup2(p1.z); bv[7]=dup2(p1.w);
            #pragma unroll
            for (int j = 0; j < 8; j++) {
                fma2(acc[0][j], av0, bv[j]);
                fma2(acc[1][j], av1, bv[j]);
            }
            u64t kzd = dup2(ks_s[kbase + kk]);
            fma2(dacc[0], av0, kzd);
            fma2(dacc[1], av1, kzd);
        }
        if (more) {
            a0.x = feat_xf(a0.x, k0+lk+0, subq); a0.y = feat_xf(a0.y, k0+lk+1, subq);
            a0.z = feat_xf(a0.z, k0+lk+2, subq); a0.w = feat_xf(a0.w, k0+lk+3, subq);
            a1.x = feat_xf(a1.x, k0+lk+4, subq); a1.y = feat_xf(a1.y, k0+lk+5, subq);
            a1.z = feat_xf(a1.z, k0+lk+6, subq); a1.w = feat_xf(a1.w, k0+lk+7, subq);
            float (*An)[128] = As[buf ^ 1];
            An[lk+0][lr]=a0.x; An[lk+1][lr]=a0.y; An[lk+2][lr]=a0.z; An[lk+3][lr]=a0.w;
            An[lk+4][lr]=a1.x; An[lk+5][lr]=a1.y; An[lk+6][lr]=a1.z; An[lk+7][lr]=a1.w;
            *(float4*)&Bs[buf ^ 1][lr2][lq] = bb;
        }
        __syncthreads();
        buf ^= 1;
    }
    const int col0 = tx * 4, col1 = 32 + tx * 4;
    #pragma unroll
    for (int i = 0; i < 2; i++) {
        int n0 = bm + ty * 4 + 2 * i;
        float2 dp = unp2(dacc[i]);
        float rd0 = 1.0f / dp.x;
        float rd1 = 1.0f / dp.y;
        float o0[8], o1[8];
        #pragma unroll
        for (int j = 0; j < 8; j++) {
            float2 p = unp2(acc[i][j]);
            o0[j] = p.x * rd0; o1[j] = p.y * rd1;
        }
        float* c0 = AT + ((long)(b * NPIX + n0)) * INNER + hh * DH;
        float* c1 = c0 + INNER;
        *(float4*)(c0 + col0) = make_float4(o0[0],o0[1],o0[2],o0[3]);
        *(float4*)(c0 + col1) = make_float4(o0[4],o0[5],o0[6],o0[7]);
        *(float4*)(c1 + col0) = make_float4(o1[0],o1[1],o1[2],o1[3]);
        *(float4*)(c1 + col1) = make_float4(o1[4],o1[5],o1[6],o1[7]);
    }
}

// ---------------- group norm + NHWC -> NCHW ----------------
__global__ void groupnorm_kernel(const float* __restrict__ Y, const float* __restrict__ G,
                                 const float* __restrict__ Bt, float* __restrict__ Z) {
    int b = blockIdx.x >> 3, grp = blockIdx.x & 7;
    const int CPG = 24, NELEM = CPG * NPIX;
    float s = 0.f, s2 = 0.f;
    for (int t = threadIdx.x; t < NELEM; t += 256) {
        int c = grp * CPG + (t % CPG);
        int pix = t / CPG;
        float v = Y[((long)b * NPIX + pix) * DIM + c];
        s += v; s2 += v * v;
    }
    __shared__ float ssum[8], ssq[8];
    int lane = threadIdx.x & 31, wid = threadIdx.x >> 5;
    s = warpSum(s); s2 = warpSum(s2);
    if (lane == 0) { ssum[wid] = s; ssq[wid] = s2; }
    __syncthreads();
    if (wid == 0) {
        float a = (lane < 8) ? ssum[lane] : 0.f;
        float b2 = (lane < 8) ? ssq[lane] : 0.f;
        a = warpSum(a); b2 = warpSum(b2);
        if (lane == 0) { ssum[0] = a; ssq[0] = b2; }
    }
    __syncthreads();
    float mu = ssum[0] / NELEM;
    float var = ssq[0] / NELEM - mu * mu;
    float rstd = rsqrtf(var + 1e-5f);
    for (int t = threadIdx.x; t < NELEM; t += 256) {
        int c = grp * CPG + (t % CPG);
        int pix = t / CPG;
        float v = Y[((long)b * NPIX + pix) * DIM + c];
        Z[((long)(b * DIM + c)) * NPIX + pix] = (v - mu) * rstd * G[c] + Bt[c];
    }
}

// ---------------- circular grouped conv + gelu, FFMA2 channel pairs ----------------
template<int CIN_G, int COUT_G, int KS, int CIN_TOTAL, int COUT_TOTAL, bool DO_GELU>
__global__ void __launch_bounds__(256) conv_circ(
    const float* __restrict__ IN, const float* __restrict__ W,
    const float* __restrict__ Bi, float* __restrict__ OUT) {
    const int PAD = KS / 2;
    const int HALO = 16 + 2 * PAD;
    const int COP = COUT_G / 2;
    __shared__ float s_in[HALO * HALO];
    __shared__ __align__(8) float s_w[KS * KS * COUT_G];  // [tap][co], co contiguous
    int tile = blockIdx.x;
    int ty0 = (tile >> 2) * 16, tx0 = (tile & 3) * 16;
    int g = blockIdx.y, b = blockIdx.z;
    int tid = threadIdx.x;
    int tx = tid & 15, ty = tid >> 4;
    u64t acc2[COP];
    #pragma unroll
    for (int cp = 0; cp < COP; cp++)
        acc2[cp] = pack2(Bi[g * COUT_G + 2 * cp], Bi[g * COUT_G + 2 * cp + 1]);
    for (int ci = 0; ci < CIN_G; ci++) {
        for (int t = tid; t < HALO * HALO; t += 256) {
            int r = t / HALO, c = t % HALO;
            int gy = (ty0 + r - PAD) & 63;
            int gx = (tx0 + c - PAD) & 63;
            s_in[t] = IN[(((long)b * CIN_TOTAL + g * CIN_G + ci) * 64 + gy) * 64 + gx];
        }
        for (int t = tid; t < COUT_G * KS * KS; t += 256) {
            int co = t % COUT_G, r = t / COUT_G;
            s_w[r * COUT_G + co] = W[(((long)(g * COUT_G + co)) * CIN_G + ci) * (KS * KS) + r];
        }
        __syncthreads();
        #pragma unroll
        for (int ky = 0; ky < KS; ky++) {
            #pragma unroll
            for (int kx = 0; kx < KS; kx++) {
                u64t vd = dup2(s_in[(ty + ky) * HALO + tx + kx]);
                const u64t* wrow = (const u64t*)&s_w[(ky * KS + kx) * COUT_G];
                #pragma unroll
                for (int cp = 0; cp < COP; cp++)
                    fma2(acc2[cp], vd, wrow[cp]);
            }
        }
        __syncthreads();
    }
    #pragma unroll
    for (int cp = 0; cp < COP; cp++) {
        float2 p = unp2(acc2[cp]);
        float v0 = DO_GELU ? gelu_exact(p.x) : p.x;
        float v1 = DO_GELU ? gelu_exact(p.y) : p.y;
        long base = (((long)b * COUT_TOTAL + g * COUT_G + 2 * cp) * 64 + ty0 + ty) * 64 + tx0 + tx;
        OUT[base] = v0;
        OUT[base + NPIX] = v1;
    }
}

// ---------------- 1x1 conv 48->3 ----------------
__global__ void conv1_kernel(const float* __restrict__ IN, const float* __restrict__ W,
                             const float* __restrict__ Bi, float* __restrict__ OUT) {
    int b = blockIdx.y;
    int pix = blockIdx.x * 256 + threadIdx.x;
    float a0 = Bi[0], a1 = Bi[1], a2 = Bi[2];
    #pragma unroll
    for (int c = 0; c < 48; c++) {
        float v = IN[((long)b * 48 + c) * NPIX + pix];
        a0 = fmaf(v, W[0 * 48 + c], a0);
        a1 = fmaf(v, W[1 * 48 + c], a1);
        a2 = fmaf(v, W[2 * 48 + c], a2);
    }
    long base = ((long)b * NPIX + pix) * 3;
    OUT[base + 0] = a0; OUT[base + 1] = a1; OUT[base + 2] = a2;
}

// ---------------- host ----------------
extern "C" void kernel_launch(void* const* d_in, const int* in_sizes, int n_in,
                              void* d_out, int out_size) {
    const float* x        = (const float*)d_in[0];
    const float* to_in_w  = (const float*)d_in[1];
    const float* to_in_b  = (const float*)d_in[2];
    const float* pos_emb  = (const float*)d_in[3];
    const float* proj     = (const float*)d_in[4];
    const float* sn_attn_g= (const float*)d_in[5];
    const float* wq       = (const float*)d_in[6];
    const float* wk       = (const float*)d_in[7];
    const float* wv       = (const float*)d_in[8];
    const float* wo       = (const float*)d_in[9];
    const float* bo       = (const float*)d_in[10];
    const float* sn_ff_g  = (const float*)d_in[11];
    const float* w1       = (const float*)d_in[12];
    const float* b1       = (const float*)d_in[13];
    const float* w2       = (const float*)d_in[14];
    const float* b2       = (const float*)d_in[15];
    const float* expand_w = (const float*)d_in[16];
    const float* fwd_w    = (const float*)d_in[17];
    const float* dec_lin_w= (const float*)d_in[18];
    const float* dec_lin_b= (const float*)d_in[19];
    const float* gn_g     = (const float*)d_in[20];
    const float* gn_b     = (const float*)d_in[21];
    const float* c9_w     = (const float*)d_in[22];
    const float* c9_b     = (const float*)d_in[23];
    const float* c7_w     = (const float*)d_in[24];
    const float* c7_b     = (const float*)d_in[25];
    const float* c5_w     = (const float*)d_in[26];
    const float* c5_b     = (const float*)d_in[27];
    const float* c1_w     = (const float*)d_in[28];
    const float* c1_b     = (const float*)d_in[29];
    float* out = (float*)d_out;

    float *ph, *phn, *pq, *pk, *pv, *pqp, *pkp, *pctx, *pctxp, *pksum, *pkmax, *pkmp,
          *pksp, *pdiagq, *pdiagk, *pqmaxp, *pqmax,
          *pattn, *pff, *pt1, *pt2, *py, *pnchw, *pc9, *pc7, *pc5;
    cudaGetSymbolAddress((void**)&ph, g_h);
    cudaGetSymbolAddress((void**)&phn, g_hn);
    cudaGetSymbolAddress((void**)&pq, g_q);
    cudaGetSymbolAddress((void**)&pk, g_k);
    cudaGetSymbolAddress((void**)&pv, g_v);
    cudaGetSymbolAddress((void**)&pqp, g_qp);
    cudaGetSymbolAddress((void**)&pkp, g_kp);
    cudaGetSymbolAddress((void**)&pctx, g_ctx);
    cudaGetSymbolAddress((void**)&pctxp, g_ctxp);
    cudaGetSymbolAddress((void**)&pksum, g_ksum);
    cudaGetSymbolAddress((void**)&pkmax, g_kmax);
    cudaGetSymbolAddress((void**)&pkmp, g_kmpart);
    cudaGetSymbolAddress((void**)&pksp, g_kspart);
    cudaGetSymbolAddress((void**)&pdiagq, g_diagq);
    cudaGetSymbolAddress((void**)&pdiagk, g_diagk);
    cudaGetSymbolAddress((void**)&pqmaxp, g_qmaxp);
    cudaGetSymbolAddress((void**)&pqmax, g_qmax);
    cudaGetSymbolAddress((void**)&pattn, g_attn);
    cudaGetSymbolAddress((void**)&pff, g_ff);
    cudaGetSymbolAddress((void**)&pt1, g_t1);
    cudaGetSymbolAddress((void**)&pt2, g_t2);
    cudaGetSymbolAddress((void**)&py, g_y);
    cudaGetSymbolAddress((void**)&pnchw, g_nchw);
    cudaGetSymbolAddress((void**)&pc9, g_c9o);
    cudaGetSymbolAddress((void**)&pc7, g_c7o);
    cudaGetSymbolAddress((void**)&pc5, g_c5o);

    embed_kernel<<<ROWS, DIM>>>(x, to_in_w, to_in_b, pos_emb, ph);

    const long CTOT = (long)BHN * MP * DH;
    for (int i = 0; i < DEPTH; i++) {
        const float* proj_i = proj + (long)i * MFEAT * DH;
        scalenorm_kernel<<<2048, 256>>>(ph, phn, sn_attn_g, i);
        gemm_qkv_f2<<<dim3(128, 4, 3), 256>>>(phn,
            wq + (long)i * INNER * DIM, wk + (long)i * INNER * DIM, wv + (long)i * INNER * DIM,
            pq, pk, pv);
        gemm_dd2<<<dim3(32, 5, 64), 256>>>(pq, pk, proj_i, pqp, pkp, pkmp, pqmaxp, pdiagq, pdiagk);
        kmax_fin2<<<BHN, 32>>>(pkmp, pkmax);
        qmax_fin<<<(BHN * NPIX) / 256, 256>>>(pqmaxp, pqmax);
        gemm_ctx2<<<dim3(5, CTX_SPLIT, BHN), 128>>>(pkp, pv, pdiagk, pkmax, pctxp, pksp);
        ctx_reduce_kernel<<<(int)((CTOT + 255) / 256), 256>>>(pctxp, pctx);
        ksum_fin_kernel<<<BHN, MP>>>(pksp, pksum);
        gemm_out2<<<dim3(32, 1, BHN), 256>>>(pqp, pctx, pksum, pdiagq, pqmax, pattn);
        gemm_f2n64k<3><<<dim3(128, 3), 256>>>(pattn, wo + (long)i * DIM * INNER, bo + (long)i * DIM, ph, ph, DIM, INNER);
        scalenorm_kernel<<<2048, 256>>>(ph, phn, sn_ff_g, i);
        gemm_f2n128k<2><<<dim3(128, 6), 256>>>(phn, w1 + (long)i * FF * DIM, b1 + (long)i * FF, nullptr, pff, FF, DIM);
        gemm_f2n64k<3><<<dim3(128, 3), 256>>>(pff, w2 + (long)i * DIM * FF, b2 + (long)i * DIM, ph, ph, DIM, FF);
    }

    gemm_f2n64k<0><<<dim3(128, 3), 256>>>(ph, expand_w, nullptr, nullptr, pt1, DIM, DIM);
    gemm_f2n64k<0><<<dim3(128, 3), 256>>>(pt1, fwd_w, nullptr, nullptr, pt2, DIM, DIM);
    gemm_f2n64k<1><<<dim3(128, 3), 256>>>(pt2, dec_lin_w, dec_lin_b, nullptr, py, DIM, DIM);

    groupnorm_kernel<<<32, 256>>>(py, gn_g, gn_b, pnchw);
    conv_circ<24, 24, 9, 192, 192, true><<<dim3(16, 8, 4), 256>>>(pnchw, c9_w, c9_b, pc9);
    conv_circ<24, 12, 7, 192,  96, true><<<dim3(16, 8, 4), 256>>>(pc9, c7_w, c7_b, pc7);
    conv_circ<12,  6, 5,  96,  48, true><<<dim3(16, 8, 4), 256>>>(pc7, c5_w, c5_b, pc5);
    conv1_kernel<<<dim3(16, 4), 256>>>(pc5, c1_w, c1_b, out);
}